// round 2
// baseline (speedup 1.0000x reference)
#include <cuda_runtime.h>
#include <cstddef>

#define TT    1024
#define BB    256
#define INDIM 128
#define HH    256
#define NBRNN 96

typedef unsigned long long ull;

// ---------------- scratch (device globals: no allocation allowed) ----------------
__device__ float g_X0[(size_t)TT * BB * HH];      // input proj + biases, [T,B,H]
__device__ float g_h1all[(size_t)TT * BB * HH];   // all layer-1 hidden states
__device__ float g_h0buf[2][BB * HH];             // double-buffered h0
__device__ float g_h1buf[2][BB * HH];             // double-buffered h1
__device__ unsigned g_bar_count;
__device__ unsigned g_bar_gen;

// ---------------- f32x2 helpers (Blackwell packed fp32 FMA) ----------------
__device__ __forceinline__ ull pack2(float lo, float hi) {
    ull r; asm("mov.b64 %0, {%1, %2};" : "=l"(r) : "f"(lo), "f"(hi)); return r;
}
__device__ __forceinline__ void unpack2(ull v, float& lo, float& hi) {
    asm("mov.b64 {%0, %1}, %2;" : "=f"(lo), "=f"(hi) : "l"(v));
}
__device__ __forceinline__ void fma2(ull& d, ull a, ull b) {
    asm("fma.rn.f32x2 %0, %1, %2, %0;" : "+l"(d) : "l"(a), "l"(b));
}

__device__ __forceinline__ float tanh_fast(float x) {
    float xc = fminf(fmaxf(x, -15.0f), 15.0f);
    float e  = __expf(2.0f * xc);
    return __fdividef(e - 1.0f, e + 1.0f);
}

// ---------------- grid barrier (sense-reversing, L2-resident counters) ----------------
__device__ __forceinline__ void gbar(unsigned nb) {
    __threadfence();     // publish this CTA's stores before arrival
    __syncthreads();
    if (threadIdx.x == 0) {
        volatile unsigned* vg = &g_bar_gen;
        unsigned g = *vg;
        unsigned t = atomicAdd(&g_bar_count, 1u);
        if (t == nb - 1u) {
            atomicExch(&g_bar_count, 0u);
            __threadfence();
            atomicAdd(&g_bar_gen, 1u);
        } else {
            while (*vg == g) { }
        }
        __threadfence();  // acquire: order subsequent loads after observed release
    }
    __syncthreads();
}

// ---------------- prologue: X0 = input @ W_ih0^T + (b_ih0+b_hh0+bias0); copy init hidden ----------------
// 32768 GEMM blocks (32 rows x 64 cols, K=128) + 8 copy blocks; 256 threads each.
__global__ void __launch_bounds__(256) k_prologue(
    const float* __restrict__ inp, const float* __restrict__ Wih0,
    const float* __restrict__ bih0, const float* __restrict__ bhh0,
    const float* __restrict__ bias0, const float* __restrict__ hidden)
{
    int bx = blockIdx.x, tid = threadIdx.x;
    if (bx >= 32768) {
        int base = (bx - 32768) * 16384;
        for (int s = 0; s < 64; ++s) {
            int i = base + s * 256 + tid;
            float v = hidden[i];
            if (i < BB * HH) g_h0buf[1][i] = v;
            else             g_h1buf[1][i - BB * HH] = v;
        }
        return;
    }
    extern __shared__ float sm[];
    float* sw = sm;                    // Wt [128][64]
    float* sa = sm + 128 * 64;         // input rows [32][132]
    float* sb = sa + 32 * 132;         // bias sum [64]
    int rt = bx >> 2, ji = bx & 3;
    int row0 = rt * 32, jg0 = ji * 64;
    for (int i = tid; i < 128 * 64; i += 256) {
        int k = i >> 6, j = i & 63;
        sw[i] = Wih0[(jg0 + j) * INDIM + k];
    }
    for (int i = tid; i < 32 * 32; i += 256) {
        int r = i >> 5, c = (i & 31) << 2;
        *(float4*)&sa[r * 132 + c] = *(const float4*)&inp[(size_t)(row0 + r) * INDIM + c];
    }
    if (tid < 64) sb[tid] = bih0[jg0 + tid] + bhh0[jg0 + tid] + bias0[jg0 + tid];
    __syncthreads();

    int lb = tid >> 3, j0 = (tid & 7) << 3;
    ull acc0 = pack2(sb[j0 + 0], sb[j0 + 1]);
    ull acc1 = pack2(sb[j0 + 2], sb[j0 + 3]);
    ull acc2 = pack2(sb[j0 + 4], sb[j0 + 5]);
    ull acc3 = pack2(sb[j0 + 6], sb[j0 + 7]);
    const float* arow = &sa[lb * 132];
    #pragma unroll 4
    for (int k4 = 0; k4 < INDIM; k4 += 4) {
        float4 a = *(const float4*)&arow[k4];
        #pragma unroll
        for (int kk = 0; kk < 4; ++kk) {
            float av = (&a.x)[kk];
            ull aa = pack2(av, av);
            ulonglong2 w01 = *(const ulonglong2*)&sw[(k4 + kk) * 64 + j0];
            ulonglong2 w23 = *(const ulonglong2*)&sw[(k4 + kk) * 64 + j0 + 4];
            fma2(acc0, aa, w01.x); fma2(acc1, aa, w01.y);
            fma2(acc2, aa, w23.x); fma2(acc3, aa, w23.y);
        }
    }
    float o0,o1,o2,o3,o4,o5,o6,o7;
    unpack2(acc0,o0,o1); unpack2(acc1,o2,o3); unpack2(acc2,o4,o5); unpack2(acc3,o6,o7);
    float* op = &g_X0[(size_t)(row0 + lb) * HH + jg0 + j0];
    *(float4*)op       = make_float4(o0,o1,o2,o3);
    *(float4*)(op + 4) = make_float4(o4,o5,o6,o7);
}

// ---------------- persistent recurrence kernel ----------------
// CTAs 0..31: layer0 tiles (32b x 64j, K=256).  CTAs 32..95: layer1 tiles (16b x 64j, K=512).
// Phase p in [0,T]: layer0 computes h0(p) (p<T); layer1 computes h1(p-1) (p>=1).
// h0(t) lives in g_h0buf[t&1]; h1(t) in g_h1buf[t&1]. One grid barrier per phase.
__global__ void __launch_bounds__(256, 1) k_rnn(
    const float* __restrict__ Whh0, const float* __restrict__ Wih1,
    const float* __restrict__ Whh1, const float* __restrict__ bih1,
    const float* __restrict__ bhh1, const float* __restrict__ bias1)
{
    extern __shared__ float sm[];
    const int bx = blockIdx.x, tid = threadIdx.x;

    if (bx < 32) {
        // ---------------- layer 0 ----------------
        const int bi = bx >> 2, ji = bx & 3;
        const int b0 = bi * 32, jg0 = ji * 64;
        float* sw = sm;                 // Whh0^T tile [256][64]
        float* sa = sm + 256 * 64;      // h0(p-1) rows [32][260]
        for (int i = tid; i < 256 * 64; i += 256) {
            int k = i >> 6, j = i & 63;
            sw[i] = Whh0[(jg0 + j) * HH + k];
        }
        const int lb = tid >> 3, j0 = (tid & 7) << 3;
        for (int p = 0; p <= TT; ++p) {
            const float* src = g_h0buf[(p + 1) & 1];   // h0(p-1)
            for (int i = tid; i < 32 * 64; i += 256) {
                int r = i >> 6, c = (i & 63) << 2;
                *(float4*)&sa[r * 260 + c] = __ldcg((const float4*)&src[(b0 + r) * HH + c]);
            }
            __syncthreads();
            if (p < TT) {
                const float* xp = &g_X0[((size_t)p * BB + b0 + lb) * HH + jg0 + j0];
                float4 x0 = __ldcg((const float4*)xp);
                float4 x1 = __ldcg((const float4*)(xp + 4));
                ull acc0 = pack2(x0.x, x0.y), acc1 = pack2(x0.z, x0.w);
                ull acc2 = pack2(x1.x, x1.y), acc3 = pack2(x1.z, x1.w);
                const float* arow = &sa[lb * 260];
                #pragma unroll 4
                for (int k4 = 0; k4 < HH; k4 += 4) {
                    float4 a = *(const float4*)&arow[k4];
                    #pragma unroll
                    for (int kk = 0; kk < 4; ++kk) {
                        float av = (&a.x)[kk];
                        ull aa = pack2(av, av);
                        ulonglong2 w01 = *(const ulonglong2*)&sw[(k4 + kk) * 64 + j0];
                        ulonglong2 w23 = *(const ulonglong2*)&sw[(k4 + kk) * 64 + j0 + 4];
                        fma2(acc0, aa, w01.x); fma2(acc1, aa, w01.y);
                        fma2(acc2, aa, w23.x); fma2(acc3, aa, w23.y);
                    }
                }
                float u0,u1,u2,u3,u4,u5,u6,u7;
                unpack2(acc0,u0,u1); unpack2(acc1,u2,u3);
                unpack2(acc2,u4,u5); unpack2(acc3,u6,u7);
                u0=tanh_fast(u0); u1=tanh_fast(u1); u2=tanh_fast(u2); u3=tanh_fast(u3);
                u4=tanh_fast(u4); u5=tanh_fast(u5); u6=tanh_fast(u6); u7=tanh_fast(u7);
                float* dp = &g_h0buf[p & 1][(b0 + lb) * HH + jg0 + j0];
                *(float4*)dp       = make_float4(u0,u1,u2,u3);
                *(float4*)(dp + 4) = make_float4(u4,u5,u6,u7);
            }
            gbar(NBRNN);
        }
    } else {
        // ---------------- layer 1 ----------------
        const int bxx = bx - 32;
        const int bi = bxx >> 2, ji = bxx & 3;
        const int b0 = bi * 16, jg0 = ji * 64;
        float* swI = sm;                     // Wih1^T tile [256][64]
        float* swH = sm + 256 * 64;          // Whh1^T tile [256][64]
        float* sa0 = swH + 256 * 64;         // h0(p-1) rows [16][260]
        float* sa1 = sa0 + 16 * 260;         // h1(p-2) rows [16][260]
        float* sb  = sa1 + 16 * 260;         // bias sum [64]
        for (int i = tid; i < 256 * 64; i += 256) {
            int k = i >> 6, j = i & 63;
            swI[i] = Wih1[(jg0 + j) * HH + k];
            swH[i] = Whh1[(jg0 + j) * HH + k];
        }
        if (tid < 64) sb[tid] = bih1[jg0 + tid] + bhh1[jg0 + tid] + bias1[jg0 + tid];
        const int lb = tid >> 4, j0 = (tid & 15) << 2;
        for (int p = 0; p <= TT; ++p) {
            const float* s0 = g_h0buf[(p + 1) & 1];   // h0(p-1)
            const float* s1 = g_h1buf[p & 1];         // h1(p-2)
            for (int i = tid; i < 16 * 64; i += 256) {
                int r = i >> 6, c = (i & 63) << 2;
                *(float4*)&sa0[r * 260 + c] = __ldcg((const float4*)&s0[(b0 + r) * HH + c]);
                *(float4*)&sa1[r * 260 + c] = __ldcg((const float4*)&s1[(b0 + r) * HH + c]);
            }
            __syncthreads();
            if (p >= 1) {
                ull acc0 = pack2(sb[j0 + 0], sb[j0 + 1]);
                ull acc1 = pack2(sb[j0 + 2], sb[j0 + 3]);
                const float* a0row = &sa0[lb * 260];
                const float* a1row = &sa1[lb * 260];
                #pragma unroll 4
                for (int k4 = 0; k4 < HH; k4 += 4) {
                    float4 a0 = *(const float4*)&a0row[k4];
                    float4 a1 = *(const float4*)&a1row[k4];
                    #pragma unroll
                    for (int kk = 0; kk < 4; ++kk) {
                        float av0 = (&a0.x)[kk];
                        float av1 = (&a1.x)[kk];
                        ull aa0 = pack2(av0, av0);
                        ull aa1 = pack2(av1, av1);
                        ulonglong2 wI = *(const ulonglong2*)&swI[(k4 + kk) * 64 + j0];
                        ulonglong2 wH = *(const ulonglong2*)&swH[(k4 + kk) * 64 + j0];
                        fma2(acc0, aa0, wI.x); fma2(acc1, aa0, wI.y);
                        fma2(acc0, aa1, wH.x); fma2(acc1, aa1, wH.y);
                    }
                }
                float u0,u1,u2,u3;
                unpack2(acc0,u0,u1); unpack2(acc1,u2,u3);
                u0=tanh_fast(u0); u1=tanh_fast(u1); u2=tanh_fast(u2); u3=tanh_fast(u3);
                float4 v = make_float4(u0,u1,u2,u3);
                *(float4*)&g_h1buf[(p + 1) & 1][(b0 + lb) * HH + jg0 + j0] = v;  // h1(p-1), parity (p-1)&1
                *(float4*)&g_h1all[((size_t)(p - 1) * BB + b0 + lb) * HH + jg0 + j0] = v;
            }
            gbar(NBRNN);
        }
    }
}

// ---------------- epilogue: logits = h1all @ fc_w^T + fc_b; copy last hidden ----------------
// 32768 blocks of 8 warps (warp per row) + 512 copy blocks.
__global__ void __launch_bounds__(256) k_epilogue(
    const float* __restrict__ fcw, const float* __restrict__ fcb,
    float* __restrict__ out, int out_size)
{
    int bx = blockIdx.x, tid = threadIdx.x;
    if (bx >= 32768) {
        // last_hidden: h0(T-1) parity (T-1)&1 = 1, h1(T-1) parity 1
        int i = (bx - 32768) * 256 + tid;
        int base = TT * BB * 2;
        if (base + i < out_size) {
            float v = (i < BB * HH) ? g_h0buf[1][i] : g_h1buf[1][i - BB * HH];
            out[base + i] = v;
        }
        return;
    }
    __shared__ float sfw[2 * HH];
    __shared__ float sfb[2];
    for (int i = tid; i < 2 * HH; i += 256) sfw[i] = fcw[i];
    if (tid < 2) sfb[tid] = fcb[tid];
    __syncthreads();

    int w = tid >> 5, lane = tid & 31;
    size_t row = (size_t)bx * 8 + w;            // row in [0, T*B)
    const float* hp = &g_h1all[row * HH + lane * 8];
    float4 h0v = *(const float4*)hp;
    float4 h1v = *(const float4*)(hp + 4);
    const float* w0 = &sfw[lane * 8];
    const float* w1 = &sfw[HH + lane * 8];
    float c0 = 0.f, c1 = 0.f;
    #pragma unroll
    for (int q = 0; q < 4; ++q) {
        c0 += (&h0v.x)[q] * w0[q] + (&h1v.x)[q] * w0[q + 4];
        c1 += (&h0v.x)[q] * w1[q] + (&h1v.x)[q] * w1[q + 4];
    }
    #pragma unroll
    for (int off = 16; off > 0; off >>= 1) {
        c0 += __shfl_down_sync(0xFFFFFFFFu, c0, off);
        c1 += __shfl_down_sync(0xFFFFFFFFu, c1, off);
    }
    if (lane == 0) {
        out[row * 2 + 0] = c0 + sfb[0];
        out[row * 2 + 1] = c1 + sfb[1];
    }
}

// ---------------- launch ----------------
extern "C" void kernel_launch(void* const* d_in, const int* in_sizes, int n_in,
                              void* d_out, int out_size) {
    const float* inp    = (const float*)d_in[0];
    const float* hidden = (const float*)d_in[1];
    const float* Wih0   = (const float*)d_in[2];
    const float* bih0   = (const float*)d_in[3];
    const float* Whh0   = (const float*)d_in[4];
    const float* bhh0   = (const float*)d_in[5];
    const float* bias0  = (const float*)d_in[6];
    const float* Wih1   = (const float*)d_in[7];
    const float* bih1   = (const float*)d_in[8];
    const float* Whh1   = (const float*)d_in[9];
    const float* bhh1   = (const float*)d_in[10];
    const float* bias1  = (const float*)d_in[11];
    const float* fcw    = (const float*)d_in[12];
    const float* fcb    = (const float*)d_in[13];
    float* out = (float*)d_out;

    static bool attr_done = false;
    if (!attr_done) {
        cudaFuncSetAttribute(k_prologue, cudaFuncAttributeMaxDynamicSharedMemorySize, 49920);
        cudaFuncSetAttribute(k_rnn,      cudaFuncAttributeMaxDynamicSharedMemorySize, 164608);
        attr_done = true;
    }

    k_prologue<<<32776, 256, 49920>>>(inp, Wih0, bih0, bhh0, bias0, hidden);
    k_rnn<<<NBRNN, 256, 164608>>>(Whh0, Wih1, Whh1, bih1, bhh1, bias1);
    k_epilogue<<<33280, 256>>>(fcw, fcb, out, out_size);
}

// round 3
// speedup vs baseline: 1.6765x; 1.6765x over previous
#include <cuda_runtime.h>
#include <cstddef>

#define TT    1024
#define BB    256
#define INDIM 128
#define HH    256
#define NBRNN 96

typedef unsigned long long ull;

// ---------------- scratch (device globals) ----------------
__device__ float g_X0[(size_t)TT * BB * HH];      // input proj (pre-bias-added), [T*B, H]
__device__ float g_h1all[(size_t)TT * BB * HH];   // all layer-1 hidden states
__device__ float g_h0buf[2][BB * HH];             // double-buffered h0
__device__ float g_h1buf[2][BB * HH];             // double-buffered h1
__device__ __align__(128) unsigned g_bar_count;
__device__ __align__(128) unsigned g_bar_gen;     // separate 128B line from count

// ---------------- f32x2 helpers ----------------
__device__ __forceinline__ ull pack2(float lo, float hi) {
    ull r; asm("mov.b64 %0, {%1, %2};" : "=l"(r) : "f"(lo), "f"(hi)); return r;
}
__device__ __forceinline__ void unpack2(ull v, float& lo, float& hi) {
    asm("mov.b64 {%0, %1}, %2;" : "=f"(lo), "=f"(hi) : "l"(v));
}
__device__ __forceinline__ void fma2(ull& d, ull a, ull b) {
    asm("fma.rn.f32x2 %0, %1, %2, %0;" : "+l"(d) : "l"(a), "l"(b));
}
__device__ __forceinline__ void add2(ull& d, ull a) {
    asm("add.rn.f32x2 %0, %0, %1;" : "+l"(d) : "l"(a));
}

__device__ __forceinline__ float tanh_fast(float x) {
    float xc = fminf(fmaxf(x, -15.0f), 15.0f);
    float e  = __expf(2.0f * xc);
    return __fdividef(e - 1.0f, e + 1.0f);
}

// ---------------- grid barrier (sense-reversing) ----------------
__device__ __forceinline__ void gbar(unsigned nb) {
    __threadfence();
    __syncthreads();
    if (threadIdx.x == 0) {
        volatile unsigned* vg = &g_bar_gen;
        unsigned g = *vg;
        unsigned t = atomicAdd(&g_bar_count, 1u);
        if (t == nb - 1u) {
            atomicExch(&g_bar_count, 0u);
            __threadfence();
            atomicAdd(&g_bar_gen, 1u);
        } else {
            while (*vg == g) { }
        }
        __threadfence();
    }
    __syncthreads();
}

// =====================================================================
// Prologue: X0 = input @ Wih0^T  (bias added here too); copy init hidden.
// GEMM: 16384 CTAs, tile 64 rows x 64 cols, K=128 split in 2 (ks = warp-group).
// Thread tile 4b x 8j. 256 threads: jg=tid&7, bg=(tid>>3)&15, ks=tid>>7.
// smem floats: sw[128*64) | sa[64*132) | sb[64) | sp (ull, 128 slots * 18)
// =====================================================================
#define PRO_SMEM 85248
__global__ void __launch_bounds__(256) k_prologue(
    const float* __restrict__ inp, const float* __restrict__ Wih0,
    const float* __restrict__ bih0, const float* __restrict__ bhh0,
    const float* __restrict__ bias0, const float* __restrict__ hidden)
{
    int bx = blockIdx.x, tid = threadIdx.x;
    if (bx >= 16384) {
        int base = (bx - 16384) * 16384;
        for (int s = 0; s < 64; ++s) {
            int i = base + s * 256 + tid;
            float v = hidden[i];
            if (i < BB * HH) g_h0buf[1][i] = v;
            else             g_h1buf[1][i - BB * HH] = v;
        }
        return;
    }
    extern __shared__ float sm[];
    float* sw = sm;                 // [128][64]
    float* sa = sm + 8192;          // [64][132]
    float* sb = sm + 16640;         // [64]
    ull*   sp = (ull*)(sm + 16704); // 128 slots * 18 ull

    int rt = bx >> 2, ji = bx & 3;
    int row0 = rt * 64, jg0 = ji * 64;

    for (int i = tid; i < 8192; i += 256) {
        int k = i >> 6, j = i & 63;
        sw[i] = Wih0[(jg0 + j) * INDIM + k];
    }
    for (int i = tid; i < 64 * 32; i += 256) {
        int r = i >> 5, c = (i & 31) << 2;
        *(float4*)&sa[r * 132 + c] = *(const float4*)&inp[(size_t)(row0 + r) * INDIM + c];
    }
    if (tid < 64) sb[tid] = bih0[jg0 + tid] + bhh0[jg0 + tid] + bias0[jg0 + tid];
    __syncthreads();

    const int jg = tid & 7, bg = (tid >> 3) & 15, ks = tid >> 7;
    const int j0 = jg << 3, r0 = bg << 2, k0 = ks << 6;

    ull acc[16];
    #pragma unroll
    for (int i = 0; i < 16; ++i) acc[i] = 0ull;

    #pragma unroll 4
    for (int k4 = 0; k4 < 16; ++k4) {
        int kb = k0 + (k4 << 2);
        float4 a0 = *(const float4*)&sa[(r0 + 0) * 132 + kb];
        float4 a1 = *(const float4*)&sa[(r0 + 1) * 132 + kb];
        float4 a2 = *(const float4*)&sa[(r0 + 2) * 132 + kb];
        float4 a3 = *(const float4*)&sa[(r0 + 3) * 132 + kb];
        #pragma unroll
        for (int kk = 0; kk < 4; ++kk) {
            ulonglong2 w01 = *(const ulonglong2*)&sw[(kb + kk) * 64 + j0];
            ulonglong2 w23 = *(const ulonglong2*)&sw[(kb + kk) * 64 + j0 + 4];
            ull aa0 = pack2((&a0.x)[kk], (&a0.x)[kk]);
            ull aa1 = pack2((&a1.x)[kk], (&a1.x)[kk]);
            ull aa2 = pack2((&a2.x)[kk], (&a2.x)[kk]);
            ull aa3 = pack2((&a3.x)[kk], (&a3.x)[kk]);
            fma2(acc[0],  aa0, w01.x); fma2(acc[1],  aa0, w01.y);
            fma2(acc[2],  aa0, w23.x); fma2(acc[3],  aa0, w23.y);
            fma2(acc[4],  aa1, w01.x); fma2(acc[5],  aa1, w01.y);
            fma2(acc[6],  aa1, w23.x); fma2(acc[7],  aa1, w23.y);
            fma2(acc[8],  aa2, w01.x); fma2(acc[9],  aa2, w01.y);
            fma2(acc[10], aa2, w23.x); fma2(acc[11], aa2, w23.y);
            fma2(acc[12], aa3, w01.x); fma2(acc[13], aa3, w01.y);
            fma2(acc[14], aa3, w23.x); fma2(acc[15], aa3, w23.y);
        }
    }

    if (ks) {
        ull* q = &sp[(size_t)((bg << 3) + jg) * 18];
        #pragma unroll
        for (int m = 0; m < 8; ++m)
            *(ulonglong2*)&q[2 * m] = make_ulonglong2(acc[2 * m], acc[2 * m + 1]);
    }
    __syncthreads();
    if (!ks) {
        const ull* q = &sp[(size_t)((bg << 3) + jg) * 18];
        #pragma unroll
        for (int m = 0; m < 8; ++m) {
            ulonglong2 v = *(const ulonglong2*)&q[2 * m];
            add2(acc[2 * m], v.x); add2(acc[2 * m + 1], v.y);
        }
        #pragma unroll
        for (int i = 0; i < 4; ++i) {
            float u0,u1,u2,u3,u4,u5,u6,u7;
            unpack2(acc[i*4+0],u0,u1); unpack2(acc[i*4+1],u2,u3);
            unpack2(acc[i*4+2],u4,u5); unpack2(acc[i*4+3],u6,u7);
            const float* b = &sb[j0];
            float* op = &g_X0[(size_t)(row0 + r0 + i) * HH + jg0 + j0];
            *(float4*)op       = make_float4(u0+b[0], u1+b[1], u2+b[2], u3+b[3]);
            *(float4*)(op + 4) = make_float4(u4+b[4], u5+b[5], u6+b[6], u7+b[7]);
        }
    }
}

// =====================================================================
// Persistent recurrence kernel.
// CTAs 0..31: layer0 (32b x 64j, K=256 split 4).  CTAs 32..95: layer1 (16b x 64j, K=512 split 4).
// Phase p in [0,T]: layer0 computes h0(p) (p<T); layer1 computes h1(p-1) (p>=1).
// h0(t) -> g_h0buf[t&1]; h1(t) -> g_h1buf[t&1]. One grid barrier per phase.
// =====================================================================
#define RNN_SMEM 179968
__global__ void __launch_bounds__(256, 1) k_rnn(
    const float* __restrict__ Whh0, const float* __restrict__ Wih1,
    const float* __restrict__ Whh1, const float* __restrict__ bih1,
    const float* __restrict__ bhh1, const float* __restrict__ bias1)
{
    extern __shared__ float sm[];
    const int bx = blockIdx.x, tid = threadIdx.x;

    if (bx < 32) {
        // ---------------- layer 0: tile 32b x 64j, K=256, ks-split 4 ----------------
        const int bi = bx >> 2, ji = bx & 3;
        const int b0 = bi * 32, jg0 = ji * 64;
        float* sw = sm;                    // [256][64]
        float* sa = sm + 16384;            // [32][260]
        ull*   sp = (ull*)(sm + 24704);    // 192 slots * 18 ull

        for (int i = tid; i < 16384; i += 256) {
            int k = i >> 6, j = i & 63;
            sw[i] = Whh0[(jg0 + j) * HH + k];
        }
        const int jg = tid & 7, bg = (tid >> 3) & 7, ks = tid >> 6;
        const int j0 = jg << 3, r0 = bg << 2, k0 = ks << 6;

        for (int p = 0; p <= TT; ++p) {
            const float* src = g_h0buf[(p + 1) & 1];   // h0(p-1)
            for (int i = tid; i < 32 * 64; i += 256) {
                int r = i >> 6, c = (i & 63) << 2;
                *(float4*)&sa[r * 260 + c] = __ldcg((const float4*)&src[(b0 + r) * HH + c]);
            }
            __syncthreads();
            if (p < TT) {
                ull acc[16];
                #pragma unroll
                for (int i = 0; i < 16; ++i) acc[i] = 0ull;

                #pragma unroll 4
                for (int k4 = 0; k4 < 16; ++k4) {
                    int kb = k0 + (k4 << 2);
                    float4 a0 = *(const float4*)&sa[(r0 + 0) * 260 + kb];
                    float4 a1 = *(const float4*)&sa[(r0 + 1) * 260 + kb];
                    float4 a2 = *(const float4*)&sa[(r0 + 2) * 260 + kb];
                    float4 a3 = *(const float4*)&sa[(r0 + 3) * 260 + kb];
                    #pragma unroll
                    for (int kk = 0; kk < 4; ++kk) {
                        ulonglong2 w01 = *(const ulonglong2*)&sw[(kb + kk) * 64 + j0];
                        ulonglong2 w23 = *(const ulonglong2*)&sw[(kb + kk) * 64 + j0 + 4];
                        ull aa0 = pack2((&a0.x)[kk], (&a0.x)[kk]);
                        ull aa1 = pack2((&a1.x)[kk], (&a1.x)[kk]);
                        ull aa2 = pack2((&a2.x)[kk], (&a2.x)[kk]);
                        ull aa3 = pack2((&a3.x)[kk], (&a3.x)[kk]);
                        fma2(acc[0],  aa0, w01.x); fma2(acc[1],  aa0, w01.y);
                        fma2(acc[2],  aa0, w23.x); fma2(acc[3],  aa0, w23.y);
                        fma2(acc[4],  aa1, w01.x); fma2(acc[5],  aa1, w01.y);
                        fma2(acc[6],  aa1, w23.x); fma2(acc[7],  aa1, w23.y);
                        fma2(acc[8],  aa2, w01.x); fma2(acc[9],  aa2, w01.y);
                        fma2(acc[10], aa2, w23.x); fma2(acc[11], aa2, w23.y);
                        fma2(acc[12], aa3, w01.x); fma2(acc[13], aa3, w01.y);
                        fma2(acc[14], aa3, w23.x); fma2(acc[15], aa3, w23.y);
                    }
                }
                if (ks) {
                    ull* q = &sp[(size_t)(((ks - 1) << 6) + (bg << 3) + jg) * 18];
                    #pragma unroll
                    for (int m = 0; m < 8; ++m)
                        *(ulonglong2*)&q[2 * m] = make_ulonglong2(acc[2 * m], acc[2 * m + 1]);
                }
                __syncthreads();
                if (!ks) {
                    #pragma unroll
                    for (int s = 0; s < 3; ++s) {
                        const ull* q = &sp[(size_t)((s << 6) + (bg << 3) + jg) * 18];
                        #pragma unroll
                        for (int m = 0; m < 8; ++m) {
                            ulonglong2 v = *(const ulonglong2*)&q[2 * m];
                            add2(acc[2 * m], v.x); add2(acc[2 * m + 1], v.y);
                        }
                    }
                    #pragma unroll
                    for (int i = 0; i < 4; ++i) {
                        const float* xp = &g_X0[((size_t)p * BB + b0 + r0 + i) * HH + jg0 + j0];
                        float4 x0 = __ldcg((const float4*)xp);
                        float4 x1 = __ldcg((const float4*)(xp + 4));
                        float u0,u1,u2,u3,u4,u5,u6,u7;
                        unpack2(acc[i*4+0],u0,u1); unpack2(acc[i*4+1],u2,u3);
                        unpack2(acc[i*4+2],u4,u5); unpack2(acc[i*4+3],u6,u7);
                        u0=tanh_fast(u0+x0.x); u1=tanh_fast(u1+x0.y);
                        u2=tanh_fast(u2+x0.z); u3=tanh_fast(u3+x0.w);
                        u4=tanh_fast(u4+x1.x); u5=tanh_fast(u5+x1.y);
                        u6=tanh_fast(u6+x1.z); u7=tanh_fast(u7+x1.w);
                        float* dp = &g_h0buf[p & 1][(b0 + r0 + i) * HH + jg0 + j0];
                        *(float4*)dp       = make_float4(u0,u1,u2,u3);
                        *(float4*)(dp + 4) = make_float4(u4,u5,u6,u7);
                    }
                }
            } else {
                __syncthreads();
            }
            gbar(NBRNN);
        }
    } else {
        // ---------------- layer 1: tile 16b x 64j, K=512 (h0|h1 concat), ks-split 4 ----------------
        const int bxx = bx - 32;
        const int bi = bxx >> 2, ji = bxx & 3;
        const int b0 = bi * 16, jg0 = ji * 64;
        float* sw = sm;                    // [512][64] rows 0-255 Wih1^T, 256-511 Whh1^T
        float* sa = sm + 32768;            // [16][520] cols 0-255 h0(p-1), 256-511 h1(p-2)
        float* sb = sm + 41088;            // [64]
        ull*   sp = (ull*)(sm + 41152);    // 192 slots * 10 ull

        for (int i = tid; i < 16384; i += 256) {
            int k = i >> 6, j = i & 63;
            sw[i]         = Wih1[(jg0 + j) * HH + k];
            sw[16384 + i] = Whh1[(jg0 + j) * HH + k];
        }
        if (tid < 64) sb[tid] = bih1[jg0 + tid] + bhh1[jg0 + tid] + bias1[jg0 + tid];

        const int jg = tid & 7, bg = (tid >> 3) & 7, ks = tid >> 6;
        const int j0 = jg << 3, r0 = bg << 1, k0 = ks << 7;

        for (int p = 0; p <= TT; ++p) {
            const float* s0 = g_h0buf[(p + 1) & 1];   // h0(p-1)
            const float* s1 = g_h1buf[p & 1];         // h1(p-2)
            for (int i = tid; i < 16 * 64; i += 256) {
                int r = i >> 6, c = (i & 63) << 2;
                *(float4*)&sa[r * 520 + c]       = __ldcg((const float4*)&s0[(b0 + r) * HH + c]);
                *(float4*)&sa[r * 520 + 256 + c] = __ldcg((const float4*)&s1[(b0 + r) * HH + c]);
            }
            __syncthreads();
            if (p >= 1) {
                ull acc[8];
                #pragma unroll
                for (int i = 0; i < 8; ++i) acc[i] = 0ull;

                #pragma unroll 4
                for (int k4 = 0; k4 < 32; ++k4) {
                    int kb = k0 + (k4 << 2);
                    float4 a0 = *(const float4*)&sa[(r0 + 0) * 520 + kb];
                    float4 a1 = *(const float4*)&sa[(r0 + 1) * 520 + kb];
                    #pragma unroll
                    for (int kk = 0; kk < 4; ++kk) {
                        ulonglong2 w01 = *(const ulonglong2*)&sw[(kb + kk) * 64 + j0];
                        ulonglong2 w23 = *(const ulonglong2*)&sw[(kb + kk) * 64 + j0 + 4];
                        ull aa0 = pack2((&a0.x)[kk], (&a0.x)[kk]);
                        ull aa1 = pack2((&a1.x)[kk], (&a1.x)[kk]);
                        fma2(acc[0], aa0, w01.x); fma2(acc[1], aa0, w01.y);
                        fma2(acc[2], aa0, w23.x); fma2(acc[3], aa0, w23.y);
                        fma2(acc[4], aa1, w01.x); fma2(acc[5], aa1, w01.y);
                        fma2(acc[6], aa1, w23.x); fma2(acc[7], aa1, w23.y);
                    }
                }
                if (ks) {
                    ull* q = &sp[(size_t)(((ks - 1) << 6) + (bg << 3) + jg) * 10];
                    #pragma unroll
                    for (int m = 0; m < 4; ++m)
                        *(ulonglong2*)&q[2 * m] = make_ulonglong2(acc[2 * m], acc[2 * m + 1]);
                }
                __syncthreads();
                if (!ks) {
                    #pragma unroll
                    for (int s = 0; s < 3; ++s) {
                        const ull* q = &sp[(size_t)((s << 6) + (bg << 3) + jg) * 10];
                        #pragma unroll
                        for (int m = 0; m < 4; ++m) {
                            ulonglong2 v = *(const ulonglong2*)&q[2 * m];
                            add2(acc[2 * m], v.x); add2(acc[2 * m + 1], v.y);
                        }
                    }
                    const float* b = &sb[j0];
                    #pragma unroll
                    for (int i = 0; i < 2; ++i) {
                        float u0,u1,u2,u3,u4,u5,u6,u7;
                        unpack2(acc[i*4+0],u0,u1); unpack2(acc[i*4+1],u2,u3);
                        unpack2(acc[i*4+2],u4,u5); unpack2(acc[i*4+3],u6,u7);
                        u0=tanh_fast(u0+b[0]); u1=tanh_fast(u1+b[1]);
                        u2=tanh_fast(u2+b[2]); u3=tanh_fast(u3+b[3]);
                        u4=tanh_fast(u4+b[4]); u5=tanh_fast(u5+b[5]);
                        u6=tanh_fast(u6+b[6]); u7=tanh_fast(u7+b[7]);
                        float4 v0 = make_float4(u0,u1,u2,u3);
                        float4 v1 = make_float4(u4,u5,u6,u7);
                        float* dp = &g_h1buf[(p + 1) & 1][(b0 + r0 + i) * HH + jg0 + j0];
                        *(float4*)dp       = v0;
                        *(float4*)(dp + 4) = v1;
                        float* ap = &g_h1all[((size_t)(p - 1) * BB + b0 + r0 + i) * HH + jg0 + j0];
                        *(float4*)ap       = v0;
                        *(float4*)(ap + 4) = v1;
                    }
                }
            } else {
                __syncthreads();
            }
            gbar(NBRNN);
        }
    }
}

// =====================================================================
// Epilogue: logits = h1all @ fc_w^T + fc_b; copy last hidden.
// =====================================================================
__global__ void __launch_bounds__(256) k_epilogue(
    const float* __restrict__ fcw, const float* __restrict__ fcb,
    float* __restrict__ out, int out_size)
{
    int bx = blockIdx.x, tid = threadIdx.x;
    if (bx >= 32768) {
        int i = (bx - 32768) * 256 + tid;
        int base = TT * BB * 2;
        if (base + i < out_size) {
            float v = (i < BB * HH) ? g_h0buf[1][i] : g_h1buf[1][i - BB * HH];
            out[base + i] = v;
        }
        return;
    }
    __shared__ float sfw[2 * HH];
    __shared__ float sfb[2];
    for (int i = tid; i < 2 * HH; i += 256) sfw[i] = fcw[i];
    if (tid < 2) sfb[tid] = fcb[tid];
    __syncthreads();

    int w = tid >> 5, lane = tid & 31;
    size_t row = (size_t)bx * 8 + w;
    const float* hp = &g_h1all[row * HH + lane * 8];
    float4 h0v = *(const float4*)hp;
    float4 h1v = *(const float4*)(hp + 4);
    const float* w0 = &sfw[lane * 8];
    const float* w1 = &sfw[HH + lane * 8];
    float c0 = 0.f, c1 = 0.f;
    #pragma unroll
    for (int q = 0; q < 4; ++q) {
        c0 += (&h0v.x)[q] * w0[q] + (&h1v.x)[q] * w0[q + 4];
        c1 += (&h0v.x)[q] * w1[q] + (&h1v.x)[q] * w1[q + 4];
    }
    #pragma unroll
    for (int off = 16; off > 0; off >>= 1) {
        c0 += __shfl_down_sync(0xFFFFFFFFu, c0, off);
        c1 += __shfl_down_sync(0xFFFFFFFFu, c1, off);
    }
    if (lane == 0) {
        out[row * 2 + 0] = c0 + sfb[0];
        out[row * 2 + 1] = c1 + sfb[1];
    }
}

// ---------------- launch ----------------
extern "C" void kernel_launch(void* const* d_in, const int* in_sizes, int n_in,
                              void* d_out, int out_size) {
    const float* inp    = (const float*)d_in[0];
    const float* hidden = (const float*)d_in[1];
    const float* Wih0   = (const float*)d_in[2];
    const float* bih0   = (const float*)d_in[3];
    const float* Whh0   = (const float*)d_in[4];
    const float* bhh0   = (const float*)d_in[5];
    const float* bias0  = (const float*)d_in[6];
    const float* Wih1   = (const float*)d_in[7];
    const float* bih1   = (const float*)d_in[8];
    const float* Whh1   = (const float*)d_in[9];
    const float* bhh1   = (const float*)d_in[10];
    const float* bias1  = (const float*)d_in[11];
    const float* fcw    = (const float*)d_in[12];
    const float* fcb    = (const float*)d_in[13];
    float* out = (float*)d_out;

    static bool attr_done = false;
    if (!attr_done) {
        cudaFuncSetAttribute(k_prologue, cudaFuncAttributeMaxDynamicSharedMemorySize, PRO_SMEM);
        cudaFuncSetAttribute(k_rnn,      cudaFuncAttributeMaxDynamicSharedMemorySize, RNN_SMEM);
        attr_done = true;
    }

    k_prologue<<<16392, 256, PRO_SMEM>>>(inp, Wih0, bih0, bhh0, bias0, hidden);
    k_rnn<<<NBRNN, 256, RNN_SMEM>>>(Whh0, Wih1, Whh1, bih1, bhh1, bias1);
    k_epilogue<<<33280, 256>>>(fcw, fcb, out, out_size);
}

// round 4
// speedup vs baseline: 1.7243x; 1.0285x over previous
#include <cuda_runtime.h>
#include <cstddef>

#define TT    1024
#define BB    256
#define INDIM 128
#define HH    256

typedef unsigned long long ull;

// ---------------- scratch (device globals) ----------------
__device__ float g_X0[(size_t)TT * BB * HH];      // input proj (bias added), [T*B, H]
__device__ float g_h1all[(size_t)TT * BB * HH];   // all layer-1 hidden states
__device__ float g_h0ring[4][BB * HH];            // h0 ring, slot = t & 3
__device__ float g_h1ring[4][BB * HH];            // h1 ring, slot = t & 3
__device__ __align__(128) unsigned g_cnt0;        // group0 monotonic arrival count
__device__ __align__(128) unsigned g_cnt1;        // group1 monotonic arrival count
__device__ __align__(128) int g_seq0;             // steps completed by group0
__device__ __align__(128) int g_seq1;             // steps completed by group1

// ---------------- acq/rel primitives (no membar.gl anywhere) ----------------
__device__ __forceinline__ unsigned arrive_acqrel(unsigned* p) {
    unsigned r;
    asm volatile("atom.acq_rel.gpu.global.add.u32 %0, [%1], 1;" : "=r"(r) : "l"(p) : "memory");
    return r;
}
__device__ __forceinline__ int ld_acq(const int* p) {
    int r;
    asm volatile("ld.acquire.gpu.global.s32 %0, [%1];" : "=r"(r) : "l"(p) : "memory");
    return r;
}
__device__ __forceinline__ void st_rel(int* p, int v) {
    asm volatile("st.release.gpu.global.s32 [%0], %1;" :: "l"(p), "r"(v) : "memory");
}

// ---------------- f32x2 helpers ----------------
__device__ __forceinline__ ull pack2(float lo, float hi) {
    ull r; asm("mov.b64 %0, {%1, %2};" : "=l"(r) : "f"(lo), "f"(hi)); return r;
}
__device__ __forceinline__ void unpack2(ull v, float& lo, float& hi) {
    asm("mov.b64 {%0, %1}, %2;" : "=f"(lo), "=f"(hi) : "l"(v));
}
__device__ __forceinline__ void fma2(ull& d, ull a, ull b) {
    asm("fma.rn.f32x2 %0, %1, %2, %0;" : "+l"(d) : "l"(a), "l"(b));
}
__device__ __forceinline__ void add2(ull& d, ull a) {
    asm("add.rn.f32x2 %0, %0, %1;" : "+l"(d) : "l"(a));
}

__device__ __forceinline__ float tanh_fast(float x) {
    float xc = fminf(fmaxf(x, -15.0f), 15.0f);
    float e  = __expf(2.0f * xc);
    return __fdividef(e - 1.0f, e + 1.0f);
}

// =====================================================================
// Prologue: X0 = input @ Wih0^T + biases; init rings; reset sync state.
// =====================================================================
#define PRO_SMEM 85248
__global__ void __launch_bounds__(256) k_prologue(
    const float* __restrict__ inp, const float* __restrict__ Wih0,
    const float* __restrict__ bih0, const float* __restrict__ bhh0,
    const float* __restrict__ bias0, const float* __restrict__ hidden)
{
    int bx = blockIdx.x, tid = threadIdx.x;
    if (bx >= 16384) {
        if (bx == 16384 && tid == 0) {
            g_cnt0 = 0; g_cnt1 = 0; g_seq0 = 0; g_seq1 = 0;
        }
        int base = (bx - 16384) * 16384;
        for (int s = 0; s < 64; ++s) {
            int i = base + s * 256 + tid;
            float v = hidden[i];
            if (i < BB * HH) g_h0ring[3][i] = v;             // h0(-1) -> slot 3
            else             g_h1ring[3][i - BB * HH] = v;   // h1(-1) -> slot 3
        }
        return;
    }
    extern __shared__ float sm[];
    float* sw = sm;                 // [128][64]
    float* sa = sm + 8192;          // [64][132]
    float* sb = sm + 16640;         // [64]
    ull*   sp = (ull*)(sm + 16704); // 128 slots * 18 ull

    int rt = bx >> 2, ji = bx & 3;
    int row0 = rt * 64, jg0 = ji * 64;

    for (int i = tid; i < 8192; i += 256) {
        int k = i >> 6, j = i & 63;
        sw[i] = Wih0[(jg0 + j) * INDIM + k];
    }
    for (int i = tid; i < 64 * 32; i += 256) {
        int r = i >> 5, c = (i & 31) << 2;
        *(float4*)&sa[r * 132 + c] = *(const float4*)&inp[(size_t)(row0 + r) * INDIM + c];
    }
    if (tid < 64) sb[tid] = bih0[jg0 + tid] + bhh0[jg0 + tid] + bias0[jg0 + tid];
    __syncthreads();

    const int jg = tid & 7, bg = (tid >> 3) & 15, ks = tid >> 7;
    const int j0 = jg << 3, r0 = bg << 2, k0 = ks << 6;

    ull acc[16];
    #pragma unroll
    for (int i = 0; i < 16; ++i) acc[i] = 0ull;

    #pragma unroll 4
    for (int k4 = 0; k4 < 16; ++k4) {
        int kb = k0 + (k4 << 2);
        float4 a0 = *(const float4*)&sa[(r0 + 0) * 132 + kb];
        float4 a1 = *(const float4*)&sa[(r0 + 1) * 132 + kb];
        float4 a2 = *(const float4*)&sa[(r0 + 2) * 132 + kb];
        float4 a3 = *(const float4*)&sa[(r0 + 3) * 132 + kb];
        #pragma unroll
        for (int kk = 0; kk < 4; ++kk) {
            ulonglong2 w01 = *(const ulonglong2*)&sw[(kb + kk) * 64 + j0];
            ulonglong2 w23 = *(const ulonglong2*)&sw[(kb + kk) * 64 + j0 + 4];
            ull aa0 = pack2((&a0.x)[kk], (&a0.x)[kk]);
            ull aa1 = pack2((&a1.x)[kk], (&a1.x)[kk]);
            ull aa2 = pack2((&a2.x)[kk], (&a2.x)[kk]);
            ull aa3 = pack2((&a3.x)[kk], (&a3.x)[kk]);
            fma2(acc[0],  aa0, w01.x); fma2(acc[1],  aa0, w01.y);
            fma2(acc[2],  aa0, w23.x); fma2(acc[3],  aa0, w23.y);
            fma2(acc[4],  aa1, w01.x); fma2(acc[5],  aa1, w01.y);
            fma2(acc[6],  aa1, w23.x); fma2(acc[7],  aa1, w23.y);
            fma2(acc[8],  aa2, w01.x); fma2(acc[9],  aa2, w01.y);
            fma2(acc[10], aa2, w23.x); fma2(acc[11], aa2, w23.y);
            fma2(acc[12], aa3, w01.x); fma2(acc[13], aa3, w01.y);
            fma2(acc[14], aa3, w23.x); fma2(acc[15], aa3, w23.y);
        }
    }

    if (ks) {
        ull* q = &sp[(size_t)((bg << 3) + jg) * 18];
        #pragma unroll
        for (int m = 0; m < 8; ++m)
            *(ulonglong2*)&q[2 * m] = make_ulonglong2(acc[2 * m], acc[2 * m + 1]);
    }
    __syncthreads();
    if (!ks) {
        const ull* q = &sp[(size_t)((bg << 3) + jg) * 18];
        #pragma unroll
        for (int m = 0; m < 8; ++m) {
            ulonglong2 v = *(const ulonglong2*)&q[2 * m];
            add2(acc[2 * m], v.x); add2(acc[2 * m + 1], v.y);
        }
        #pragma unroll
        for (int i = 0; i < 4; ++i) {
            float u0,u1,u2,u3,u4,u5,u6,u7;
            unpack2(acc[i*4+0],u0,u1); unpack2(acc[i*4+1],u2,u3);
            unpack2(acc[i*4+2],u4,u5); unpack2(acc[i*4+3],u6,u7);
            const float* b = &sb[j0];
            float* op = &g_X0[(size_t)(row0 + r0 + i) * HH + jg0 + j0];
            *(float4*)op       = make_float4(u0+b[0], u1+b[1], u2+b[2], u3+b[3]);
            *(float4*)(op + 4) = make_float4(u4+b[4], u5+b[5], u6+b[6], u7+b[7]);
        }
    }
}

// =====================================================================
// Persistent recurrence kernel, decoupled groups.
// CTAs 0..31  (group0): layer0, tile 32b x 64j, K=256 split 4.
// CTAs 32..95 (group1): layer1, tile 16b x 64j, K=512 split 4.
// group0 step t: reads h0(t-1) [slot (t+3)&3], writes h0(t) [slot t&3].
//   guard: g_seq1 >= t-3 (ring overwrite). publish: g_seq0 = t+1.
// group1 step t: reads h0(t) [needs g_seq0 >= t+1] and h1(t-1) [slot (t+3)&3],
//   writes h1(t) [slot t&3] + g_h1all[t]. publish: g_seq1 = t+1.
// =====================================================================
#define RNN_SMEM 179968
__global__ void __launch_bounds__(256, 1) k_rnn(
    const float* __restrict__ Whh0, const float* __restrict__ Wih1,
    const float* __restrict__ Whh1, const float* __restrict__ bih1,
    const float* __restrict__ bhh1, const float* __restrict__ bias1)
{
    extern __shared__ float sm[];
    const int bx = blockIdx.x, tid = threadIdx.x;

    if (bx < 32) {
        // ---------------- layer 0 ----------------
        const int bi = bx >> 2, ji = bx & 3;
        const int b0 = bi * 32, jg0 = ji * 64;
        float* sw = sm;                    // [256][64]
        float* sa = sm + 16384;            // [32][260]
        ull*   sp = (ull*)(sm + 24704);    // 192 slots * 18 ull

        for (int i = tid; i < 16384; i += 256) {
            int k = i >> 6, j = i & 63;
            sw[i] = Whh0[(jg0 + j) * HH + k];
        }
        const int jg = tid & 7, bg = (tid >> 3) & 7, ks = tid >> 6;
        const int j0 = jg << 3, r0 = bg << 2, k0 = ks << 6;

        for (int t = 0; t < TT; ++t) {
            // ring overwrite guard: layer1 must have consumed h0(t-4)
            while (ld_acq(&g_seq1) < t - 3) { }
            const float* src = g_h0ring[(t + 3) & 3];   // h0(t-1)
            for (int i = tid; i < 32 * 64; i += 256) {
                int r = i >> 6, c = (i & 63) << 2;
                *(float4*)&sa[r * 260 + c] = __ldcg((const float4*)&src[(b0 + r) * HH + c]);
            }
            __syncthreads();

            // prefetch X0 (ks==0 warps only; warp-uniform branch)
            float4 px0[4], px1[4];
            if (!ks) {
                #pragma unroll
                for (int i = 0; i < 4; ++i) {
                    const float* xp = &g_X0[((size_t)t * BB + b0 + r0 + i) * HH + jg0 + j0];
                    px0[i] = __ldcg((const float4*)xp);
                    px1[i] = __ldcg((const float4*)(xp + 4));
                }
            }

            ull acc[16];
            #pragma unroll
            for (int i = 0; i < 16; ++i) acc[i] = 0ull;

            #pragma unroll 4
            for (int k4 = 0; k4 < 16; ++k4) {
                int kb = k0 + (k4 << 2);
                float4 a0 = *(const float4*)&sa[(r0 + 0) * 260 + kb];
                float4 a1 = *(const float4*)&sa[(r0 + 1) * 260 + kb];
                float4 a2 = *(const float4*)&sa[(r0 + 2) * 260 + kb];
                float4 a3 = *(const float4*)&sa[(r0 + 3) * 260 + kb];
                #pragma unroll
                for (int kk = 0; kk < 4; ++kk) {
                    ulonglong2 w01 = *(const ulonglong2*)&sw[(kb + kk) * 64 + j0];
                    ulonglong2 w23 = *(const ulonglong2*)&sw[(kb + kk) * 64 + j0 + 4];
                    ull aa0 = pack2((&a0.x)[kk], (&a0.x)[kk]);
                    ull aa1 = pack2((&a1.x)[kk], (&a1.x)[kk]);
                    ull aa2 = pack2((&a2.x)[kk], (&a2.x)[kk]);
                    ull aa3 = pack2((&a3.x)[kk], (&a3.x)[kk]);
                    fma2(acc[0],  aa0, w01.x); fma2(acc[1],  aa0, w01.y);
                    fma2(acc[2],  aa0, w23.x); fma2(acc[3],  aa0, w23.y);
                    fma2(acc[4],  aa1, w01.x); fma2(acc[5],  aa1, w01.y);
                    fma2(acc[6],  aa1, w23.x); fma2(acc[7],  aa1, w23.y);
                    fma2(acc[8],  aa2, w01.x); fma2(acc[9],  aa2, w01.y);
                    fma2(acc[10], aa2, w23.x); fma2(acc[11], aa2, w23.y);
                    fma2(acc[12], aa3, w01.x); fma2(acc[13], aa3, w01.y);
                    fma2(acc[14], aa3, w23.x); fma2(acc[15], aa3, w23.y);
                }
            }
            if (ks) {
                ull* q = &sp[(size_t)(((ks - 1) << 6) + (bg << 3) + jg) * 18];
                #pragma unroll
                for (int m = 0; m < 8; ++m)
                    *(ulonglong2*)&q[2 * m] = make_ulonglong2(acc[2 * m], acc[2 * m + 1]);
            }
            __syncthreads();
            if (!ks) {
                #pragma unroll
                for (int s = 0; s < 3; ++s) {
                    const ull* q = &sp[(size_t)((s << 6) + (bg << 3) + jg) * 18];
                    #pragma unroll
                    for (int m = 0; m < 8; ++m) {
                        ulonglong2 v = *(const ulonglong2*)&q[2 * m];
                        add2(acc[2 * m], v.x); add2(acc[2 * m + 1], v.y);
                    }
                }
                #pragma unroll
                for (int i = 0; i < 4; ++i) {
                    float u0,u1,u2,u3,u4,u5,u6,u7;
                    unpack2(acc[i*4+0],u0,u1); unpack2(acc[i*4+1],u2,u3);
                    unpack2(acc[i*4+2],u4,u5); unpack2(acc[i*4+3],u6,u7);
                    u0=tanh_fast(u0+px0[i].x); u1=tanh_fast(u1+px0[i].y);
                    u2=tanh_fast(u2+px0[i].z); u3=tanh_fast(u3+px0[i].w);
                    u4=tanh_fast(u4+px1[i].x); u5=tanh_fast(u5+px1[i].y);
                    u6=tanh_fast(u6+px1[i].z); u7=tanh_fast(u7+px1[i].w);
                    float* dp = &g_h0ring[t & 3][(b0 + r0 + i) * HH + jg0 + j0];
                    *(float4*)dp       = make_float4(u0,u1,u2,u3);
                    *(float4*)(dp + 4) = make_float4(u4,u5,u6,u7);
                }
            }
            // group0 barrier + publish
            __syncthreads();
            if (tid == 0) {
                unsigned r = arrive_acqrel(&g_cnt0);
                if (r == 32u * (unsigned)(t + 1) - 1u) st_rel(&g_seq0, t + 1);
            }
            while (ld_acq(&g_seq0) < t + 1) { }
        }
    } else {
        // ---------------- layer 1 ----------------
        const int bxx = bx - 32;
        const int bi = bxx >> 2, ji = bxx & 3;
        const int b0 = bi * 16, jg0 = ji * 64;
        float* sw = sm;                    // [512][64]: rows 0-255 Wih1^T, 256-511 Whh1^T
        float* sa = sm + 32768;            // [16][520]: cols 0-255 h0(t), 256-511 h1(t-1)
        float* sb = sm + 41088;            // [64]
        ull*   sp = (ull*)(sm + 41152);    // 192 slots * 10 ull

        for (int i = tid; i < 16384; i += 256) {
            int k = i >> 6, j = i & 63;
            sw[i]         = Wih1[(jg0 + j) * HH + k];
            sw[16384 + i] = Whh1[(jg0 + j) * HH + k];
        }
        if (tid < 64) sb[tid] = bih1[jg0 + tid] + bhh1[jg0 + tid] + bias1[jg0 + tid];

        const int jg = tid & 7, bg = (tid >> 3) & 7, ks = tid >> 6;
        const int j0 = jg << 3, r0 = bg << 1, k0 = ks << 7;

        for (int t = 0; t < TT; ++t) {
            while (ld_acq(&g_seq0) < t + 1) { }        // h0(t) ready
            const float* s0 = g_h0ring[t & 3];         // h0(t)
            const float* s1 = g_h1ring[(t + 3) & 3];   // h1(t-1)
            for (int i = tid; i < 16 * 64; i += 256) {
                int r = i >> 6, c = (i & 63) << 2;
                *(float4*)&sa[r * 520 + c]       = __ldcg((const float4*)&s0[(b0 + r) * HH + c]);
                *(float4*)&sa[r * 520 + 256 + c] = __ldcg((const float4*)&s1[(b0 + r) * HH + c]);
            }
            __syncthreads();

            ull acc[8];
            #pragma unroll
            for (int i = 0; i < 8; ++i) acc[i] = 0ull;

            #pragma unroll 4
            for (int k4 = 0; k4 < 32; ++k4) {
                int kb = k0 + (k4 << 2);
                float4 a0 = *(const float4*)&sa[(r0 + 0) * 520 + kb];
                float4 a1 = *(const float4*)&sa[(r0 + 1) * 520 + kb];
                #pragma unroll
                for (int kk = 0; kk < 4; ++kk) {
                    ulonglong2 w01 = *(const ulonglong2*)&sw[(kb + kk) * 64 + j0];
                    ulonglong2 w23 = *(const ulonglong2*)&sw[(kb + kk) * 64 + j0 + 4];
                    ull aa0 = pack2((&a0.x)[kk], (&a0.x)[kk]);
                    ull aa1 = pack2((&a1.x)[kk], (&a1.x)[kk]);
                    fma2(acc[0], aa0, w01.x); fma2(acc[1], aa0, w01.y);
                    fma2(acc[2], aa0, w23.x); fma2(acc[3], aa0, w23.y);
                    fma2(acc[4], aa1, w01.x); fma2(acc[5], aa1, w01.y);
                    fma2(acc[6], aa1, w23.x); fma2(acc[7], aa1, w23.y);
                }
            }
            if (ks) {
                ull* q = &sp[(size_t)(((ks - 1) << 6) + (bg << 3) + jg) * 10];
                #pragma unroll
                for (int m = 0; m < 4; ++m)
                    *(ulonglong2*)&q[2 * m] = make_ulonglong2(acc[2 * m], acc[2 * m + 1]);
            }
            __syncthreads();
            if (!ks) {
                #pragma unroll
                for (int s = 0; s < 3; ++s) {
                    const ull* q = &sp[(size_t)((s << 6) + (bg << 3) + jg) * 10];
                    #pragma unroll
                    for (int m = 0; m < 4; ++m) {
                        ulonglong2 v = *(const ulonglong2*)&q[2 * m];
                        add2(acc[2 * m], v.x); add2(acc[2 * m + 1], v.y);
                    }
                }
                const float* b = &sb[j0];
                #pragma unroll
                for (int i = 0; i < 2; ++i) {
                    float u0,u1,u2,u3,u4,u5,u6,u7;
                    unpack2(acc[i*4+0],u0,u1); unpack2(acc[i*4+1],u2,u3);
                    unpack2(acc[i*4+2],u4,u5); unpack2(acc[i*4+3],u6,u7);
                    u0=tanh_fast(u0+b[0]); u1=tanh_fast(u1+b[1]);
                    u2=tanh_fast(u2+b[2]); u3=tanh_fast(u3+b[3]);
                    u4=tanh_fast(u4+b[4]); u5=tanh_fast(u5+b[5]);
                    u6=tanh_fast(u6+b[6]); u7=tanh_fast(u7+b[7]);
                    float4 v0 = make_float4(u0,u1,u2,u3);
                    float4 v1 = make_float4(u4,u5,u6,u7);
                    float* dp = &g_h1ring[t & 3][(b0 + r0 + i) * HH + jg0 + j0];
                    *(float4*)dp       = v0;
                    *(float4*)(dp + 4) = v1;
                    float* ap = &g_h1all[((size_t)t * BB + b0 + r0 + i) * HH + jg0 + j0];
                    __stcs((float4*)ap, v0);
                    __stcs((float4*)(ap + 4), v1);
                }
            }
            // group1 barrier + publish
            __syncthreads();
            if (tid == 0) {
                unsigned r = arrive_acqrel(&g_cnt1);
                if (r == 64u * (unsigned)(t + 1) - 1u) st_rel(&g_seq1, t + 1);
            }
            while (ld_acq(&g_seq1) < t + 1) { }
        }
    }
}

// =====================================================================
// Epilogue: logits = h1all @ fc_w^T + fc_b; copy last hidden.
// =====================================================================
__global__ void __launch_bounds__(256) k_epilogue(
    const float* __restrict__ fcw, const float* __restrict__ fcb,
    float* __restrict__ out, int out_size)
{
    int bx = blockIdx.x, tid = threadIdx.x;
    if (bx >= 32768) {
        int i = (bx - 32768) * 256 + tid;
        int base = TT * BB * 2;
        if (base + i < out_size) {
            // h0(1023) -> slot 1023&3 = 3; h1(1023) -> slot 3
            float v = (i < BB * HH) ? g_h0ring[3][i] : g_h1ring[3][i - BB * HH];
            out[base + i] = v;
        }
        return;
    }
    __shared__ float sfw[2 * HH];
    __shared__ float sfb[2];
    for (int i = tid; i < 2 * HH; i += 256) sfw[i] = fcw[i];
    if (tid < 2) sfb[tid] = fcb[tid];
    __syncthreads();

    int w = tid >> 5, lane = tid & 31;
    size_t row = (size_t)bx * 8 + w;
    const float* hp = &g_h1all[row * HH + lane * 8];
    float4 h0v = *(const float4*)hp;
    float4 h1v = *(const float4*)(hp + 4);
    const float* w0 = &sfw[lane * 8];
    const float* w1 = &sfw[HH + lane * 8];
    float c0 = 0.f, c1 = 0.f;
    #pragma unroll
    for (int q = 0; q < 4; ++q) {
        c0 += (&h0v.x)[q] * w0[q] + (&h1v.x)[q] * w0[q + 4];
        c1 += (&h0v.x)[q] * w1[q] + (&h1v.x)[q] * w1[q + 4];
    }
    #pragma unroll
    for (int off = 16; off > 0; off >>= 1) {
        c0 += __shfl_down_sync(0xFFFFFFFFu, c0, off);
        c1 += __shfl_down_sync(0xFFFFFFFFu, c1, off);
    }
    if (lane == 0) {
        out[row * 2 + 0] = c0 + sfb[0];
        out[row * 2 + 1] = c1 + sfb[1];
    }
}

// ---------------- launch ----------------
extern "C" void kernel_launch(void* const* d_in, const int* in_sizes, int n_in,
                              void* d_out, int out_size) {
    const float* inp    = (const float*)d_in[0];
    const float* hidden = (const float*)d_in[1];
    const float* Wih0   = (const float*)d_in[2];
    const float* bih0   = (const float*)d_in[3];
    const float* Whh0   = (const float*)d_in[4];
    const float* bhh0   = (const float*)d_in[5];
    const float* bias0  = (const float*)d_in[6];
    const float* Wih1   = (const float*)d_in[7];
    const float* bih1   = (const float*)d_in[8];
    const float* Whh1   = (const float*)d_in[9];
    const float* bhh1   = (const float*)d_in[10];
    const float* bias1  = (const float*)d_in[11];
    const float* fcw    = (const float*)d_in[12];
    const float* fcb    = (const float*)d_in[13];
    float* out = (float*)d_out;

    static bool attr_done = false;
    if (!attr_done) {
        cudaFuncSetAttribute(k_prologue, cudaFuncAttributeMaxDynamicSharedMemorySize, PRO_SMEM);
        cudaFuncSetAttribute(k_rnn,      cudaFuncAttributeMaxDynamicSharedMemorySize, RNN_SMEM);
        attr_done = true;
    }

    k_prologue<<<16392, 256, PRO_SMEM>>>(inp, Wih0, bih0, bhh0, bias0, hidden);
    k_rnn<<<96, 256, RNN_SMEM>>>(Whh0, Wih1, Whh1, bih1, bhh1, bias1);
    k_epilogue<<<33280, 256>>>(fcw, fcb, out, out_size);
}

// round 5
// speedup vs baseline: 2.0167x; 1.1695x over previous
#include <cuda_runtime.h>
#include <cstddef>

#define TT    1024
#define BB    256
#define INDIM 128
#define HH    256

typedef unsigned long long ull;

// ---------------- scratch (device globals) ----------------
__device__ float g_X0[(size_t)TT * BB * HH];      // input proj + biases, [T*B, H]
__device__ float g_h1all[(size_t)TT * BB * HH];   // all layer-1 hidden states
__device__ float g_h0ring[4][BB * HH];            // h0 ring, slot = t & 3
__device__ float g_h1ring[4][BB * HH];            // h1 ring, slot = t & 3
__device__ __align__(128) unsigned g_cnt0;
__device__ __align__(128) unsigned g_cnt1;
__device__ __align__(128) int g_seq0;
__device__ __align__(128) int g_seq1;

// ---------------- acq/rel primitives ----------------
__device__ __forceinline__ unsigned arrive_acqrel(unsigned* p) {
    unsigned r;
    asm volatile("atom.acq_rel.gpu.global.add.u32 %0, [%1], 1;" : "=r"(r) : "l"(p) : "memory");
    return r;
}
__device__ __forceinline__ int ld_acq(const int* p) {
    int r;
    asm volatile("ld.acquire.gpu.global.s32 %0, [%1];" : "=r"(r) : "l"(p) : "memory");
    return r;
}
__device__ __forceinline__ void st_rel(int* p, int v) {
    asm volatile("st.release.gpu.global.s32 [%0], %1;" :: "l"(p), "r"(v) : "memory");
}

// ---------------- f32x2 helpers ----------------
__device__ __forceinline__ ull pack2(float lo, float hi) {
    ull r; asm("mov.b64 %0, {%1, %2};" : "=l"(r) : "f"(lo), "f"(hi)); return r;
}
__device__ __forceinline__ void unpack2(ull v, float& lo, float& hi) {
    asm("mov.b64 {%0, %1}, %2;" : "=f"(lo), "=f"(hi) : "l"(v));
}
__device__ __forceinline__ void fma2(ull& d, ull a, ull b) {
    asm("fma.rn.f32x2 %0, %1, %2, %0;" : "+l"(d) : "l"(a), "l"(b));
}
__device__ __forceinline__ void add2(ull& d, ull a) {
    asm("add.rn.f32x2 %0, %0, %1;" : "+l"(d) : "l"(a));
}

__device__ __forceinline__ float tanh_fast(float x) {
    float xc = fminf(fmaxf(x, -15.0f), 15.0f);
    float e  = __expf(2.0f * xc);
    return __fdividef(e - 1.0f, e + 1.0f);
}

// =====================================================================
// Prologue: X0 = input @ Wih0^T + biases; init rings; reset sync.
// 16384 GEMM CTAs (tile 64b x 64j, K=128) + 8 copy CTAs.
// Thread map: jg=tid&7, bg=(tid>>3)&7, ks=tid>>6 (K-chunk 32).
// Thread tile 8b x 8j. A transposed+duplicated in smem.
// =====================================================================
#define PRO_SMEM 100608
__global__ void __launch_bounds__(256) k_prologue(
    const float* __restrict__ inp, const float* __restrict__ Wih0,
    const float* __restrict__ bih0, const float* __restrict__ bhh0,
    const float* __restrict__ bias0, const float* __restrict__ hidden)
{
    int bx = blockIdx.x, tid = threadIdx.x;
    if (bx >= 16384) {
        if (bx == 16384 && tid == 0) {
            g_cnt0 = 0; g_cnt1 = 0; g_seq0 = 0; g_seq1 = 0;
        }
        int base = (bx - 16384) * 16384;
        for (int s = 0; s < 64; ++s) {
            int i = base + s * 256 + tid;
            float v = hidden[i];
            if (i < BB * HH) g_h0ring[3][i] = v;
            else             g_h1ring[3][i - BB * HH] = v;
        }
        return;
    }
    extern __shared__ char smch[];
    float* sw  = (float*)smch;              // [128][64]  32KB
    ull*   saD = (ull*)(smch + 32768);      // [128 rows][66 ull] dup-A (67584B)
    float* sb  = (float*)(smch + 100352);   // [64]
    ull*   RED = saD;                       // alias (64KB used)

    int rt = bx >> 2, ji = bx & 3;
    int row0 = rt * 64, jg0 = ji * 64;

    for (int i = tid; i < 8192; i += 256) {
        int k = i >> 6, j = i & 63;
        sw[i] = Wih0[(jg0 + j) * INDIM + k];
    }
    if (tid < 64) sb[tid] = bih0[jg0 + tid] + bhh0[jg0 + tid] + bias0[jg0 + tid];

    // stage input transposed + duplicated: saD[k][b] = (v,v)
    #pragma unroll
    for (int it = 0; it < 8; ++it) {
        int i = tid + it * 256;           // 0..2047
        int r = i >> 5, c = (i & 31) << 2;
        float4 v = *(const float4*)&inp[(size_t)(row0 + r) * INDIM + c];
        ull* d = &saD[(size_t)c * 66 + r];
        d[0]   = pack2(v.x, v.x);
        d[66]  = pack2(v.y, v.y);
        d[132] = pack2(v.z, v.z);
        d[198] = pack2(v.w, v.w);
    }
    __syncthreads();

    const int jg = tid & 7, bg = (tid >> 3) & 7, ks = tid >> 6;
    const int k0 = ks << 5;
    const ull* swU = (const ull*)sw;

    ull acc[32];
    #pragma unroll
    for (int m = 0; m < 32; ++m) acc[m] = 0ull;

    const ull* pA = &saD[(size_t)k0 * 66 + (bg << 3)];
    const ull* pW = &swU[(size_t)k0 * 32 + (jg << 2)];
    #pragma unroll 4
    for (int k = 0; k < 32; ++k) {
        ulonglong2 A01 = *(const ulonglong2*)(pA);
        ulonglong2 A23 = *(const ulonglong2*)(pA + 2);
        ulonglong2 A45 = *(const ulonglong2*)(pA + 4);
        ulonglong2 A67 = *(const ulonglong2*)(pA + 6);
        ulonglong2 w01 = *(const ulonglong2*)(pW);
        ulonglong2 w23 = *(const ulonglong2*)(pW + 2);
        fma2(acc[0],  A01.x, w01.x); fma2(acc[1],  A01.x, w01.y); fma2(acc[2],  A01.x, w23.x); fma2(acc[3],  A01.x, w23.y);
        fma2(acc[4],  A01.y, w01.x); fma2(acc[5],  A01.y, w01.y); fma2(acc[6],  A01.y, w23.x); fma2(acc[7],  A01.y, w23.y);
        fma2(acc[8],  A23.x, w01.x); fma2(acc[9],  A23.x, w01.y); fma2(acc[10], A23.x, w23.x); fma2(acc[11], A23.x, w23.y);
        fma2(acc[12], A23.y, w01.x); fma2(acc[13], A23.y, w01.y); fma2(acc[14], A23.y, w23.x); fma2(acc[15], A23.y, w23.y);
        fma2(acc[16], A45.x, w01.x); fma2(acc[17], A45.x, w01.y); fma2(acc[18], A45.x, w23.x); fma2(acc[19], A45.x, w23.y);
        fma2(acc[20], A45.y, w01.x); fma2(acc[21], A45.y, w01.y); fma2(acc[22], A45.y, w23.x); fma2(acc[23], A45.y, w23.y);
        fma2(acc[24], A67.x, w01.x); fma2(acc[25], A67.x, w01.y); fma2(acc[26], A67.x, w23.x); fma2(acc[27], A67.x, w23.y);
        fma2(acc[28], A67.y, w01.x); fma2(acc[29], A67.y, w01.y); fma2(acc[30], A67.y, w23.x); fma2(acc[31], A67.y, w23.y);
        pA += 66; pW += 32;
    }
    __syncthreads();   // saD reads done before RED alias writes

    const int pos = (bg << 3) | jg;
    #pragma unroll
    for (int i = 0; i < 16; ++i)
        *(ulonglong2*)&RED[(size_t)((i << 2) + ks) * 128 + (pos << 1)] =
            make_ulonglong2(acc[2 * i], acc[2 * i + 1]);
    __syncthreads();

    const int wi = tid >> 5, lane = tid & 31;
    #pragma unroll
    for (int q = 0; q < 4; ++q) {
        int u  = (wi << 2) + q;         // 0..31
        int ch = u >> 1, ph = u & 1;
        int pp = (ph << 5) + lane;      // pos 0..63
        ulonglong2 s = *(const ulonglong2*)&RED[(size_t)(ch << 2) * 128 + (pp << 1)];
        #pragma unroll
        for (int kss = 1; kss < 4; ++kss) {
            ulonglong2 r = *(const ulonglong2*)&RED[(size_t)((ch << 2) + kss) * 128 + (pp << 1)];
            add2(s.x, r.x); add2(s.y, r.y);
        }
        int b = ch >> 1, jp0 = (ch << 1) & 3;
        int row = row0 + ((pp >> 3) << 3) + b;
        int cl  = ((pp & 7) << 3) + (jp0 << 1);   // local col
        float f0, f1, f2, f3;
        unpack2(s.x, f0, f1); unpack2(s.y, f2, f3);
        float4 bb = *(const float4*)&sb[cl];
        *(float4*)&g_X0[(size_t)row * HH + jg0 + cl] =
            make_float4(f0 + bb.x, f1 + bb.y, f2 + bb.z, f3 + bb.w);
    }
}

// =====================================================================
// Persistent recurrence kernel, decoupled groups, transposed dup-A smem.
// CTAs 0..31  (group0): layer0, CTA tile 32b x 64j, K=256, warp=K-chunk 32.
// CTAs 32..95 (group1): layer1, CTA tile 16b x 64j, K=512, warp=K-chunk 64.
// =====================================================================
#define RNN_SMEM 205056
__global__ void __launch_bounds__(256, 1) k_rnn(
    const float* __restrict__ Whh0, const float* __restrict__ Wih1,
    const float* __restrict__ Whh1, const float* __restrict__ bih1,
    const float* __restrict__ bhh1, const float* __restrict__ bias1)
{
    extern __shared__ char smch[];
    const int bx = blockIdx.x, tid = threadIdx.x;
    const int jg = tid & 7, bg = (tid >> 3) & 3, ks = tid >> 5;   // warp id = ks
    const int wi = tid >> 5, lane = tid & 31;

    if (bx < 32) {
        // ================= layer 0 =================
        const int bi = bx >> 2, ji = bx & 3;
        const int b0 = bi * 32, jg0 = ji * 64;
        float* sw  = (float*)smch;              // [256][64] 64KB
        ull*   saD = (ull*)(smch + 65536);      // [256][34 ull] 69632B
        ull*   RED = saD;                       // alias (64KB)
        const ull* swU = (const ull*)sw;

        for (int i = tid; i < 16384; i += 256) {
            int k = i >> 6, j = i & 63;
            sw[i] = Whh0[(jg0 + j) * HH + k];
        }

        // reduce-phase output coordinates (chunks 2*wi, 2*wi+1)
        int rowA[2], colA[2];
        #pragma unroll
        for (int cc = 0; cc < 2; ++cc) {
            int ch = (wi << 1) | cc;
            int b = ch >> 1, jp0 = (ch << 1) & 3;
            rowA[cc] = b0 + ((lane >> 3) << 3) + b;
            colA[cc] = jg0 + ((lane & 7) << 3) + (jp0 << 1);
        }
        const int k0 = ks << 5;

        for (int t = 0; t < TT; ++t) {
            if (tid == 0) { while (ld_acq(&g_seq1) < t - 3) { } }
            __syncthreads();

            // stage h0(t-1) transposed+dup
            const float* src = g_h0ring[(t + 3) & 3];
            #pragma unroll
            for (int it = 0; it < 8; ++it) {
                int i = tid + it * 256;
                int r = i >> 6, c = (i & 63) << 2;
                float4 v = __ldcg((const float4*)&src[(b0 + r) * HH + c]);
                ull* d = &saD[(size_t)c * 34 + r];
                d[0]   = pack2(v.x, v.x);
                d[34]  = pack2(v.y, v.y);
                d[68]  = pack2(v.z, v.z);
                d[102] = pack2(v.w, v.w);
            }
            __syncthreads();

            // prefetch X0 for reduce phase
            float4 px[2];
            #pragma unroll
            for (int cc = 0; cc < 2; ++cc)
                px[cc] = __ldcs((const float4*)&g_X0[((size_t)t * BB + rowA[cc]) * HH + colA[cc]]);

            ull acc[32];
            #pragma unroll
            for (int m = 0; m < 32; ++m) acc[m] = 0ull;

            const ull* pA = &saD[(size_t)k0 * 34 + (bg << 3)];
            const ull* pW = &swU[(size_t)k0 * 32 + (jg << 2)];
            #pragma unroll 4
            for (int k = 0; k < 32; ++k) {
                ulonglong2 A01 = *(const ulonglong2*)(pA);
                ulonglong2 A23 = *(const ulonglong2*)(pA + 2);
                ulonglong2 A45 = *(const ulonglong2*)(pA + 4);
                ulonglong2 A67 = *(const ulonglong2*)(pA + 6);
                ulonglong2 w01 = *(const ulonglong2*)(pW);
                ulonglong2 w23 = *(const ulonglong2*)(pW + 2);
                fma2(acc[0],  A01.x, w01.x); fma2(acc[1],  A01.x, w01.y); fma2(acc[2],  A01.x, w23.x); fma2(acc[3],  A01.x, w23.y);
                fma2(acc[4],  A01.y, w01.x); fma2(acc[5],  A01.y, w01.y); fma2(acc[6],  A01.y, w23.x); fma2(acc[7],  A01.y, w23.y);
                fma2(acc[8],  A23.x, w01.x); fma2(acc[9],  A23.x, w01.y); fma2(acc[10], A23.x, w23.x); fma2(acc[11], A23.x, w23.y);
                fma2(acc[12], A23.y, w01.x); fma2(acc[13], A23.y, w01.y); fma2(acc[14], A23.y, w23.x); fma2(acc[15], A23.y, w23.y);
                fma2(acc[16], A45.x, w01.x); fma2(acc[17], A45.x, w01.y); fma2(acc[18], A45.x, w23.x); fma2(acc[19], A45.x, w23.y);
                fma2(acc[20], A45.y, w01.x); fma2(acc[21], A45.y, w01.y); fma2(acc[22], A45.y, w23.x); fma2(acc[23], A45.y, w23.y);
                fma2(acc[24], A67.x, w01.x); fma2(acc[25], A67.x, w01.y); fma2(acc[26], A67.x, w23.x); fma2(acc[27], A67.x, w23.y);
                fma2(acc[28], A67.y, w01.x); fma2(acc[29], A67.y, w01.y); fma2(acc[30], A67.y, w23.x); fma2(acc[31], A67.y, w23.y);
                pA += 34; pW += 32;
            }
            __syncthreads();   // all saD reads done

            const int pos = (bg << 3) | jg;
            #pragma unroll
            for (int i = 0; i < 16; ++i)
                *(ulonglong2*)&RED[(size_t)((i << 3) + ks) * 64 + (pos << 1)] =
                    make_ulonglong2(acc[2 * i], acc[2 * i + 1]);
            __syncthreads();

            float* dst = g_h0ring[t & 3];
            #pragma unroll
            for (int cc = 0; cc < 2; ++cc) {
                int ch = (wi << 1) | cc;
                ulonglong2 s = *(const ulonglong2*)&RED[(size_t)(ch << 3) * 64 + (lane << 1)];
                #pragma unroll
                for (int kss = 1; kss < 8; ++kss) {
                    ulonglong2 r = *(const ulonglong2*)&RED[(size_t)((ch << 3) + kss) * 64 + (lane << 1)];
                    add2(s.x, r.x); add2(s.y, r.y);
                }
                float f0, f1, f2, f3;
                unpack2(s.x, f0, f1); unpack2(s.y, f2, f3);
                f0 = tanh_fast(f0 + px[cc].x); f1 = tanh_fast(f1 + px[cc].y);
                f2 = tanh_fast(f2 + px[cc].z); f3 = tanh_fast(f3 + px[cc].w);
                *(float4*)&dst[(size_t)rowA[cc] * HH + colA[cc]] = make_float4(f0, f1, f2, f3);
            }

            __syncthreads();
            if (tid == 0) {
                unsigned r = arrive_acqrel(&g_cnt0);
                if (r == 32u * (unsigned)(t + 1) - 1u) st_rel(&g_seq0, t + 1);
                while (ld_acq(&g_seq0) < t + 1) { }
            }
            __syncthreads();
        }
    } else {
        // ================= layer 1 =================
        const int bxx = bx - 32;
        const int bi = bxx >> 2, ji = bxx & 3;
        const int b0 = bi * 16, jg0 = ji * 64;
        float* sw  = (float*)smch;              // [512][64] 128KB
        ull*   saD = (ull*)(smch + 131072);     // [512][18 ull] 73728B
        float* sb  = (float*)(smch + 204800);   // [64]
        ull*   RED = saD;                       // alias (32KB)
        const ull* swU = (const ull*)sw;

        for (int i = tid; i < 16384; i += 256) {
            int k = i >> 6, j = i & 63;
            sw[i]         = Wih1[(jg0 + j) * HH + k];
            sw[16384 + i] = Whh1[(jg0 + j) * HH + k];
        }
        if (tid < 64) sb[tid] = bih1[jg0 + tid] + bhh1[jg0 + tid] + bias1[jg0 + tid];

        // reduce-phase coords (chunk = wi)
        int b = wi >> 1, jp0 = (wi << 1) & 3;
        const int rowR = b0 + ((lane >> 3) << 2) + b;
        const int clR  = ((lane & 7) << 3) + (jp0 << 1);   // local col
        const int k0 = ks << 6;

        for (int t = 0; t < TT; ++t) {
            if (tid == 0) { while (ld_acq(&g_seq0) < t + 1) { } }
            __syncthreads();

            // stage h0(t) rows b0..b0+15 -> k 0..255, h1(t-1) -> k 256..511
            const float* s0 = g_h0ring[t & 3];
            const float* s1 = g_h1ring[(t + 3) & 3];
            #pragma unroll
            for (int it = 0; it < 4; ++it) {
                int i = tid + it * 256;          // 0..1023
                int r = i >> 6, c = (i & 63) << 2;
                float4 v0 = __ldcg((const float4*)&s0[(b0 + r) * HH + c]);
                float4 v1 = __ldcg((const float4*)&s1[(b0 + r) * HH + c]);
                ull* d0 = &saD[(size_t)c * 18 + r];
                d0[0]  = pack2(v0.x, v0.x);
                d0[18] = pack2(v0.y, v0.y);
                d0[36] = pack2(v0.z, v0.z);
                d0[54] = pack2(v0.w, v0.w);
                ull* d1 = &saD[(size_t)(256 + c) * 18 + r];
                d1[0]  = pack2(v1.x, v1.x);
                d1[18] = pack2(v1.y, v1.y);
                d1[36] = pack2(v1.z, v1.z);
                d1[54] = pack2(v1.w, v1.w);
            }
            __syncthreads();

            ull acc[16];
            #pragma unroll
            for (int m = 0; m < 16; ++m) acc[m] = 0ull;

            const ull* pA = &saD[(size_t)k0 * 18 + (bg << 2)];
            const ull* pW = &swU[(size_t)k0 * 32 + (jg << 2)];
            #pragma unroll 4
            for (int k = 0; k < 64; ++k) {
                ulonglong2 A01 = *(const ulonglong2*)(pA);
                ulonglong2 A23 = *(const ulonglong2*)(pA + 2);
                ulonglong2 w01 = *(const ulonglong2*)(pW);
                ulonglong2 w23 = *(const ulonglong2*)(pW + 2);
                fma2(acc[0],  A01.x, w01.x); fma2(acc[1],  A01.x, w01.y); fma2(acc[2],  A01.x, w23.x); fma2(acc[3],  A01.x, w23.y);
                fma2(acc[4],  A01.y, w01.x); fma2(acc[5],  A01.y, w01.y); fma2(acc[6],  A01.y, w23.x); fma2(acc[7],  A01.y, w23.y);
                fma2(acc[8],  A23.x, w01.x); fma2(acc[9],  A23.x, w01.y); fma2(acc[10], A23.x, w23.x); fma2(acc[11], A23.x, w23.y);
                fma2(acc[12], A23.y, w01.x); fma2(acc[13], A23.y, w01.y); fma2(acc[14], A23.y, w23.x); fma2(acc[15], A23.y, w23.y);
                pA += 18; pW += 32;
            }
            __syncthreads();

            const int pos = (bg << 3) | jg;
            #pragma unroll
            for (int i = 0; i < 8; ++i)
                *(ulonglong2*)&RED[(size_t)((i << 3) + ks) * 64 + (pos << 1)] =
                    make_ulonglong2(acc[2 * i], acc[2 * i + 1]);
            __syncthreads();

            {
                ulonglong2 s = *(const ulonglong2*)&RED[(size_t)(wi << 3) * 64 + (lane << 1)];
                #pragma unroll
                for (int kss = 1; kss < 8; ++kss) {
                    ulonglong2 r = *(const ulonglong2*)&RED[(size_t)((wi << 3) + kss) * 64 + (lane << 1)];
                    add2(s.x, r.x); add2(s.y, r.y);
                }
                float f0, f1, f2, f3;
                unpack2(s.x, f0, f1); unpack2(s.y, f2, f3);
                float4 bb = *(const float4*)&sb[clR];
                f0 = tanh_fast(f0 + bb.x); f1 = tanh_fast(f1 + bb.y);
                f2 = tanh_fast(f2 + bb.z); f3 = tanh_fast(f3 + bb.w);
                float4 v = make_float4(f0, f1, f2, f3);
                *(float4*)&g_h1ring[t & 3][(size_t)rowR * HH + jg0 + clR] = v;
                __stcs((float4*)&g_h1all[((size_t)t * BB + rowR) * HH + jg0 + clR], v);
            }

            __syncthreads();
            if (tid == 0) {
                unsigned r = arrive_acqrel(&g_cnt1);
                if (r == 64u * (unsigned)(t + 1) - 1u) st_rel(&g_seq1, t + 1);
                while (ld_acq(&g_seq1) < t + 1) { }
            }
            __syncthreads();
        }
    }
}

// =====================================================================
// Epilogue: logits = h1all @ fc_w^T + fc_b; copy last hidden.
// =====================================================================
__global__ void __launch_bounds__(256) k_epilogue(
    const float* __restrict__ fcw, const float* __restrict__ fcb,
    float* __restrict__ out, int out_size)
{
    int bx = blockIdx.x, tid = threadIdx.x;
    if (bx >= 32768) {
        int i = (bx - 32768) * 256 + tid;
        int base = TT * BB * 2;
        if (base + i < out_size) {
            float v = (i < BB * HH) ? g_h0ring[3][i] : g_h1ring[3][i - BB * HH];
            out[base + i] = v;
        }
        return;
    }
    __shared__ float sfw[2 * HH];
    __shared__ float sfb[2];
    for (int i = tid; i < 2 * HH; i += 256) sfw[i] = fcw[i];
    if (tid < 2) sfb[tid] = fcb[tid];
    __syncthreads();

    int w = tid >> 5, lane = tid & 31;
    size_t row = (size_t)bx * 8 + w;
    const float* hp = &g_h1all[row * HH + lane * 8];
    float4 h0v = *(const float4*)hp;
    float4 h1v = *(const float4*)(hp + 4);
    const float* w0 = &sfw[lane * 8];
    const float* w1 = &sfw[HH + lane * 8];
    float c0 = 0.f, c1 = 0.f;
    #pragma unroll
    for (int q = 0; q < 4; ++q) {
        c0 += (&h0v.x)[q] * w0[q] + (&h1v.x)[q] * w0[q + 4];
        c1 += (&h0v.x)[q] * w1[q] + (&h1v.x)[q] * w1[q + 4];
    }
    #pragma unroll
    for (int off = 16; off > 0; off >>= 1) {
        c0 += __shfl_down_sync(0xFFFFFFFFu, c0, off);
        c1 += __shfl_down_sync(0xFFFFFFFFu, c1, off);
    }
    if (lane == 0) {
        out[row * 2 + 0] = c0 + sfb[0];
        out[row * 2 + 1] = c1 + sfb[1];
    }
}

// ---------------- launch ----------------
extern "C" void kernel_launch(void* const* d_in, const int* in_sizes, int n_in,
                              void* d_out, int out_size) {
    const float* inp    = (const float*)d_in[0];
    const float* hidden = (const float*)d_in[1];
    const float* Wih0   = (const float*)d_in[2];
    const float* bih0   = (const float*)d_in[3];
    const float* Whh0   = (const float*)d_in[4];
    const float* bhh0   = (const float*)d_in[5];
    const float* bias0  = (const float*)d_in[6];
    const float* Wih1   = (const float*)d_in[7];
    const float* bih1   = (const float*)d_in[8];
    const float* Whh1   = (const float*)d_in[9];
    const float* bhh1   = (const float*)d_in[10];
    const float* bias1  = (const float*)d_in[11];
    const float* fcw    = (const float*)d_in[12];
    const float* fcb    = (const float*)d_in[13];
    float* out = (float*)d_out;

    static bool attr_done = false;
    if (!attr_done) {
        cudaFuncSetAttribute(k_prologue, cudaFuncAttributeMaxDynamicSharedMemorySize, PRO_SMEM);
        cudaFuncSetAttribute(k_rnn,      cudaFuncAttributeMaxDynamicSharedMemorySize, RNN_SMEM);
        attr_done = true;
    }

    k_prologue<<<16392, 256, PRO_SMEM>>>(inp, Wih0, bih0, bhh0, bias0, hidden);
    k_rnn<<<96, 256, RNN_SMEM>>>(Whh0, Wih1, Whh1, bih1, bhh1, bias1);
    k_epilogue<<<33280, 256>>>(fcw, fcb, out, out_size);
}

// round 7
// speedup vs baseline: 3.0671x; 1.5209x over previous
#include <cuda_runtime.h>
#include <cstddef>

#define TT    1024
#define BB    256
#define INDIM 128
#define HH    256

typedef unsigned long long ull;

// ---------------- scratch (device globals) ----------------
__device__ float g_X0[(size_t)TT * BB * HH];      // input proj + biases
__device__ float g_h1all[(size_t)TT * BB * HH];   // all layer-1 hidden states
__device__ float g_h0ring[4][BB * HH];
__device__ float g_h1ring[4][BB * HH];
__device__ __align__(128) unsigned g_cnt0;
__device__ __align__(128) unsigned g_cnt1;
__device__ __align__(128) int g_seq0;
__device__ __align__(128) int g_seq1;

// ---------------- acq/rel primitives ----------------
__device__ __forceinline__ unsigned arrive_acqrel(unsigned* p) {
    unsigned r;
    asm volatile("atom.acq_rel.gpu.global.add.u32 %0, [%1], 1;" : "=r"(r) : "l"(p) : "memory");
    return r;
}
__device__ __forceinline__ int ld_acq(const int* p) {
    int r;
    asm volatile("ld.acquire.gpu.global.s32 %0, [%1];" : "=r"(r) : "l"(p) : "memory");
    return r;
}
__device__ __forceinline__ void st_rel(int* p, int v) {
    asm volatile("st.release.gpu.global.s32 [%0], %1;" :: "l"(p), "r"(v) : "memory");
}

// ---------------- f32x2 helpers ----------------
__device__ __forceinline__ void unpack2(ull v, float& lo, float& hi) {
    asm("mov.b64 {%0, %1}, %2;" : "=f"(lo), "=f"(hi) : "l"(v));
}
__device__ __forceinline__ void fma2(ull& d, ull a, ull b) {
    asm("fma.rn.f32x2 %0, %1, %2, %0;" : "+l"(d) : "l"(a), "l"(b));
}
__device__ __forceinline__ void add2(ull& d, ull a) {
    asm("add.rn.f32x2 %0, %0, %1;" : "+l"(d) : "l"(a));
}
__device__ __forceinline__ float pairsum(ull v) {
    float lo, hi; unpack2(v, lo, hi); return lo + hi;
}
__device__ __forceinline__ float tanh_fast(float x) {
    float xc = fminf(fmaxf(x, -15.0f), 15.0f);
    float e  = __expf(2.0f * xc);
    return __fdividef(e - 1.0f, e + 1.0f);
}

// FMA micro-tiles: acc[b*4+j] += a[b].pair * w[j].pair  (pairs along K)
__device__ __forceinline__ void mt8x4(ull* acc, const ulonglong2* a, const ulonglong2* w) {
    #pragma unroll
    for (int b = 0; b < 8; ++b) {
        #pragma unroll
        for (int j = 0; j < 4; ++j) {
            fma2(acc[b * 4 + j], a[b].x, w[j].x);
            fma2(acc[b * 4 + j], a[b].y, w[j].y);
        }
    }
}
__device__ __forceinline__ void mt4x4(ull* acc, const ulonglong2* a, const ulonglong2* w) {
    #pragma unroll
    for (int b = 0; b < 4; ++b) {
        #pragma unroll
        for (int j = 0; j < 4; ++j) {
            fma2(acc[b * 4 + j], a[b].x, w[j].x);
            fma2(acc[b * 4 + j], a[b].y, w[j].y);
        }
    }
}

// =====================================================================
// Prologue: X0 = input @ Wih0^T + biases. Tile 32b x 64j, K=128.
// W layout: group g=j>>2 (stride 544 words), row base g*544+(j&3)*128+(g&7)*4.
// A layout: group r>>3 (stride 1056), row base (r>>3)*1056+(r&7)*128+((r>>3)&3)*4.
// Warps: ks=wi>>1 (4 k-chunks of 32), jh=wi&1. Thread: bg=lane>>3, jg=lane&7.
// =====================================================================
#define PRO_SMEM 100608
__global__ void __launch_bounds__(256) k_prologue(
    const float* __restrict__ inp, const float* __restrict__ Wih0,
    const float* __restrict__ bih0, const float* __restrict__ bhh0,
    const float* __restrict__ bias0, const float* __restrict__ hidden)
{
    int bx = blockIdx.x, tid = threadIdx.x;
    if (bx >= 32768) {
        if (bx == 32768 && tid == 0) {
            g_cnt0 = 0; g_cnt1 = 0; g_seq0 = 0; g_seq1 = 0;
        }
        int base = (bx - 32768) * 16384;
        for (int s = 0; s < 64; ++s) {
            int i = base + s * 256 + tid;
            float v = hidden[i];
            if (i < BB * HH) g_h0ring[3][i] = v;
            else             g_h1ring[3][i - BB * HH] = v;
        }
        return;
    }
    extern __shared__ char smch[];
    float* sw  = (float*)smch;              // W: 16 groups * 544 words = 34816B
    float* sa  = (float*)(smch + 34816);    // A: 4 groups * 1056 words = 16896B
    ull*   RED = (ull*)(smch + 34816);      // alias, 64KB
    float* sb  = (float*)(smch + 100352);   // [64]

    const int rt = bx >> 2, ji = bx & 3;
    const int row0 = rt * 32, jg0 = ji * 64;
    const int lane = tid & 31, wi = tid >> 5;
    const int bg = lane >> 3, jg = lane & 7;
    const int ks = wi >> 1, jh = wi & 1;

    // W staging: conflict-free contiguous rows
    for (int i = tid; i < 2048; i += 256) {
        int j = i >> 5, k4 = (i & 31) << 2;
        *(float4*)&sw[(j >> 2) * 544 + (j & 3) * 128 + (((j >> 2) & 7) << 2) + k4] =
            *(const float4*)&Wih0[(size_t)(jg0 + j) * INDIM + k4];
    }
    // A staging
    for (int i = tid; i < 1024; i += 256) {
        int r = i >> 5, c4 = (i & 31) << 2;
        *(float4*)&sa[(r >> 3) * 1056 + (r & 7) * 128 + (((r >> 3) & 3) << 2) + c4] =
            *(const float4*)&inp[(size_t)(row0 + r) * INDIM + c4];
    }
    if (tid < 64) sb[tid] = bih0[jg0 + tid] + bhh0[jg0 + tid] + bias0[jg0 + tid];
    __syncthreads();

    ull acc[32];
    #pragma unroll
    for (int m = 0; m < 32; ++m) acc[m] = 0ull;

    const int k0 = ks << 5;
    const char* pA = (const char*)sa + ((size_t)bg * 1060 + k0) * 4;
    const char* pW = (const char*)sw + ((size_t)(jh * 8 + jg) * 544 + jg * 4 + k0) * 4;
    #pragma unroll
    for (int kb = 0; kb < 8; ++kb) {
        ulonglong2 a[8], w[4];
        #pragma unroll
        for (int b = 0; b < 8; ++b) a[b] = *(const ulonglong2*)(pA + b * 512);
        #pragma unroll
        for (int j = 0; j < 4; ++j) w[j] = *(const ulonglong2*)(pW + j * 512);
        mt8x4(acc, a, w);
        pA += 16; pW += 16;
    }
    __syncthreads();   // A reads done before RED alias writes

    #pragma unroll
    for (int i = 0; i < 16; ++i)
        *(ulonglong2*)&RED[(size_t)((i << 3) + wi) * 64 + (lane << 1)] =
            make_ulonglong2(acc[2 * i], acc[2 * i + 1]);
    __syncthreads();

    #pragma unroll
    for (int q = 0; q < 4; ++q) {
        int mp = (q << 2) + ks;
        ulonglong2 s = *(const ulonglong2*)&RED[(size_t)((mp << 3) + jh) * 64 + (lane << 1)];
        #pragma unroll
        for (int k2 = 1; k2 < 4; ++k2) {
            ulonglong2 r = *(const ulonglong2*)&RED[(size_t)((mp << 3) + (k2 << 1) + jh) * 64 + (lane << 1)];
            add2(s.x, r.x); add2(s.y, r.y);
        }
        int b_g = row0 + (bg << 3) + (mp >> 1);
        int j_l = (jh << 5) + (jg << 2) + ((mp & 1) << 1);
        float2 bb = *(const float2*)&sb[j_l];
        float2 o = make_float2(pairsum(s.x) + bb.x, pairsum(s.y) + bb.y);
        *(float2*)&g_X0[(size_t)b_g * HH + jg0 + j_l] = o;
    }
}

// =====================================================================
// Persistent recurrence. group0 (CTAs 0..31): layer0 32b x 64j K=256.
// group1 (CTAs 32..95): layer1 16b x 64j K=512 (h0|h1 concat).
// Group-padded swizzled smem; warps: ks=wi>>1, jh=wi&1.
// =====================================================================
#define RNN_SMEM 166656
__global__ void __launch_bounds__(256, 1) k_rnn(
    const float* __restrict__ Whh0, const float* __restrict__ Wih1,
    const float* __restrict__ Whh1, const float* __restrict__ bih1,
    const float* __restrict__ bhh1, const float* __restrict__ bias1)
{
    extern __shared__ char smch[];
    const int bx = blockIdx.x, tid = threadIdx.x;
    const int lane = tid & 31, wi = tid >> 5;
    const int bg = lane >> 3, jg = lane & 7;
    const int ks = wi >> 1, jh = wi & 1;

    if (bx < 32) {
        // ================= layer 0 =================
        const int bi = bx >> 2, ji = bx & 3;
        const int b0 = bi * 32, jg0 = ji * 64;
        float* sw  = (float*)smch;             // W: 16 groups * 1056 words = 67584B
        float* sa  = (float*)(smch + 67584);   // A: 4 groups * 2080 words = 33280B
        ull*   RED = (ull*)(smch + 67584);     // alias, 64KB

        // W staging (once)
        for (int i = tid; i < 4096; i += 256) {
            int j = i >> 6, k4 = (i & 63) << 2;
            *(float4*)&sw[(j >> 2) * 1056 + (j & 3) * 256 + (((j >> 2) & 7) << 2) + k4] =
                *(const float4*)&Whh0[(size_t)(jg0 + j) * HH + k4];
        }

        const int k0 = ks << 6;
        const char* pA0 = (const char*)sa + ((size_t)bg * 2084 + k0) * 4;
        const char* pW0 = (const char*)sw + ((size_t)(jh * 8 + jg) * 1056 + jg * 4 + k0) * 4;

        for (int t = 0; t < TT; ++t) {
            if (tid == 0) { while (ld_acq(&g_seq1) < t - 3) { } }
            __syncthreads();

            // stage h0(t-1)
            const float* src = g_h0ring[(t + 3) & 3];
            #pragma unroll
            for (int it = 0; it < 8; ++it) {
                int i = tid + it * 256;
                int r = i >> 6, c4 = (i & 63) << 2;
                float4 v = __ldcg((const float4*)&src[(b0 + r) * HH + c4]);
                *(float4*)&sa[(r >> 3) * 2080 + (r & 7) * 256 + (((r >> 3) & 3) << 2) + c4] = v;
            }
            __syncthreads();

            ull acc[32];
            #pragma unroll
            for (int m = 0; m < 32; ++m) acc[m] = 0ull;

            const char* pA = pA0;
            const char* pW = pW0;
            #pragma unroll 4
            for (int kb = 0; kb < 16; ++kb) {
                ulonglong2 a[8], w[4];
                #pragma unroll
                for (int b = 0; b < 8; ++b) a[b] = *(const ulonglong2*)(pA + b * 1024);
                #pragma unroll
                for (int j = 0; j < 4; ++j) w[j] = *(const ulonglong2*)(pW + j * 1024);
                mt8x4(acc, a, w);
                pA += 16; pW += 16;
            }

            // prefetch X0 for reduce phase
            float2 px[4];
            #pragma unroll
            for (int q = 0; q < 4; ++q) {
                int mp = (q << 2) + ks;
                int b_g = b0 + (bg << 3) + (mp >> 1);
                int j_l = (jh << 5) + (jg << 2) + ((mp & 1) << 1);
                px[q] = __ldcs((const float2*)&g_X0[((size_t)t * BB + b_g) * HH + jg0 + j_l]);
            }
            __syncthreads();   // A reads done before RED alias writes

            #pragma unroll
            for (int i = 0; i < 16; ++i)
                *(ulonglong2*)&RED[(size_t)((i << 3) + wi) * 64 + (lane << 1)] =
                    make_ulonglong2(acc[2 * i], acc[2 * i + 1]);
            __syncthreads();

            float* dst = g_h0ring[t & 3];
            #pragma unroll
            for (int q = 0; q < 4; ++q) {
                int mp = (q << 2) + ks;
                ulonglong2 s = *(const ulonglong2*)&RED[(size_t)((mp << 3) + jh) * 64 + (lane << 1)];
                #pragma unroll
                for (int k2 = 1; k2 < 4; ++k2) {
                    ulonglong2 r = *(const ulonglong2*)&RED[(size_t)((mp << 3) + (k2 << 1) + jh) * 64 + (lane << 1)];
                    add2(s.x, r.x); add2(s.y, r.y);
                }
                int b_g = b0 + (bg << 3) + (mp >> 1);
                int j_l = (jh << 5) + (jg << 2) + ((mp & 1) << 1);
                float2 o = make_float2(tanh_fast(pairsum(s.x) + px[q].x),
                                       tanh_fast(pairsum(s.y) + px[q].y));
                *(float2*)&dst[(size_t)b_g * HH + jg0 + j_l] = o;
            }

            __syncthreads();
            if (tid == 0) {
                unsigned r = arrive_acqrel(&g_cnt0);
                if (r == 32u * (unsigned)(t + 1) - 1u) st_rel(&g_seq0, t + 1);
                while (ld_acq(&g_seq0) < t + 1) { }
            }
            __syncthreads();
        }
    } else {
        // ================= layer 1 =================
        const int bxx = bx - 32;
        const int bi = bxx >> 2, ji = bxx & 3;
        const int b0 = bi * 16, jg0 = ji * 64;
        float* sw  = (float*)smch;             // W: 16 groups * 2080 words = 133120B
        float* sa  = (float*)(smch + 133120);  // A: 4 groups * 2080 words = 33280B
        ull*   RED = (ull*)(smch + 133120);    // alias, 32KB
        float* sb  = (float*)(smch + 166400);  // [64]

        // W staging: cols 0-255 Wih1, 256-511 Whh1
        for (int i = tid; i < 8192; i += 256) {
            int j = i >> 7, k4 = (i & 127) << 2;
            float4 v = (k4 < 256)
                ? *(const float4*)&Wih1[(size_t)(jg0 + j) * HH + k4]
                : *(const float4*)&Whh1[(size_t)(jg0 + j) * HH + (k4 - 256)];
            *(float4*)&sw[(j >> 2) * 2080 + (j & 3) * 512 + (((j >> 2) & 7) << 2) + k4] = v;
        }
        if (tid < 64) sb[tid] = bih1[jg0 + tid] + bhh1[jg0 + tid] + bias1[jg0 + tid];

        const int k0 = ks << 7;
        const char* pA0 = (const char*)sa + ((size_t)bg * 2084 + k0) * 4;
        const char* pW0 = (const char*)sw + ((size_t)(jh * 8 + jg) * 2080 + jg * 4 + k0) * 4;

        for (int t = 0; t < TT; ++t) {
            if (tid == 0) { while (ld_acq(&g_seq0) < t + 1) { } }
            __syncthreads();

            // stage h0(t) -> cols 0-255, h1(t-1) -> cols 256-511
            const float* s0 = g_h0ring[t & 3];
            const float* s1 = g_h1ring[(t + 3) & 3];
            #pragma unroll
            for (int it = 0; it < 8; ++it) {
                int i = tid + it * 256;
                int r = i >> 7, c4 = (i & 127) << 2;
                float4 v = (c4 < 256)
                    ? __ldcg((const float4*)&s0[(b0 + r) * HH + c4])
                    : __ldcg((const float4*)&s1[(b0 + r) * HH + (c4 - 256)]);
                *(float4*)&sa[(r >> 2) * 2080 + (r & 3) * 512 + (((r >> 2) & 3) << 2) + c4] = v;
            }
            __syncthreads();

            ull acc[16];
            #pragma unroll
            for (int m = 0; m < 16; ++m) acc[m] = 0ull;

            const char* pA = pA0;
            const char* pW = pW0;
            #pragma unroll 4
            for (int kb = 0; kb < 32; ++kb) {
                ulonglong2 a[4], w[4];
                #pragma unroll
                for (int b = 0; b < 4; ++b) a[b] = *(const ulonglong2*)(pA + b * 2048);
                #pragma unroll
                for (int j = 0; j < 4; ++j) w[j] = *(const ulonglong2*)(pW + j * 2048);
                mt4x4(acc, a, w);
                pA += 16; pW += 16;
            }
            __syncthreads();   // A reads done before RED alias writes

            #pragma unroll
            for (int i = 0; i < 8; ++i)
                *(ulonglong2*)&RED[(size_t)((i << 3) + wi) * 64 + (lane << 1)] =
                    make_ulonglong2(acc[2 * i], acc[2 * i + 1]);
            __syncthreads();

            float* dst = g_h1ring[t & 3];
            #pragma unroll
            for (int q = 0; q < 2; ++q) {
                int mp = (q << 2) + ks;
                ulonglong2 s = *(const ulonglong2*)&RED[(size_t)((mp << 3) + jh) * 64 + (lane << 1)];
                #pragma unroll
                for (int k2 = 1; k2 < 4; ++k2) {
                    ulonglong2 r = *(const ulonglong2*)&RED[(size_t)((mp << 3) + (k2 << 1) + jh) * 64 + (lane << 1)];
                    add2(s.x, r.x); add2(s.y, r.y);
                }
                int b_g = b0 + (bg << 2) + (mp >> 1);
                int j_l = (jh << 5) + (jg << 2) + ((mp & 1) << 1);
                float2 bb = *(const float2*)&sb[j_l];
                float2 o = make_float2(tanh_fast(pairsum(s.x) + bb.x),
                                       tanh_fast(pairsum(s.y) + bb.y));
                *(float2*)&dst[(size_t)b_g * HH + jg0 + j_l] = o;
                __stcs((float2*)&g_h1all[((size_t)t * BB + b_g) * HH + jg0 + j_l], o);
            }

            __syncthreads();
            if (tid == 0) {
                unsigned r = arrive_acqrel(&g_cnt1);
                if (r == 64u * (unsigned)(t + 1) - 1u) st_rel(&g_seq1, t + 1);
                while (ld_acq(&g_seq1) < t + 1) { }
            }
            __syncthreads();
        }
    }
}

// =====================================================================
// Epilogue: logits = h1all @ fc_w^T + fc_b; copy last hidden.
// =====================================================================
__global__ void __launch_bounds__(256) k_epilogue(
    const float* __restrict__ fcw, const float* __restrict__ fcb,
    float* __restrict__ out, int out_size)
{
    int bx = blockIdx.x, tid = threadIdx.x;
    if (bx >= 32768) {
        int i = (bx - 32768) * 256 + tid;
        int base = TT * BB * 2;
        if (base + i < out_size) {
            float v = (i < BB * HH) ? g_h0ring[3][i] : g_h1ring[3][i - BB * HH];
            out[base + i] = v;
        }
        return;
    }
    __shared__ float sfw[2 * HH];
    __shared__ float sfb[2];
    for (int i = tid; i < 2 * HH; i += 256) sfw[i] = fcw[i];
    if (tid < 2) sfb[tid] = fcb[tid];
    __syncthreads();

    int w = tid >> 5, lane = tid & 31;
    size_t row = (size_t)bx * 8 + w;
    const float* hp = &g_h1all[row * HH + lane * 8];
    float4 h0v = *(const float4*)hp;
    float4 h1v = *(const float4*)(hp + 4);
    const float* w0 = &sfw[lane * 8];
    const float* w1 = &sfw[HH + lane * 8];
    float c0 = 0.f, c1 = 0.f;
    #pragma unroll
    for (int q = 0; q < 4; ++q) {
        c0 += (&h0v.x)[q] * w0[q] + (&h1v.x)[q] * w0[q + 4];
        c1 += (&h0v.x)[q] * w1[q] + (&h1v.x)[q] * w1[q + 4];
    }
    #pragma unroll
    for (int off = 16; off > 0; off >>= 1) {
        c0 += __shfl_down_sync(0xFFFFFFFFu, c0, off);
        c1 += __shfl_down_sync(0xFFFFFFFFu, c1, off);
    }
    if (lane == 0) {
        out[row * 2 + 0] = c0 + sfb[0];
        out[row * 2 + 1] = c1 + sfb[1];
    }
}

// ---------------- launch ----------------
extern "C" void kernel_launch(void* const* d_in, const int* in_sizes, int n_in,
                              void* d_out, int out_size) {
    const float* inp    = (const float*)d_in[0];
    const float* hidden = (const float*)d_in[1];
    const float* Wih0   = (const float*)d_in[2];
    const float* bih0   = (const float*)d_in[3];
    const float* Whh0   = (const float*)d_in[4];
    const float* bhh0   = (const float*)d_in[5];
    const float* bias0  = (const float*)d_in[6];
    const float* Wih1   = (const float*)d_in[7];
    const float* bih1   = (const float*)d_in[8];
    const float* Whh1   = (const float*)d_in[9];
    const float* bhh1   = (const float*)d_in[10];
    const float* bias1  = (const float*)d_in[11];
    const float* fcw    = (const float*)d_in[12];
    const float* fcb    = (const float*)d_in[13];
    float* out = (float*)d_out;

    static bool attr_done = false;
    if (!attr_done) {
        cudaFuncSetAttribute(k_prologue, cudaFuncAttributeMaxDynamicSharedMemorySize, PRO_SMEM);
        cudaFuncSetAttribute(k_rnn,      cudaFuncAttributeMaxDynamicSharedMemorySize, RNN_SMEM);
        attr_done = true;
    }

    k_prologue<<<32776, 256, PRO_SMEM>>>(inp, Wih0, bih0, bhh0, bias0, hidden);
    k_rnn<<<96, 256, RNN_SMEM>>>(Whh0, Wih1, Whh1, bih1, bhh1, bias1);
    k_epilogue<<<33280, 256>>>(fcw, fcb, out, out_size);
}

// round 8
// speedup vs baseline: 3.2851x; 1.0711x over previous
#include <cuda_runtime.h>
#include <cuda_bf16.h>
#include <cstddef>

#define TT    1024
#define BB    256
#define INDIM 128
#define HH    256

typedef unsigned long long ull;
typedef unsigned int uint;

// ---------------- scratch (device globals) ----------------
__device__ float g_X0[(size_t)TT * BB * HH];      // input proj + biases (fp32, exact)
__device__ float g_h1all[(size_t)TT * BB * HH];   // all layer-1 hidden states (fp32)
__device__ float g_h0ring[4][BB * HH];            // fp32 rings (final output only)
__device__ float g_h1ring[4][BB * HH];
// MMA A-fragment rings: [slot][ver(hi/lo)][ (ks*16 + b/16)*128 + lane*4 + reg ]
__device__ uint g_h0Afrag[4][2][16 * 16 * 128];
__device__ uint g_h1Afrag[4][2][16 * 16 * 128];
__device__ __align__(128) unsigned g_cnt0;
__device__ __align__(128) unsigned g_cnt1;
__device__ __align__(128) int g_seq0;
__device__ __align__(128) int g_seq1;

// ---------------- acq/rel primitives ----------------
__device__ __forceinline__ unsigned arrive_acqrel(unsigned* p) {
    unsigned r;
    asm volatile("atom.acq_rel.gpu.global.add.u32 %0, [%1], 1;" : "=r"(r) : "l"(p) : "memory");
    return r;
}
__device__ __forceinline__ int ld_acq(const int* p) {
    int r;
    asm volatile("ld.acquire.gpu.global.s32 %0, [%1];" : "=r"(r) : "l"(p) : "memory");
    return r;
}
__device__ __forceinline__ void st_rel(int* p, int v) {
    asm volatile("st.release.gpu.global.s32 [%0], %1;" :: "l"(p), "r"(v) : "memory");
}

// ---------------- f32x2 helpers (prologue only) ----------------
__device__ __forceinline__ void unpack2(ull v, float& lo, float& hi) {
    asm("mov.b64 {%0, %1}, %2;" : "=f"(lo), "=f"(hi) : "l"(v));
}
__device__ __forceinline__ void fma2(ull& d, ull a, ull b) {
    asm("fma.rn.f32x2 %0, %1, %2, %0;" : "+l"(d) : "l"(a), "l"(b));
}
__device__ __forceinline__ void add2(ull& d, ull a) {
    asm("add.rn.f32x2 %0, %0, %1;" : "+l"(d) : "l"(a));
}
__device__ __forceinline__ float pairsum(ull v) {
    float lo, hi; unpack2(v, lo, hi); return lo + hi;
}
__device__ __forceinline__ float tanh_fast(float x) {
    float xc = fminf(fmaxf(x, -15.0f), 15.0f);
    float e  = __expf(2.0f * xc);
    return __fdividef(e - 1.0f, e + 1.0f);
}

// split (a,b) into bf16x2 hi word + bf16x2 lo word (low halfword = first elem)
__device__ __forceinline__ void split2(float a, float b, uint& hi, uint& lo) {
    __nv_bfloat162 h = __floats2bfloat162_rn(a, b);
    float ha = __bfloat162float(h.x), hb = __bfloat162float(h.y);
    __nv_bfloat162 l = __floats2bfloat162_rn(a - ha, b - hb);
    hi = *(uint*)&h; lo = *(uint*)&l;
}

#define MMA16816(d, a, b) \
    asm volatile("mma.sync.aligned.m16n8k16.row.col.f32.bf16.bf16.f32 " \
        "{%0,%1,%2,%3}, {%4,%5,%6,%7}, {%8,%9}, {%0,%1,%2,%3};" \
        : "+f"(d[0]), "+f"(d[1]), "+f"(d[2]), "+f"(d[3]) \
        : "r"((a).x), "r"((a).y), "r"((a).z), "r"((a).w), "r"((b).x), "r"((b).y))

// =====================================================================
// Prologue (unchanged R7 SIMT GEMM): X0 = input @ Wih0^T + biases.
// Copy CTAs additionally seed fp32 + frag rings with the initial hidden.
// =====================================================================
#define PRO_SMEM 100608
__global__ void __launch_bounds__(256) k_prologue(
    const float* __restrict__ inp, const float* __restrict__ Wih0,
    const float* __restrict__ bih0, const float* __restrict__ bhh0,
    const float* __restrict__ bias0, const float* __restrict__ hidden)
{
    int bx = blockIdx.x, tid = threadIdx.x;
    if (bx >= 32768) {
        if (bx == 32768 && tid == 0) {
            g_cnt0 = 0; g_cnt1 = 0; g_seq0 = 0; g_seq1 = 0;
        }
        // 8 copy CTAs: 65536 float2 pairs total
        int pbase = (bx - 32768) * 8192;
        for (int s = 0; s < 32; ++s) {
            int pg = pbase + s * 256 + tid;      // pair index
            int v2 = pg * 2;                     // value index (even)
            int tensor = v2 >> 16;
            int rem = v2 & 65535;
            int b = rem >> 8, k = rem & 255;     // k even
            float2 hv = *(const float2*)&hidden[v2];
            if (tensor == 0) *(float2*)&g_h0ring[3][rem] = hv;
            else             *(float2*)&g_h1ring[3][rem] = hv;
            uint hi, lo; split2(hv.x, hv.y, hi, lo);
            int ksb = k >> 4, mb = b >> 4;
            int lanep = ((b & 7) << 2) | ((k >> 1) & 3);
            int reg = ((b & 15) >> 3) | (((k & 15) >> 3) << 1);
            int idx = (ksb * 16 + mb) * 128 + lanep * 4 + reg;
            if (tensor == 0) { g_h0Afrag[3][0][idx] = hi; g_h0Afrag[3][1][idx] = lo; }
            else             { g_h1Afrag[3][0][idx] = hi; g_h1Afrag[3][1][idx] = lo; }
        }
        return;
    }
    extern __shared__ char smch[];
    float* sw  = (float*)smch;              // W: 16 groups * 544 words
    float* sa  = (float*)(smch + 34816);    // A: 4 groups * 1056 words
    ull*   RED = (ull*)(smch + 34816);      // alias
    float* sb  = (float*)(smch + 100352);   // [64]

    const int rt = bx >> 2, ji = bx & 3;
    const int row0 = rt * 32, jg0 = ji * 64;
    const int lane = tid & 31, wi = tid >> 5;
    const int bg = lane >> 3, jg = lane & 7;
    const int ks = wi >> 1, jh = wi & 1;

    for (int i = tid; i < 2048; i += 256) {
        int j = i >> 5, k4 = (i & 31) << 2;
        *(float4*)&sw[(j >> 2) * 544 + (j & 3) * 128 + (((j >> 2) & 7) << 2) + k4] =
            *(const float4*)&Wih0[(size_t)(jg0 + j) * INDIM + k4];
    }
    for (int i = tid; i < 1024; i += 256) {
        int r = i >> 5, c4 = (i & 31) << 2;
        *(float4*)&sa[(r >> 3) * 1056 + (r & 7) * 128 + (((r >> 3) & 3) << 2) + c4] =
            *(const float4*)&inp[(size_t)(row0 + r) * INDIM + c4];
    }
    if (tid < 64) sb[tid] = bih0[jg0 + tid] + bhh0[jg0 + tid] + bias0[jg0 + tid];
    __syncthreads();

    ull acc[32];
    #pragma unroll
    for (int m = 0; m < 32; ++m) acc[m] = 0ull;

    const int k0 = ks << 5;
    const char* pA = (const char*)sa + ((size_t)bg * 1060 + k0) * 4;
    const char* pW = (const char*)sw + ((size_t)(jh * 8 + jg) * 544 + jg * 4 + k0) * 4;
    #pragma unroll
    for (int kb = 0; kb < 8; ++kb) {
        ulonglong2 a[8], w[4];
        #pragma unroll
        for (int b = 0; b < 8; ++b) a[b] = *(const ulonglong2*)(pA + b * 512);
        #pragma unroll
        for (int j = 0; j < 4; ++j) w[j] = *(const ulonglong2*)(pW + j * 512);
        #pragma unroll
        for (int b = 0; b < 8; ++b)
            #pragma unroll
            for (int j = 0; j < 4; ++j) {
                fma2(acc[b * 4 + j], a[b].x, w[j].x);
                fma2(acc[b * 4 + j], a[b].y, w[j].y);
            }
        pA += 16; pW += 16;
    }
    __syncthreads();

    #pragma unroll
    for (int i = 0; i < 16; ++i)
        *(ulonglong2*)&RED[(size_t)((i << 3) + wi) * 64 + (lane << 1)] =
            make_ulonglong2(acc[2 * i], acc[2 * i + 1]);
    __syncthreads();

    #pragma unroll
    for (int q = 0; q < 4; ++q) {
        int mp = (q << 2) + ks;
        ulonglong2 s = *(const ulonglong2*)&RED[(size_t)((mp << 3) + jh) * 64 + (lane << 1)];
        #pragma unroll
        for (int k2 = 1; k2 < 4; ++k2) {
            ulonglong2 r = *(const ulonglong2*)&RED[(size_t)((mp << 3) + (k2 << 1) + jh) * 64 + (lane << 1)];
            add2(s.x, r.x); add2(s.y, r.y);
        }
        int b_g = row0 + (bg << 3) + (mp >> 1);
        int j_l = (jh << 5) + (jg << 2) + ((mp & 1) << 1);
        float2 bb = *(const float2*)&sb[j_l];
        float2 o = make_float2(pairsum(s.x) + bb.x, pairsum(s.y) + bb.y);
        *(float2*)&g_X0[(size_t)b_g * HH + jg0 + j_l] = o;
    }
}

// =====================================================================
// Persistent recurrence, tensor-core (HMMA bf16 x2-split) version.
// group0 (CTAs 0..31): layer0, tile 32b x 64j, K=256; warps = 2 nh x 4 kq.
// group1 (CTAs 32..95): layer1, tile 16b x 64j, K=512; warps = 2 nh x 4 kq.
// =====================================================================
#define RNN_SMEM 164096
__global__ void __launch_bounds__(256, 1) k_rnn(
    const float* __restrict__ Whh0, const float* __restrict__ Wih1,
    const float* __restrict__ Whh1, const float* __restrict__ bih1,
    const float* __restrict__ bhh1, const float* __restrict__ bias1)
{
    extern __shared__ char smch[];
    const int bx = blockIdx.x, tid = threadIdx.x;
    const int lane = tid & 31, wi = tid >> 5;
    const int gID = lane >> 2, tig = lane & 3;
    const int nh = wi >> 2, kq = wi & 3;

    if (bx < 32) {
        // ================= layer 0 =================
        const int b0 = (bx >> 2) * 32, jg0 = (bx & 3) * 64;
        uint*  sw  = (uint*)smch;               // W frags: [2][16][8][32][2] = 16384 uint
        uint*  sa  = (uint*)(smch + 65536);     // A frags: [2][16][2][128] = 8192 uint
        float* RED = (float*)(smch + 65536);    // alias: [16][4][32][4] floats

        // W fragment staging (once)
        for (int i = tid; i < 4096; i += 256) {
            int j = i >> 6, k4 = (i & 63) << 2;
            float4 w = *(const float4*)&Whh0[(size_t)(jg0 + j) * HH + k4];
            uint h01, l01, h23, l23;
            split2(w.x, w.y, h01, l01);
            split2(w.z, w.w, h23, l23);
            int lane0 = ((j & 7) << 2) | ((k4 >> 1) & 3);
            int reg = (k4 >> 3) & 1, ksb = k4 >> 4, ng = j >> 3;
            int base0 = ((0 * 16 + ksb) * 8 + ng) * 32;
            int base1 = ((1 * 16 + ksb) * 8 + ng) * 32;
            sw[(base0 + lane0) * 2 + reg]     = h01;
            sw[(base0 + lane0 + 1) * 2 + reg] = h23;
            sw[(base1 + lane0) * 2 + reg]     = l01;
            sw[(base1 + lane0 + 1) * 2 + reg] = l23;
        }

        for (int t = 0; t < TT; ++t) {
            if (tid == 0) { while (ld_acq(&g_seq1) < t - 3) { } }
            __syncthreads();

            // stage A = h0(t-1) frags (verbatim coalesced copy)
            {
                const uint* srcH = g_h0Afrag[(t + 3) & 3][0];
                const uint* srcL = g_h0Afrag[(t + 3) & 3][1];
                for (int i = tid; i < 1024; i += 256) {
                    int ksb = i >> 6, mgl = (i >> 5) & 1, w4 = (i & 31) * 4;
                    int sidx = (ksb * 16 + (b0 >> 4) + mgl) * 128 + w4;
                    int didx = (ksb * 2 + mgl) * 128 + w4;
                    *(uint4*)&sa[didx]        = __ldcg((const uint4*)&srcH[sidx]);
                    *(uint4*)&sa[didx + 4096] = __ldcg((const uint4*)&srcL[sidx]);
                }
            }
            __syncthreads();

            float acc[2][4][4];
            #pragma unroll
            for (int mg = 0; mg < 2; ++mg)
                #pragma unroll
                for (int ng = 0; ng < 4; ++ng)
                    #pragma unroll
                    for (int q = 0; q < 4; ++q) acc[mg][ng][q] = 0.0f;

            #pragma unroll
            for (int s4 = 0; s4 < 4; ++s4) {
                int ksb = kq * 4 + s4;
                uint4 aH[2], aL[2];
                #pragma unroll
                for (int mg = 0; mg < 2; ++mg) {
                    aH[mg] = *(uint4*)&sa[(ksb * 2 + mg) * 128 + lane * 4];
                    aL[mg] = *(uint4*)&sa[(ksb * 2 + mg) * 128 + lane * 4 + 4096];
                }
                uint2 bH[4], bL[4];
                #pragma unroll
                for (int ng = 0; ng < 4; ++ng) {
                    int ngg = nh * 4 + ng;
                    bH[ng] = *(uint2*)&sw[((0 * 16 + ksb) * 8 + ngg) * 64 + lane * 2];
                    bL[ng] = *(uint2*)&sw[((1 * 16 + ksb) * 8 + ngg) * 64 + lane * 2];
                }
                #pragma unroll
                for (int mg = 0; mg < 2; ++mg)
                    #pragma unroll
                    for (int ng = 0; ng < 4; ++ng) {
                        MMA16816(acc[mg][ng], aH[mg], bH[ng]);
                        MMA16816(acc[mg][ng], aL[mg], bH[ng]);
                        MMA16816(acc[mg][ng], aH[mg], bL[ng]);
                        MMA16816(acc[mg][ng], aL[mg], bL[ng]);
                    }
            }
            __syncthreads();   // A reads done before RED alias writes

            #pragma unroll
            for (int mg = 0; mg < 2; ++mg)
                #pragma unroll
                for (int ng = 0; ng < 4; ++ng) {
                    int gt = nh * 8 + mg * 4 + ng;
                    *(float4*)&RED[((gt * 4 + kq) * 32 + lane) * 4] =
                        make_float4(acc[mg][ng][0], acc[mg][ng][1], acc[mg][ng][2], acc[mg][ng][3]);
                }
            __syncthreads();

            // reduce + epilogue: 2 tiles per warp
            float* rh = g_h0ring[t & 3];
            uint* fH = g_h0Afrag[t & 3][0];
            uint* fL = g_h0Afrag[t & 3][1];
            #pragma unroll
            for (int gi = 0; gi < 2; ++gi) {
                int gt = wi * 2 + gi;
                int nhg = gt >> 3, mgg = (gt >> 2) & 1, ngg = gt & 3;
                float4 s = *(float4*)&RED[((gt * 4 + 0) * 32 + lane) * 4];
                #pragma unroll
                for (int k2 = 1; k2 < 4; ++k2) {
                    float4 r = *(float4*)&RED[((gt * 4 + k2) * 32 + lane) * 4];
                    s.x += r.x; s.y += r.y; s.z += r.z; s.w += r.w;
                }
                int b_r = b0 + mgg * 16 + gID;
                int j_c = jg0 + nhg * 32 + ngg * 8 + 2 * tig;
                float2 xa = __ldcs((const float2*)&g_X0[((size_t)t * BB + b_r) * HH + j_c]);
                float2 xb = __ldcs((const float2*)&g_X0[((size_t)t * BB + b_r + 8) * HH + j_c]);
                float v00 = tanh_fast(s.x + xa.x), v01 = tanh_fast(s.y + xa.y);
                float v10 = tanh_fast(s.z + xb.x), v11 = tanh_fast(s.w + xb.y);
                *(float2*)&rh[b_r * HH + j_c]       = make_float2(v00, v01);
                *(float2*)&rh[(b_r + 8) * HH + j_c] = make_float2(v10, v11);
                uint hi0, lo0, hi1, lo1;
                split2(v00, v01, hi0, lo0);
                split2(v10, v11, hi1, lo1);
                int idx = (((j_c >> 4) * 16 + (b_r >> 4)) * 32 + lane) * 4 + (((j_c >> 3) & 1) << 1);
                fH[idx] = hi0; fH[idx + 1] = hi1;
                fL[idx] = lo0; fL[idx + 1] = lo1;
            }

            __syncthreads();
            if (tid == 0) {
                unsigned r = arrive_acqrel(&g_cnt0);
                if (r == 32u * (unsigned)(t + 1) - 1u) st_rel(&g_seq0, t + 1);
                while (ld_acq(&g_seq0) < t + 1) { }
            }
            __syncthreads();
        }
    } else {
        // ================= layer 1 =================
        const int bxx = bx - 32;
        const int b0 = (bxx >> 2) * 16, jg0 = (bxx & 3) * 64;
        uint*  sw  = (uint*)smch;               // W frags: [2][32][8][32][2] = 32768 uint
        uint*  sa  = (uint*)(smch + 131072);    // A frags: [2][32][128] = 8192 uint
        float* RED = (float*)(smch + 131072);   // alias: [8][4][32][4] floats
        float* sb  = (float*)(smch + 163840);   // [64]

        // W fragment staging: ks 0..15 = Wih1, 16..31 = Whh1
        for (int i = tid; i < 8192; i += 256) {
            int j = i >> 7, k4 = (i & 127) << 2;
            float4 w = (k4 < 256)
                ? *(const float4*)&Wih1[(size_t)(jg0 + j) * HH + k4]
                : *(const float4*)&Whh1[(size_t)(jg0 + j) * HH + (k4 - 256)];
            uint h01, l01, h23, l23;
            split2(w.x, w.y, h01, l01);
            split2(w.z, w.w, h23, l23);
            int lane0 = ((j & 7) << 2) | ((k4 >> 1) & 3);
            int reg = (k4 >> 3) & 1, ksb = k4 >> 4, ng = j >> 3;   // ksb 0..31
            int base0 = ((0 * 32 + ksb) * 8 + ng) * 32;
            int base1 = ((1 * 32 + ksb) * 8 + ng) * 32;
            sw[(base0 + lane0) * 2 + reg]     = h01;
            sw[(base0 + lane0 + 1) * 2 + reg] = h23;
            sw[(base1 + lane0) * 2 + reg]     = l01;
            sw[(base1 + lane0 + 1) * 2 + reg] = l23;
        }
        if (tid < 64) sb[tid] = bih1[jg0 + tid] + bhh1[jg0 + tid] + bias1[jg0 + tid];

        for (int t = 0; t < TT; ++t) {
            if (tid == 0) { while (ld_acq(&g_seq0) < t + 1) { } }
            __syncthreads();

            // stage A: ks 0..15 = h0(t), ks 16..31 = h1(t-1)
            {
                const uint* s0H = g_h0Afrag[t & 3][0];
                const uint* s0L = g_h0Afrag[t & 3][1];
                const uint* s1H = g_h1Afrag[(t + 3) & 3][0];
                const uint* s1L = g_h1Afrag[(t + 3) & 3][1];
                int mb = b0 >> 4;
                for (int i = tid; i < 1024; i += 256) {
                    int ksb = i >> 5, w4 = (i & 31) * 4;
                    int didx = ksb * 128 + w4;
                    const uint *pH, *pL;
                    int sidx;
                    if (ksb < 16) { pH = s0H; pL = s0L; sidx = (ksb * 16 + mb) * 128 + w4; }
                    else          { pH = s1H; pL = s1L; sidx = ((ksb - 16) * 16 + mb) * 128 + w4; }
                    *(uint4*)&sa[didx]        = __ldcg((const uint4*)&pH[sidx]);
                    *(uint4*)&sa[didx + 4096] = __ldcg((const uint4*)&pL[sidx]);
                }
            }
            __syncthreads();

            float acc[4][4];
            #pragma unroll
            for (int ng = 0; ng < 4; ++ng)
                #pragma unroll
                for (int q = 0; q < 4; ++q) acc[ng][q] = 0.0f;

            #pragma unroll
            for (int s8 = 0; s8 < 8; ++s8) {
                int ksb = kq * 8 + s8;
                uint4 aH = *(uint4*)&sa[ksb * 128 + lane * 4];
                uint4 aL = *(uint4*)&sa[ksb * 128 + lane * 4 + 4096];
                uint2 bH[4], bL[4];
                #pragma unroll
                for (int ng = 0; ng < 4; ++ng) {
                    int ngg = nh * 4 + ng;
                    bH[ng] = *(uint2*)&sw[((0 * 32 + ksb) * 8 + ngg) * 64 + lane * 2];
                    bL[ng] = *(uint2*)&sw[((1 * 32 + ksb) * 8 + ngg) * 64 + lane * 2];
                }
                #pragma unroll
                for (int ng = 0; ng < 4; ++ng) {
                    MMA16816(acc[ng], aH, bH[ng]);
                    MMA16816(acc[ng], aL, bH[ng]);
                    MMA16816(acc[ng], aH, bL[ng]);
                    MMA16816(acc[ng], aL, bL[ng]);
                }
            }
            __syncthreads();

            #pragma unroll
            for (int ng = 0; ng < 4; ++ng) {
                int gt = nh * 4 + ng;
                *(float4*)&RED[((gt * 4 + kq) * 32 + lane) * 4] =
                    make_float4(acc[ng][0], acc[ng][1], acc[ng][2], acc[ng][3]);
            }
            __syncthreads();

            // reduce + epilogue: 1 tile per warp
            {
                int gt = wi;
                int nhg = gt >> 2, ngg = gt & 3;
                float4 s = *(float4*)&RED[((gt * 4 + 0) * 32 + lane) * 4];
                #pragma unroll
                for (int k2 = 1; k2 < 4; ++k2) {
                    float4 r = *(float4*)&RED[((gt * 4 + k2) * 32 + lane) * 4];
                    s.x += r.x; s.y += r.y; s.z += r.z; s.w += r.w;
                }
                int b_r = b0 + gID;
                int j_c = jg0 + nhg * 32 + ngg * 8 + 2 * tig;
                float2 bb = *(const float2*)&sb[nhg * 32 + ngg * 8 + 2 * tig];
                float v00 = tanh_fast(s.x + bb.x), v01 = tanh_fast(s.y + bb.y);
                float v10 = tanh_fast(s.z + bb.x), v11 = tanh_fast(s.w + bb.y);
                float* rh = g_h1ring[t & 3];
                *(float2*)&rh[b_r * HH + j_c]       = make_float2(v00, v01);
                *(float2*)&rh[(b_r + 8) * HH + j_c] = make_float2(v10, v11);
                __stcs((float2*)&g_h1all[((size_t)t * BB + b_r) * HH + j_c], make_float2(v00, v01));
                __stcs((float2*)&g_h1all[((size_t)t * BB + b_r + 8) * HH + j_c], make_float2(v10, v11));
                uint hi0, lo0, hi1, lo1;
                split2(v00, v01, hi0, lo0);
                split2(v10, v11, hi1, lo1);
                int idx = (((j_c >> 4) * 16 + (b_r >> 4)) * 32 + lane) * 4 + (((j_c >> 3) & 1) << 1);
                g_h1Afrag[t & 3][0][idx] = hi0; g_h1Afrag[t & 3][0][idx + 1] = hi1;
                g_h1Afrag[t & 3][1][idx] = lo0; g_h1Afrag[t & 3][1][idx + 1] = lo1;
            }

            __syncthreads();
            if (tid == 0) {
                unsigned r = arrive_acqrel(&g_cnt1);
                if (r == 64u * (unsigned)(t + 1) - 1u) st_rel(&g_seq1, t + 1);
                while (ld_acq(&g_seq1) < t + 1) { }
            }
            __syncthreads();
        }
    }
}

// =====================================================================
// Epilogue: logits = h1all @ fc_w^T + fc_b; copy last hidden.
// =====================================================================
__global__ void __launch_bounds__(256) k_epilogue(
    const float* __restrict__ fcw, const float* __restrict__ fcb,
    float* __restrict__ out, int out_size)
{
    int bx = blockIdx.x, tid = threadIdx.x;
    if (bx >= 32768) {
        int i = (bx - 32768) * 256 + tid;
        int base = TT * BB * 2;
        if (base + i < out_size) {
            float v = (i < BB * HH) ? g_h0ring[3][i] : g_h1ring[3][i - BB * HH];
            out[base + i] = v;
        }
        return;
    }
    __shared__ float sfw[2 * HH];
    __shared__ float sfb[2];
    for (int i = tid; i < 2 * HH; i += 256) sfw[i] = fcw[i];
    if (tid < 2) sfb[tid] = fcb[tid];
    __syncthreads();

    int w = tid >> 5, lane = tid & 31;
    size_t row = (size_t)bx * 8 + w;
    const float* hp = &g_h1all[row * HH + lane * 8];
    float4 h0v = *(const float4*)hp;
    float4 h1v = *(const float4*)(hp + 4);
    const float* w0 = &sfw[lane * 8];
    const float* w1 = &sfw[HH + lane * 8];
    float c0 = 0.f, c1 = 0.f;
    #pragma unroll
    for (int q = 0; q < 4; ++q) {
        c0 += (&h0v.x)[q] * w0[q] + (&h1v.x)[q] * w0[q + 4];
        c1 += (&h0v.x)[q] * w1[q] + (&h1v.x)[q] * w1[q + 4];
    }
    #pragma unroll
    for (int off = 16; off > 0; off >>= 1) {
        c0 += __shfl_down_sync(0xFFFFFFFFu, c0, off);
        c1 += __shfl_down_sync(0xFFFFFFFFu, c1, off);
    }
    if (lane == 0) {
        out[row * 2 + 0] = c0 + sfb[0];
        out[row * 2 + 1] = c1 + sfb[1];
    }
}

// ---------------- launch ----------------
extern "C" void kernel_launch(void* const* d_in, const int* in_sizes, int n_in,
                              void* d_out, int out_size) {
    const float* inp    = (const float*)d_in[0];
    const float* hidden = (const float*)d_in[1];
    const float* Wih0   = (const float*)d_in[2];
    const float* bih0   = (const float*)d_in[3];
    const float* Whh0   = (const float*)d_in[4];
    const float* bhh0   = (const float*)d_in[5];
    const float* bias0  = (const float*)d_in[6];
    const float* Wih1   = (const float*)d_in[7];
    const float* bih1   = (const float*)d_in[8];
    const float* Whh1   = (const float*)d_in[9];
    const float* bhh1   = (const float*)d_in[10];
    const float* bias1  = (const float*)d_in[11];
    const float* fcw    = (const float*)d_in[12];
    const float* fcb    = (const float*)d_in[13];
    float* out = (float*)d_out;

    static bool attr_done = false;
    if (!attr_done) {
        cudaFuncSetAttribute(k_prologue, cudaFuncAttributeMaxDynamicSharedMemorySize, PRO_SMEM);
        cudaFuncSetAttribute(k_rnn,      cudaFuncAttributeMaxDynamicSharedMemorySize, RNN_SMEM);
        attr_done = true;
    }

    k_prologue<<<32776, 256, PRO_SMEM>>>(inp, Wih0, bih0, bhh0, bias0, hidden);
    k_rnn<<<96, 256, RNN_SMEM>>>(Whh0, Wih1, Whh1, bih1, bhh1, bias1);
    k_epilogue<<<33280, 256>>>(fcw, fcb, out, out_size);
}

// round 12
// speedup vs baseline: 4.7530x; 1.4469x over previous
#include <cuda_runtime.h>
#include <cuda_bf16.h>
#include <cstddef>

#define TT    1024
#define BB    256
#define INDIM 128
#define HH    256
#define NG    16     // batch groups of 16 rows; 6 CTAs each

typedef unsigned long long ull;
typedef unsigned int uint;

// ---------------- scratch (device globals) ----------------
__device__ float g_X0[(size_t)TT * BB * HH];      // input proj + biases (fp32 exact)
__device__ float g_h1all[(size_t)TT * BB * HH];   // all layer-1 hidden (fp32, for logits)
__device__ float g_h0last[BB * HH];               // h0(T-1) fp32
__device__ float g_h1last[BB * HH];               // h1(T-1) fp32
// A-fragment rings, group-local: [slot][group][ver*2048 + ksb*128 + lane*4 + reg]
__device__ uint g_h0F[4][NG][4096];
__device__ uint g_h1F[4][NG][4096];
__device__ __align__(128) unsigned g_cnt0[NG * 32];   // layer0 pair arrivals (stride 128B)
__device__ __align__(128) unsigned g_cnt1[NG * 32];   // layer1 quad arrivals
__device__ __align__(128) int g_seq0[NG * 32];
__device__ __align__(128) int g_seq1[NG * 32];

// ---------------- acq/rel primitives ----------------
__device__ __forceinline__ unsigned arrive_acqrel(unsigned* p) {
    unsigned r;
    asm volatile("atom.acq_rel.gpu.global.add.u32 %0, [%1], 1;" : "=r"(r) : "l"(p) : "memory");
    return r;
}
__device__ __forceinline__ int ld_acq(const int* p) {
    int r;
    asm volatile("ld.acquire.gpu.global.s32 %0, [%1];" : "=r"(r) : "l"(p) : "memory");
    return r;
}
__device__ __forceinline__ void st_rel(int* p, int v) {
    asm volatile("st.release.gpu.global.s32 [%0], %1;" :: "l"(p), "r"(v) : "memory");
}

// ---------------- f32x2 helpers (prologue GEMM) ----------------
__device__ __forceinline__ void unpack2(ull v, float& lo, float& hi) {
    asm("mov.b64 {%0, %1}, %2;" : "=f"(lo), "=f"(hi) : "l"(v));
}
__device__ __forceinline__ void fma2(ull& d, ull a, ull b) {
    asm("fma.rn.f32x2 %0, %1, %2, %0;" : "+l"(d) : "l"(a), "l"(b));
}
__device__ __forceinline__ void add2(ull& d, ull a) {
    asm("add.rn.f32x2 %0, %0, %1;" : "+l"(d) : "l"(a));
}
__device__ __forceinline__ float pairsum(ull v) {
    float lo, hi; unpack2(v, lo, hi); return lo + hi;
}
__device__ __forceinline__ float tanh_fast(float x) {
    float xc = fminf(fmaxf(x, -15.0f), 15.0f);
    float e  = __expf(2.0f * xc);
    return __fdividef(e - 1.0f, e + 1.0f);
}
// split (a,b) -> bf16x2 hi word + bf16x2 lo word (low halfword = first elem)
__device__ __forceinline__ void split2(float a, float b, uint& hi, uint& lo) {
    __nv_bfloat162 h = __floats2bfloat162_rn(a, b);
    float ha = __bfloat162float(h.x), hb = __bfloat162float(h.y);
    __nv_bfloat162 l = __floats2bfloat162_rn(a - ha, b - hb);
    hi = *(uint*)&h; lo = *(uint*)&l;
}

#define MMA16816(d, a, b) \
    asm volatile("mma.sync.aligned.m16n8k16.row.col.f32.bf16.bf16.f32 " \
        "{%0,%1,%2,%3}, {%4,%5,%6,%7}, {%8,%9}, {%0,%1,%2,%3};" \
        : "+f"(d[0]), "+f"(d[1]), "+f"(d[2]), "+f"(d[3]) \
        : "r"((a).x), "r"((a).y), "r"((a).z), "r"((a).w), "r"((b).x), "r"((b).y))

// =====================================================================
// Prologue (R7 SIMT GEMM, validated): X0 = input @ Wih0^T + biases.
// Copy CTAs seed the frag rings (slot 3 = t=-1) and reset sync state.
// =====================================================================
#define PRO_SMEM 100608
__global__ void __launch_bounds__(256) k_prologue(
    const float* __restrict__ inp, const float* __restrict__ Wih0,
    const float* __restrict__ bih0, const float* __restrict__ bhh0,
    const float* __restrict__ bias0, const float* __restrict__ hidden)
{
    int bx = blockIdx.x, tid = threadIdx.x;
    if (bx >= 32768) {
        if (bx == 32768 && tid < NG) {
            g_cnt0[tid * 32] = 0; g_cnt1[tid * 32] = 0;
            g_seq0[tid * 32] = 0; g_seq1[tid * 32] = 0;
        }
        int pbase = (bx - 32768) * 8192;
        for (int s = 0; s < 32; ++s) {
            int pg = pbase + s * 256 + tid;
            int v2 = pg * 2;
            int tensor = v2 >> 16;
            int rem = v2 & 65535;
            int b = rem >> 8, k = rem & 255;
            float2 hv = *(const float2*)&hidden[v2];
            uint hi, lo; split2(hv.x, hv.y, hi, lo);
            int lanep = ((b & 7) << 2) | ((k >> 1) & 3);
            int reg = ((b & 15) >> 3) | (((k & 15) >> 3) << 1);
            int grp = b >> 4;
            int idx = (k >> 4) * 128 + lanep * 4 + reg;
            if (tensor == 0) { g_h0F[3][grp][idx] = hi; g_h0F[3][grp][2048 + idx] = lo; }
            else             { g_h1F[3][grp][idx] = hi; g_h1F[3][grp][2048 + idx] = lo; }
        }
        return;
    }
    extern __shared__ char smch[];
    float* sw  = (float*)smch;
    float* sa  = (float*)(smch + 34816);
    ull*   RED = (ull*)(smch + 34816);
    float* sb  = (float*)(smch + 100352);

    const int rt = bx >> 2, ji = bx & 3;
    const int row0 = rt * 32, jg0 = ji * 64;
    const int lane = tid & 31, wi = tid >> 5;
    const int bg = lane >> 3, jg = lane & 7;
    const int ks = wi >> 1, jh = wi & 1;

    for (int i = tid; i < 2048; i += 256) {
        int j = i >> 5, k4 = (i & 31) << 2;
        *(float4*)&sw[(j >> 2) * 544 + (j & 3) * 128 + (((j >> 2) & 7) << 2) + k4] =
            *(const float4*)&Wih0[(size_t)(jg0 + j) * INDIM + k4];
    }
    for (int i = tid; i < 1024; i += 256) {
        int r = i >> 5, c4 = (i & 31) << 2;
        *(float4*)&sa[(r >> 3) * 1056 + (r & 7) * 128 + (((r >> 3) & 3) << 2) + c4] =
            *(const float4*)&inp[(size_t)(row0 + r) * INDIM + c4];
    }
    if (tid < 64) sb[tid] = bih0[jg0 + tid] + bhh0[jg0 + tid] + bias0[jg0 + tid];
    __syncthreads();

    ull acc[32];
    #pragma unroll
    for (int m = 0; m < 32; ++m) acc[m] = 0ull;

    const int k0 = ks << 5;
    const char* pA = (const char*)sa + ((size_t)bg * 1060 + k0) * 4;
    const char* pW = (const char*)sw + ((size_t)(jh * 8 + jg) * 544 + jg * 4 + k0) * 4;
    #pragma unroll
    for (int kb = 0; kb < 8; ++kb) {
        ulonglong2 a[8], w[4];
        #pragma unroll
        for (int b = 0; b < 8; ++b) a[b] = *(const ulonglong2*)(pA + b * 512);
        #pragma unroll
        for (int j = 0; j < 4; ++j) w[j] = *(const ulonglong2*)(pW + j * 512);
        #pragma unroll
        for (int b = 0; b < 8; ++b)
            #pragma unroll
            for (int j = 0; j < 4; ++j) {
                fma2(acc[b * 4 + j], a[b].x, w[j].x);
                fma2(acc[b * 4 + j], a[b].y, w[j].y);
            }
        pA += 16; pW += 16;
    }
    __syncthreads();

    #pragma unroll
    for (int i = 0; i < 16; ++i)
        *(ulonglong2*)&RED[(size_t)((i << 3) + wi) * 64 + (lane << 1)] =
            make_ulonglong2(acc[2 * i], acc[2 * i + 1]);
    __syncthreads();

    #pragma unroll
    for (int q = 0; q < 4; ++q) {
        int mp = (q << 2) + ks;
        ulonglong2 s = *(const ulonglong2*)&RED[(size_t)((mp << 3) + jh) * 64 + (lane << 1)];
        #pragma unroll
        for (int k2 = 1; k2 < 4; ++k2) {
            ulonglong2 r = *(const ulonglong2*)&RED[(size_t)((mp << 3) + (k2 << 1) + jh) * 64 + (lane << 1)];
            add2(s.x, r.x); add2(s.y, r.y);
        }
        int b_g = row0 + (bg << 3) + (mp >> 1);
        int j_l = (jh << 5) + (jg << 2) + ((mp & 1) << 1);
        float2 bb = *(const float2*)&sb[j_l];
        float2 o = make_float2(pairsum(s.x) + bb.x, pairsum(s.y) + bb.y);
        *(float2*)&g_X0[(size_t)b_g * HH + j_l + jg0] = o;
    }
}

// =====================================================================
// Persistent recurrence: 16 groups x 6 CTAs, group owns 16 batch rows.
// role 0,1: layer0 j-half (m16 n128 k256). role 2..5: layer1 j-quarter
// (m16 n64 k512). Group-local barriers; frag exchange via L2; 3-term
// bf16 split MMA (HH, LH, HL).
// =====================================================================
#define RNN_SMEM 163840
__global__ void __launch_bounds__(256, 1) k_rnn(
    const float* __restrict__ Whh0, const float* __restrict__ Wih1,
    const float* __restrict__ Whh1, const float* __restrict__ bih1,
    const float* __restrict__ bhh1, const float* __restrict__ bias1)
{
    extern __shared__ uint smu[];
    const int bx = blockIdx.x, tid = threadIdx.x;
    const int lane = tid & 31, wi = tid >> 5;
    const int gID = lane >> 2, tig = lane & 3;
    const int g = bx / 6, role = bx % 6, g32 = g * 32;
    const int b0 = g * 16;

    if (role < 2) {
        // ================= layer 0: m16 x n128 x k256 =================
        const int jg0 = role * 128;
        uint* sw = smu;             // [2 ver][16 ksb][16 ng][32 lane][2 reg] = 32768
        uint* sa = smu + 32768;     // [2 ver][16 ksb][128] = 4096

        // W staging: 128 rows x 256 cols = 8192 float4s
        for (int i = tid; i < 8192; i += 256) {
            int jl = i >> 6, k4 = (i & 63) << 2;
            float4 w = *(const float4*)&Whh0[(size_t)(jg0 + jl) * HH + k4];
            uint h01, l01, h23, l23;
            split2(w.x, w.y, h01, l01);
            split2(w.z, w.w, h23, l23);
            int lane0 = ((jl & 7) << 2) | ((k4 >> 1) & 3);
            int reg = (k4 >> 3) & 1, ksb = k4 >> 4, ng = jl >> 3;
            sw[(((0 * 16 + ksb) * 16 + ng) * 32 + lane0) * 2 + reg]     = h01;
            sw[(((0 * 16 + ksb) * 16 + ng) * 32 + lane0 + 1) * 2 + reg] = h23;
            sw[(((1 * 16 + ksb) * 16 + ng) * 32 + lane0) * 2 + reg]     = l01;
            sw[(((1 * 16 + ksb) * 16 + ng) * 32 + lane0 + 1) * 2 + reg] = l23;
        }

        for (int t = 0; t < TT; ++t) {
            if (tid == 0) {
                while (ld_acq(&g_seq0[g32]) < t) { }
                while (ld_acq(&g_seq1[g32]) < t - 3) { }
            }
            __syncthreads();

            // X0 prefetch (hidden behind staging + MMA)
            float2 px[2][2];
            const int jb = jg0 + wi * 16;
            #pragma unroll
            for (int ng2 = 0; ng2 < 2; ++ng2) {
                int j = jb + ng2 * 8 + 2 * tig;
                px[ng2][0] = __ldcs((const float2*)&g_X0[((size_t)t * BB + b0 + gID) * HH + j]);
                px[ng2][1] = __ldcs((const float2*)&g_X0[((size_t)t * BB + b0 + gID + 8) * HH + j]);
            }

            // stage A = h0(t-1) frags (linear 16KB copy)
            {
                const uint* src = g_h0F[(t + 3) & 3][g];
                #pragma unroll
                for (int it = 0; it < 4; ++it) {
                    int i = (tid + it * 256) * 4;
                    *(uint4*)&sa[i] = __ldcg((const uint4*)&src[i]);
                }
            }
            __syncthreads();

            float acc[2][2][4];
            #pragma unroll
            for (int kh = 0; kh < 2; ++kh)
                #pragma unroll
                for (int n2 = 0; n2 < 2; ++n2)
                    #pragma unroll
                    for (int q = 0; q < 4; ++q) acc[kh][n2][q] = 0.0f;

            #pragma unroll
            for (int kh = 0; kh < 2; ++kh)
                #pragma unroll
                for (int s = 0; s < 8; ++s) {
                    int ksb = kh * 8 + s;
                    uint4 aH = *(uint4*)&sa[ksb * 128 + lane * 4];
                    uint4 aL = *(uint4*)&sa[2048 + ksb * 128 + lane * 4];
                    #pragma unroll
                    for (int n2 = 0; n2 < 2; ++n2) {
                        int ngg = wi * 2 + n2;
                        uint2 bH = *(uint2*)&sw[(((0 * 16 + ksb) * 16 + ngg) * 32 + lane) * 2];
                        uint2 bL = *(uint2*)&sw[(((1 * 16 + ksb) * 16 + ngg) * 32 + lane) * 2];
                        MMA16816(acc[kh][n2], aH, bH);
                        MMA16816(acc[kh][n2], aL, bH);
                        MMA16816(acc[kh][n2], aH, bL);
                    }
                }

            // epilogue: tanh, split, frag write (uint4 per ver)
            {
                uint* fH = g_h0F[t & 3][g];
                int ksb_j = (jg0 >> 4) + wi;
                uint4 hv, lv;
                #pragma unroll
                for (int n2 = 0; n2 < 2; ++n2) {
                    float d0 = acc[0][n2][0] + acc[1][n2][0];
                    float d1 = acc[0][n2][1] + acc[1][n2][1];
                    float d2 = acc[0][n2][2] + acc[1][n2][2];
                    float d3 = acc[0][n2][3] + acc[1][n2][3];
                    float v00 = tanh_fast(d0 + px[n2][0].x);
                    float v01 = tanh_fast(d1 + px[n2][0].y);
                    float v10 = tanh_fast(d2 + px[n2][1].x);
                    float v11 = tanh_fast(d3 + px[n2][1].y);
                    uint h0v, l0v, h1v, l1v;
                    split2(v00, v01, h0v, l0v);
                    split2(v10, v11, h1v, l1v);
                    if (n2 == 0) { hv.x = h0v; hv.y = h1v; lv.x = l0v; lv.y = l1v; }
                    else         { hv.z = h0v; hv.w = h1v; lv.z = l0v; lv.w = l1v; }
                    if (t == TT - 1) {
                        int j = jb + n2 * 8 + 2 * tig;
                        *(float2*)&g_h0last[(b0 + gID) * HH + j]     = make_float2(v00, v01);
                        *(float2*)&g_h0last[(b0 + gID + 8) * HH + j] = make_float2(v10, v11);
                    }
                }
                *(uint4*)&fH[ksb_j * 128 + lane * 4]        = hv;
                *(uint4*)&fH[2048 + ksb_j * 128 + lane * 4] = lv;
            }

            __syncthreads();
            if (tid == 0) {
                unsigned r = arrive_acqrel(&g_cnt0[g32]);
                if (r == 2u * (unsigned)(t + 1) - 1u) st_rel(&g_seq0[g32], t + 1);
            }
        }
    } else {
        // ================= layer 1: m16 x n64 x k512 =================
        const int q64 = role - 2;
        const int jq0 = q64 * 64;
        uint* sw = smu;             // [2 ver][32 ksb][8 ng][32][2] = 32768
        uint* sa = smu + 32768;     // [2 ver][32 ksb][128] = 8192

        for (int i = tid; i < 8192; i += 256) {
            int jl = i >> 7, k4 = (i & 127) << 2;
            float4 w = (k4 < 256)
                ? *(const float4*)&Wih1[(size_t)(jq0 + jl) * HH + k4]
                : *(const float4*)&Whh1[(size_t)(jq0 + jl) * HH + (k4 - 256)];
            uint h01, l01, h23, l23;
            split2(w.x, w.y, h01, l01);
            split2(w.z, w.w, h23, l23);
            int lane0 = ((jl & 7) << 2) | ((k4 >> 1) & 3);
            int reg = (k4 >> 3) & 1, ksb = k4 >> 4, ng = jl >> 3;
            sw[(((0 * 32 + ksb) * 8 + ng) * 32 + lane0) * 2 + reg]     = h01;
            sw[(((0 * 32 + ksb) * 8 + ng) * 32 + lane0 + 1) * 2 + reg] = h23;
            sw[(((1 * 32 + ksb) * 8 + ng) * 32 + lane0) * 2 + reg]     = l01;
            sw[(((1 * 32 + ksb) * 8 + ng) * 32 + lane0 + 1) * 2 + reg] = l23;
        }

        // per-thread bias (cols fixed across steps)
        const int jb = jq0 + wi * 8 + 2 * tig;
        const float bbx = bih1[jb] + bhh1[jb] + bias1[jb];
        const float bby = bih1[jb + 1] + bhh1[jb + 1] + bias1[jb + 1];

        for (int t = 0; t < TT; ++t) {
            if (tid == 0) {
                while (ld_acq(&g_seq0[g32]) < t + 1) { }
                while (ld_acq(&g_seq1[g32]) < t) { }
            }
            __syncthreads();

            // stage A: ksb 0..15 = h0(t), 16..31 = h1(t-1)
            {
                const uint* s0 = g_h0F[t & 3][g];
                const uint* s1 = g_h1F[(t + 3) & 3][g];
                #pragma unroll
                for (int it = 0; it < 8; ++it) {
                    int u4 = (tid + it * 256) * 4;
                    int ver = u4 >> 12, rem = u4 & 4095;
                    const uint* src = (rem < 2048) ? &s0[ver * 2048 + rem]
                                                   : &s1[ver * 2048 + rem - 2048];
                    *(uint4*)&sa[u4] = __ldcg((const uint4*)src);
                }
            }
            __syncthreads();

            float acc[4][4];
            #pragma unroll
            for (int kh = 0; kh < 4; ++kh)
                #pragma unroll
                for (int q = 0; q < 4; ++q) acc[kh][q] = 0.0f;

            #pragma unroll
            for (int ksb = 0; ksb < 32; ++ksb) {
                uint4 aH = *(uint4*)&sa[ksb * 128 + lane * 4];
                uint4 aL = *(uint4*)&sa[4096 + ksb * 128 + lane * 4];
                uint2 bH = *(uint2*)&sw[(((0 * 32 + ksb) * 8 + wi) * 32 + lane) * 2];
                uint2 bL = *(uint2*)&sw[(((1 * 32 + ksb) * 8 + wi) * 32 + lane) * 2];
                int kh = ksb >> 3;
                MMA16816(acc[kh], aH, bH);
                MMA16816(acc[kh], aL, bH);
                MMA16816(acc[kh], aH, bL);
            }

            // epilogue
            {
                float d0 = acc[0][0] + acc[1][0] + acc[2][0] + acc[3][0];
                float d1 = acc[0][1] + acc[1][1] + acc[2][1] + acc[3][1];
                float d2 = acc[0][2] + acc[1][2] + acc[2][2] + acc[3][2];
                float d3 = acc[0][3] + acc[1][3] + acc[2][3] + acc[3][3];
                float v00 = tanh_fast(d0 + bbx);
                float v01 = tanh_fast(d1 + bby);
                float v10 = tanh_fast(d2 + bbx);
                float v11 = tanh_fast(d3 + bby);
                __stcs((float2*)&g_h1all[((size_t)t * BB + b0 + gID) * HH + jb], make_float2(v00, v01));
                __stcs((float2*)&g_h1all[((size_t)t * BB + b0 + gID + 8) * HH + jb], make_float2(v10, v11));
                if (t == TT - 1) {
                    *(float2*)&g_h1last[(b0 + gID) * HH + jb]     = make_float2(v00, v01);
                    *(float2*)&g_h1last[(b0 + gID + 8) * HH + jb] = make_float2(v10, v11);
                }
                uint h0v, l0v, h1v, l1v;
                split2(v00, v01, h0v, l0v);
                split2(v10, v11, h1v, l1v);
                uint* fH = g_h1F[t & 3][g];
                int ksb_j = q64 * 4 + (wi >> 1);
                int off = (wi & 1) << 1;
                *(uint2*)&fH[ksb_j * 128 + lane * 4 + off]        = make_uint2(h0v, h1v);
                *(uint2*)&fH[2048 + ksb_j * 128 + lane * 4 + off] = make_uint2(l0v, l1v);
            }

            __syncthreads();
            if (tid == 0) {
                unsigned r = arrive_acqrel(&g_cnt1[g32]);
                if (r == 4u * (unsigned)(t + 1) - 1u) st_rel(&g_seq1[g32], t + 1);
            }
        }
    }
}

// =====================================================================
// Epilogue: logits = h1all @ fc_w^T + fc_b; copy last hidden.
// =====================================================================
__global__ void __launch_bounds__(256) k_epilogue(
    const float* __restrict__ fcw, const float* __restrict__ fcb,
    float* __restrict__ out, int out_size)
{
    int bx = blockIdx.x, tid = threadIdx.x;
    if (bx >= 32768) {
        int i = (bx - 32768) * 256 + tid;
        int base = TT * BB * 2;
        if (base + i < out_size) {
            float v = (i < BB * HH) ? g_h0last[i] : g_h1last[i - BB * HH];
            out[base + i] = v;
        }
        return;
    }
    __shared__ float sfw[2 * HH];
    __shared__ float sfb[2];
    for (int i = tid; i < 2 * HH; i += 256) sfw[i] = fcw[i];
    if (tid < 2) sfb[tid] = fcb[tid];
    __syncthreads();

    int w = tid >> 5, lane = tid & 31;
    size_t row = (size_t)bx * 8 + w;
    const float* hp = &g_h1all[row * HH + lane * 8];
    float4 h0v = *(const float4*)hp;
    float4 h1v = *(const float4*)(hp + 4);
    const float* w0 = &sfw[lane * 8];
    const float* w1 = &sfw[HH + lane * 8];
    float c0 = 0.f, c1 = 0.f;
    #pragma unroll
    for (int q = 0; q < 4; ++q) {
        c0 += (&h0v.x)[q] * w0[q] + (&h1v.x)[q] * w0[q + 4];
        c1 += (&h0v.x)[q] * w1[q] + (&h1v.x)[q] * w1[q + 4];
    }
    #pragma unroll
    for (int off = 16; off > 0; off >>= 1) {
        c0 += __shfl_down_sync(0xFFFFFFFFu, c0, off);
        c1 += __shfl_down_sync(0xFFFFFFFFu, c1, off);
    }
    if (lane == 0) {
        out[row * 2 + 0] = c0 + sfb[0];
        out[row * 2 + 1] = c1 + sfb[1];
    }
}

// ---------------- launch ----------------
extern "C" void kernel_launch(void* const* d_in, const int* in_sizes, int n_in,
                              void* d_out, int out_size) {
    const float* inp    = (const float*)d_in[0];
    const float* hidden = (const float*)d_in[1];
    const float* Wih0   = (const float*)d_in[2];
    const float* bih0   = (const float*)d_in[3];
    const float* Whh0   = (const float*)d_in[4];
    const float* bhh0   = (const float*)d_in[5];
    const float* bias0  = (const float*)d_in[6];
    const float* Wih1   = (const float*)d_in[7];
    const float* bih1   = (const float*)d_in[8];
    const float* Whh1   = (const float*)d_in[9];
    const float* bhh1   = (const float*)d_in[10];
    const float* bias1  = (const float*)d_in[11];
    const float* fcw    = (const float*)d_in[12];
    const float* fcb    = (const float*)d_in[13];
    float* out = (float*)d_out;

    static bool attr_done = false;
    if (!attr_done) {
        cudaFuncSetAttribute(k_prologue, cudaFuncAttributeMaxDynamicSharedMemorySize, PRO_SMEM);
        cudaFuncSetAttribute(k_rnn,      cudaFuncAttributeMaxDynamicSharedMemorySize, RNN_SMEM);
        attr_done = true;
    }

    k_prologue<<<32776, 256, PRO_SMEM>>>(inp, Wih0, bih0, bhh0, bias0, hidden);
    k_rnn<<<96, 256, RNN_SMEM>>>(Whh0, Wih1, Whh1, bih1, bhh1, bias1);
    k_epilogue<<<33280, 256>>>(fcw, fcb, out, out_size);
}

// round 13
// speedup vs baseline: 5.5694x; 1.1717x over previous
#include <cuda_runtime.h>
#include <cuda_bf16.h>
#include <cstddef>

#define TT    1024
#define BB    256
#define INDIM 128
#define HH    256
#define NG    16     // batch groups of 16 rows; 6 CTAs each

typedef unsigned long long ull;
typedef unsigned int uint;

// ---------------- scratch (device globals) ----------------
__device__ float g_X0[(size_t)TT * BB * HH];      // input proj + biases
__device__ float g_h1all[(size_t)TT * BB * HH];   // all layer-1 hidden (fp32, for logits)
__device__ float g_h0last[BB * HH];               // h0(T-1) fp32
__device__ float g_h1last[BB * HH];               // h1(T-1) fp32
// A-fragment rings, group-local: [slot][group][ver*2048 + ksb*128 + lane*4 + reg]
__device__ uint g_h0F[4][NG][4096];
__device__ uint g_h1F[4][NG][4096];
__device__ __align__(128) unsigned g_cnt0[NG * 32];   // layer0 warp..CTA arrivals (128B stride per group)
__device__ __align__(128) unsigned g_cnt1[NG * 32];   // layer1 arrivals

// ---------------- acq/rel primitives ----------------
__device__ __forceinline__ unsigned arrive_acqrel(unsigned* p) {
    unsigned r;
    asm volatile("atom.acq_rel.gpu.global.add.u32 %0, [%1], 1;" : "=r"(r) : "l"(p) : "memory");
    return r;
}
__device__ __forceinline__ unsigned ld_acq_u(const unsigned* p) {
    unsigned r;
    asm volatile("ld.acquire.gpu.global.u32 %0, [%1];" : "=r"(r) : "l"(p) : "memory");
    return r;
}

__device__ __forceinline__ float tanh_fast(float x) {
    float xc = fminf(fmaxf(x, -15.0f), 15.0f);
    float e  = __expf(2.0f * xc);
    return __fdividef(e - 1.0f, e + 1.0f);
}
// split (a,b) -> bf16x2 hi word + bf16x2 lo word (low halfword = first elem)
__device__ __forceinline__ void split2(float a, float b, uint& hi, uint& lo) {
    __nv_bfloat162 h = __floats2bfloat162_rn(a, b);
    float ha = __bfloat162float(h.x), hb = __bfloat162float(h.y);
    __nv_bfloat162 l = __floats2bfloat162_rn(a - ha, b - hb);
    hi = *(uint*)&h; lo = *(uint*)&l;
}

#define MMA16816(d, a, b) \
    asm volatile("mma.sync.aligned.m16n8k16.row.col.f32.bf16.bf16.f32 " \
        "{%0,%1,%2,%3}, {%4,%5,%6,%7}, {%8,%9}, {%0,%1,%2,%3};" \
        : "+f"(d[0]), "+f"(d[1]), "+f"(d[2]), "+f"(d[3]) \
        : "r"((a).x), "r"((a).y), "r"((a).z), "r"((a).w), "r"((b).x), "r"((b).y))

// =====================================================================
// Seed kernel: frag-ring seeding (slot 3 = t=-1) + counter reset.
// =====================================================================
__global__ void __launch_bounds__(256) k_seed(const float* __restrict__ hidden) {
    int bx = blockIdx.x, tid = threadIdx.x;
    if (bx == 8) {
        if (tid < NG) { g_cnt0[tid * 32] = 0; g_cnt1[tid * 32] = 0; }
        return;
    }
    int pbase = bx * 8192;
    for (int s = 0; s < 32; ++s) {
        int pg = pbase + s * 256 + tid;
        int v2 = pg * 2;
        int tensor = v2 >> 16;
        int rem = v2 & 65535;
        int b = rem >> 8, k = rem & 255;
        float2 hv = *(const float2*)&hidden[v2];
        uint hi, lo; split2(hv.x, hv.y, hi, lo);
        int lanep = ((b & 7) << 2) | ((k >> 1) & 3);
        int reg = ((b & 15) >> 3) | (((k & 15) >> 3) << 1);
        int grp = b >> 4;
        int idx = (k >> 4) * 128 + lanep * 4 + reg;
        if (tensor == 0) { g_h0F[3][grp][idx] = hi; g_h0F[3][grp][2048 + idx] = lo; }
        else             { g_h1F[3][grp][idx] = hi; g_h1F[3][grp][2048 + idx] = lo; }
    }
}

// =====================================================================
// Prologue v2 (tensor-core, persistent): X0 = input @ Wih0^T + biases.
// 148 CTAs; W frags (H+L) staged once; loop over 16384 m16 x n256 x k128
// tiles; X0 stores shuffled through smem for coalescing.
// smem: sw uint[32768] @0 | sa float[16*132] @131072 | sout float[16*260]
// @139520 | sb float[256] @156160  -> total 157184
// =====================================================================
#define PRO2_SMEM 157184
__global__ void __launch_bounds__(256, 1) k_pro2(
    const float* __restrict__ inp, const float* __restrict__ Wih0,
    const float* __restrict__ bih0, const float* __restrict__ bhh0,
    const float* __restrict__ bias0)
{
    extern __shared__ char smch[];
    uint*  sw   = (uint*)smch;
    float* sa   = (float*)(smch + 131072);
    float* sout = (float*)(smch + 139520);
    float* sb   = (float*)(smch + 156160);

    const int bx = blockIdx.x, tid = threadIdx.x;
    const int lane = tid & 31, wi = tid >> 5;
    const int gID = lane >> 2, tig = lane & 3;
    const int acol = tig * 2;

    // W frag staging: 256 rows x 128 cols = 8192 float4
    for (int i = tid; i < 8192; i += 256) {
        int j = i >> 5, k4 = (i & 31) << 2;
        float4 w = *(const float4*)&Wih0[(size_t)j * INDIM + k4];
        uint h01, l01, h23, l23;
        split2(w.x, w.y, h01, l01);
        split2(w.z, w.w, h23, l23);
        int lane0 = ((j & 7) << 2) | ((k4 >> 1) & 3);
        int reg = (k4 >> 3) & 1, ksb = k4 >> 4, ng = j >> 3;
        int b0 = ((0 * 8 + ksb) * 32 + ng) * 32;
        int b1 = ((1 * 8 + ksb) * 32 + ng) * 32;
        sw[(b0 + lane0) * 2 + reg]     = h01;
        sw[(b0 + lane0 + 1) * 2 + reg] = h23;
        sw[(b1 + lane0) * 2 + reg]     = l01;
        sw[(b1 + lane0 + 1) * 2 + reg] = l23;
    }
    if (tid < 256) sb[tid] = bih0[tid] + bhh0[tid] + bias0[tid];
    __syncthreads();

    for (int mt = bx; mt < 16384; mt += 148) {
        const size_t r0 = (size_t)mt * 16;

        // load A tile 16x128 fp32 into smem (coalesced)
        #pragma unroll
        for (int it = 0; it < 2; ++it) {
            int i = tid + it * 256;            // 0..511
            int row = i >> 5, c4 = (i & 31) << 2;
            *(float4*)&sa[row * 132 + c4] = *(const float4*)&inp[(r0 + row) * INDIM + c4];
        }
        __syncthreads();

        // per-thread A frags (8 ksb x hi/lo)
        uint4 aH[8], aL[8];
        #pragma unroll
        for (int ksb = 0; ksb < 8; ++ksb) {
            int cb = ksb * 16 + acol;
            float2 p0 = *(const float2*)&sa[gID * 132 + cb];
            float2 p1 = *(const float2*)&sa[(gID + 8) * 132 + cb];
            float2 p2 = *(const float2*)&sa[gID * 132 + cb + 8];
            float2 p3 = *(const float2*)&sa[(gID + 8) * 132 + cb + 8];
            split2(p0.x, p0.y, aH[ksb].x, aL[ksb].x);
            split2(p1.x, p1.y, aH[ksb].y, aL[ksb].y);
            split2(p2.x, p2.y, aH[ksb].z, aL[ksb].z);
            split2(p3.x, p3.y, aH[ksb].w, aL[ksb].w);
        }

        float acc[4][4];
        #pragma unroll
        for (int n2 = 0; n2 < 4; ++n2)
            #pragma unroll
            for (int q = 0; q < 4; ++q) acc[n2][q] = 0.0f;

        #pragma unroll
        for (int ksb = 0; ksb < 8; ++ksb) {
            #pragma unroll
            for (int n2 = 0; n2 < 4; ++n2) {
                int ngg = wi * 4 + n2;
                uint2 bH = *(const uint2*)&sw[(((0 * 8 + ksb) * 32 + ngg) * 32 + lane) * 2];
                uint2 bL = *(const uint2*)&sw[(((1 * 8 + ksb) * 32 + ngg) * 32 + lane) * 2];
                MMA16816(acc[n2], aH[ksb], bH);
                MMA16816(acc[n2], aL[ksb], bH);
                MMA16816(acc[n2], aH[ksb], bL);
            }
        }
        __syncthreads();   // sa reads done (sout overlaps nothing; just order tile reuse)

        // bias + stage to sout
        #pragma unroll
        for (int n2 = 0; n2 < 4; ++n2) {
            int j = (wi * 4 + n2) * 8 + acol;
            float2 bb = *(const float2*)&sb[j];
            *(float2*)&sout[gID * 260 + j]       = make_float2(acc[n2][0] + bb.x, acc[n2][1] + bb.y);
            *(float2*)&sout[(gID + 8) * 260 + j] = make_float2(acc[n2][2] + bb.x, acc[n2][3] + bb.y);
        }
        __syncthreads();

        // coalesced X0 store
        #pragma unroll
        for (int it = 0; it < 4; ++it) {
            int li = tid + it * 256;           // 0..1023 float4s
            int row = li >> 6, c4 = (li & 63) << 2;
            *(float4*)&g_X0[(r0 + row) * HH + c4] = *(const float4*)&sout[row * 260 + c4];
        }
        __syncthreads();
    }
}

// =====================================================================
// Persistent recurrence: 16 groups x 6 CTAs (validated R12 structure).
// Protocol v2: consumers poll arrival counters directly (no seq hop);
// two guards polled in parallel by warp0 / warp1.
// =====================================================================
#define RNN_SMEM 163840
__global__ void __launch_bounds__(256, 1) k_rnn(
    const float* __restrict__ Whh0, const float* __restrict__ Wih1,
    const float* __restrict__ Whh1, const float* __restrict__ bih1,
    const float* __restrict__ bhh1, const float* __restrict__ bias1)
{
    extern __shared__ uint smu[];
    const int bx = blockIdx.x, tid = threadIdx.x;
    const int lane = tid & 31, wi = tid >> 5;
    const int gID = lane >> 2, tig = lane & 3;
    const int g = bx / 6, role = bx % 6, g32 = g * 32;
    const int b0 = g * 16;

    if (role < 2) {
        // ================= layer 0: m16 x n128 x k256 =================
        const int jg0 = role * 128;
        uint* sw = smu;             // [2 ver][16 ksb][16 ng][32 lane][2 reg] = 32768
        uint* sa = smu + 32768;     // [2 ver][16 ksb][128] = 4096

        for (int i = tid; i < 8192; i += 256) {
            int jl = i >> 6, k4 = (i & 63) << 2;
            float4 w = *(const float4*)&Whh0[(size_t)(jg0 + jl) * HH + k4];
            uint h01, l01, h23, l23;
            split2(w.x, w.y, h01, l01);
            split2(w.z, w.w, h23, l23);
            int lane0 = ((jl & 7) << 2) | ((k4 >> 1) & 3);
            int reg = (k4 >> 3) & 1, ksb = k4 >> 4, ng = jl >> 3;
            sw[(((0 * 16 + ksb) * 16 + ng) * 32 + lane0) * 2 + reg]     = h01;
            sw[(((0 * 16 + ksb) * 16 + ng) * 32 + lane0 + 1) * 2 + reg] = h23;
            sw[(((1 * 16 + ksb) * 16 + ng) * 32 + lane0) * 2 + reg]     = l01;
            sw[(((1 * 16 + ksb) * 16 + ng) * 32 + lane0 + 1) * 2 + reg] = l23;
        }

        for (int t = 0; t < TT; ++t) {
            if (tid == 0)       { while ((int)ld_acq_u(&g_cnt0[g32]) < 2 * t) { } }
            else if (tid == 32) { while ((int)ld_acq_u(&g_cnt1[g32]) < 4 * (t - 3)) { } }
            __syncthreads();

            // X0 prefetch
            float2 px[2][2];
            const int jb = jg0 + wi * 16;
            #pragma unroll
            for (int ng2 = 0; ng2 < 2; ++ng2) {
                int j = jb + ng2 * 8 + 2 * tig;
                px[ng2][0] = __ldcs((const float2*)&g_X0[((size_t)t * BB + b0 + gID) * HH + j]);
                px[ng2][1] = __ldcs((const float2*)&g_X0[((size_t)t * BB + b0 + gID + 8) * HH + j]);
            }

            // stage A = h0(t-1) frags
            {
                const uint* src = g_h0F[(t + 3) & 3][g];
                #pragma unroll
                for (int it = 0; it < 4; ++it) {
                    int i = (tid + it * 256) * 4;
                    *(uint4*)&sa[i] = __ldcg((const uint4*)&src[i]);
                }
            }
            __syncthreads();

            float acc[2][2][4];
            #pragma unroll
            for (int kh = 0; kh < 2; ++kh)
                #pragma unroll
                for (int n2 = 0; n2 < 2; ++n2)
                    #pragma unroll
                    for (int q = 0; q < 4; ++q) acc[kh][n2][q] = 0.0f;

            #pragma unroll
            for (int kh = 0; kh < 2; ++kh)
                #pragma unroll
                for (int s = 0; s < 8; ++s) {
                    int ksb = kh * 8 + s;
                    uint4 aH = *(uint4*)&sa[ksb * 128 + lane * 4];
                    uint4 aL = *(uint4*)&sa[2048 + ksb * 128 + lane * 4];
                    #pragma unroll
                    for (int n2 = 0; n2 < 2; ++n2) {
                        int ngg = wi * 2 + n2;
                        uint2 bH = *(uint2*)&sw[(((0 * 16 + ksb) * 16 + ngg) * 32 + lane) * 2];
                        uint2 bL = *(uint2*)&sw[(((1 * 16 + ksb) * 16 + ngg) * 32 + lane) * 2];
                        MMA16816(acc[kh][n2], aH, bH);
                        MMA16816(acc[kh][n2], aL, bH);
                        MMA16816(acc[kh][n2], aH, bL);
                    }
                }

            // epilogue
            {
                uint* fH = g_h0F[t & 3][g];
                int ksb_j = (jg0 >> 4) + wi;
                uint4 hv, lv;
                #pragma unroll
                for (int n2 = 0; n2 < 2; ++n2) {
                    float d0 = acc[0][n2][0] + acc[1][n2][0];
                    float d1 = acc[0][n2][1] + acc[1][n2][1];
                    float d2 = acc[0][n2][2] + acc[1][n2][2];
                    float d3 = acc[0][n2][3] + acc[1][n2][3];
                    float v00 = tanh_fast(d0 + px[n2][0].x);
                    float v01 = tanh_fast(d1 + px[n2][0].y);
                    float v10 = tanh_fast(d2 + px[n2][1].x);
                    float v11 = tanh_fast(d3 + px[n2][1].y);
                    uint h0v, l0v, h1v, l1v;
                    split2(v00, v01, h0v, l0v);
                    split2(v10, v11, h1v, l1v);
                    if (n2 == 0) { hv.x = h0v; hv.y = h1v; lv.x = l0v; lv.y = l1v; }
                    else         { hv.z = h0v; hv.w = h1v; lv.z = l0v; lv.w = l1v; }
                    if (t == TT - 1) {
                        int j = jb + n2 * 8 + 2 * tig;
                        *(float2*)&g_h0last[(b0 + gID) * HH + j]     = make_float2(v00, v01);
                        *(float2*)&g_h0last[(b0 + gID + 8) * HH + j] = make_float2(v10, v11);
                    }
                }
                *(uint4*)&fH[ksb_j * 128 + lane * 4]        = hv;
                *(uint4*)&fH[2048 + ksb_j * 128 + lane * 4] = lv;
            }

            __syncthreads();
            if (tid == 0) arrive_acqrel(&g_cnt0[g32]);
        }
    } else {
        // ================= layer 1: m16 x n64 x k512 =================
        const int q64 = role - 2;
        const int jq0 = q64 * 64;
        uint* sw = smu;             // [2 ver][32 ksb][8 ng][32][2] = 32768
        uint* sa = smu + 32768;     // [2 ver][32 ksb][128] = 8192

        for (int i = tid; i < 8192; i += 256) {
            int jl = i >> 7, k4 = (i & 127) << 2;
            float4 w = (k4 < 256)
                ? *(const float4*)&Wih1[(size_t)(jq0 + jl) * HH + k4]
                : *(const float4*)&Whh1[(size_t)(jq0 + jl) * HH + (k4 - 256)];
            uint h01, l01, h23, l23;
            split2(w.x, w.y, h01, l01);
            split2(w.z, w.w, h23, l23);
            int lane0 = ((jl & 7) << 2) | ((k4 >> 1) & 3);
            int reg = (k4 >> 3) & 1, ksb = k4 >> 4, ng = jl >> 3;
            sw[(((0 * 32 + ksb) * 8 + ng) * 32 + lane0) * 2 + reg]     = h01;
            sw[(((0 * 32 + ksb) * 8 + ng) * 32 + lane0 + 1) * 2 + reg] = h23;
            sw[(((1 * 32 + ksb) * 8 + ng) * 32 + lane0) * 2 + reg]     = l01;
            sw[(((1 * 32 + ksb) * 8 + ng) * 32 + lane0 + 1) * 2 + reg] = l23;
        }

        const int jb = jq0 + wi * 8 + 2 * tig;
        const float bbx = bih1[jb] + bhh1[jb] + bias1[jb];
        const float bby = bih1[jb + 1] + bhh1[jb + 1] + bias1[jb + 1];

        for (int t = 0; t < TT; ++t) {
            if (tid == 0)       { while ((int)ld_acq_u(&g_cnt0[g32]) < 2 * (t + 1)) { } }
            else if (tid == 32) { while ((int)ld_acq_u(&g_cnt1[g32]) < 4 * t) { } }
            __syncthreads();

            // stage A: ksb 0..15 = h0(t), 16..31 = h1(t-1)
            {
                const uint* s0 = g_h0F[t & 3][g];
                const uint* s1 = g_h1F[(t + 3) & 3][g];
                #pragma unroll
                for (int it = 0; it < 8; ++it) {
                    int u4 = (tid + it * 256) * 4;
                    int ver = u4 >> 12, rem = u4 & 4095;
                    const uint* src = (rem < 2048) ? &s0[ver * 2048 + rem]
                                                   : &s1[ver * 2048 + rem - 2048];
                    *(uint4*)&sa[u4] = __ldcg((const uint4*)src);
                }
            }
            __syncthreads();

            float acc[4][4];
            #pragma unroll
            for (int kh = 0; kh < 4; ++kh)
                #pragma unroll
                for (int q = 0; q < 4; ++q) acc[kh][q] = 0.0f;

            #pragma unroll
            for (int ksb = 0; ksb < 32; ++ksb) {
                uint4 aH = *(uint4*)&sa[ksb * 128 + lane * 4];
                uint4 aL = *(uint4*)&sa[4096 + ksb * 128 + lane * 4];
                uint2 bH = *(uint2*)&sw[(((0 * 32 + ksb) * 8 + wi) * 32 + lane) * 2];
                uint2 bL = *(uint2*)&sw[(((1 * 32 + ksb) * 8 + wi) * 32 + lane) * 2];
                int kh = ksb >> 3;
                MMA16816(acc[kh], aH, bH);
                MMA16816(acc[kh], aL, bH);
                MMA16816(acc[kh], aH, bL);
            }

            // epilogue
            {
                float d0 = acc[0][0] + acc[1][0] + acc[2][0] + acc[3][0];
                float d1 = acc[0][1] + acc[1][1] + acc[2][1] + acc[3][1];
                float d2 = acc[0][2] + acc[1][2] + acc[2][2] + acc[3][2];
                float d3 = acc[0][3] + acc[1][3] + acc[2][3] + acc[3][3];
                float v00 = tanh_fast(d0 + bbx);
                float v01 = tanh_fast(d1 + bby);
                float v10 = tanh_fast(d2 + bbx);
                float v11 = tanh_fast(d3 + bby);
                __stcs((float2*)&g_h1all[((size_t)t * BB + b0 + gID) * HH + jb], make_float2(v00, v01));
                __stcs((float2*)&g_h1all[((size_t)t * BB + b0 + gID + 8) * HH + jb], make_float2(v10, v11));
                if (t == TT - 1) {
                    *(float2*)&g_h1last[(b0 + gID) * HH + jb]     = make_float2(v00, v01);
                    *(float2*)&g_h1last[(b0 + gID + 8) * HH + jb] = make_float2(v10, v11);
                }
                uint h0v, l0v, h1v, l1v;
                split2(v00, v01, h0v, l0v);
                split2(v10, v11, h1v, l1v);
                uint* fH = g_h1F[t & 3][g];
                int ksb_j = q64 * 4 + (wi >> 1);
                int off = (wi & 1) << 1;
                *(uint2*)&fH[ksb_j * 128 + lane * 4 + off]        = make_uint2(h0v, h1v);
                *(uint2*)&fH[2048 + ksb_j * 128 + lane * 4 + off] = make_uint2(l0v, l1v);
            }

            __syncthreads();
            if (tid == 0) arrive_acqrel(&g_cnt1[g32]);
        }
    }
}

// =====================================================================
// Epilogue: logits = h1all @ fc_w^T + fc_b; copy last hidden.
// =====================================================================
__global__ void __launch_bounds__(256) k_epilogue(
    const float* __restrict__ fcw, const float* __restrict__ fcb,
    float* __restrict__ out, int out_size)
{
    int bx = blockIdx.x, tid = threadIdx.x;
    if (bx >= 32768) {
        int i = (bx - 32768) * 256 + tid;
        int base = TT * BB * 2;
        if (base + i < out_size) {
            float v = (i < BB * HH) ? g_h0last[i] : g_h1last[i - BB * HH];
            out[base + i] = v;
        }
        return;
    }
    __shared__ float sfw[2 * HH];
    __shared__ float sfb[2];
    for (int i = tid; i < 2 * HH; i += 256) sfw[i] = fcw[i];
    if (tid < 2) sfb[tid] = fcb[tid];
    __syncthreads();

    int w = tid >> 5, lane = tid & 31;
    size_t row = (size_t)bx * 8 + w;
    const float* hp = &g_h1all[row * HH + lane * 8];
    float4 h0v = *(const float4*)hp;
    float4 h1v = *(const float4*)(hp + 4);
    const float* w0 = &sfw[lane * 8];
    const float* w1 = &sfw[HH + lane * 8];
    float c0 = 0.f, c1 = 0.f;
    #pragma unroll
    for (int q = 0; q < 4; ++q) {
        c0 += (&h0v.x)[q] * w0[q] + (&h1v.x)[q] * w0[q + 4];
        c1 += (&h0v.x)[q] * w1[q] + (&h1v.x)[q] * w1[q + 4];
    }
    #pragma unroll
    for (int off = 16; off > 0; off >>= 1) {
        c0 += __shfl_down_sync(0xFFFFFFFFu, c0, off);
        c1 += __shfl_down_sync(0xFFFFFFFFu, c1, off);
    }
    if (lane == 0) {
        out[row * 2 + 0] = c0 + sfb[0];
        out[row * 2 + 1] = c1 + sfb[1];
    }
}

// ---------------- launch ----------------
extern "C" void kernel_launch(void* const* d_in, const int* in_sizes, int n_in,
                              void* d_out, int out_size) {
    const float* inp    = (const float*)d_in[0];
    const float* hidden = (const float*)d_in[1];
    const float* Wih0   = (const float*)d_in[2];
    const float* bih0   = (const float*)d_in[3];
    const float* Whh0   = (const float*)d_in[4];
    const float* bhh0   = (const float*)d_in[5];
    const float* bias0  = (const float*)d_in[6];
    const float* Wih1   = (const float*)d_in[7];
    const float* bih1   = (const float*)d_in[8];
    const float* Whh1   = (const float*)d_in[9];
    const float* bhh1   = (const float*)d_in[10];
    const float* bias1  = (const float*)d_in[11];
    const float* fcw    = (const float*)d_in[12];
    const float* fcb    = (const float*)d_in[13];
    float* out = (float*)d_out;

    static bool attr_done = false;
    if (!attr_done) {
        cudaFuncSetAttribute(k_pro2, cudaFuncAttributeMaxDynamicSharedMemorySize, PRO2_SMEM);
        cudaFuncSetAttribute(k_rnn,  cudaFuncAttributeMaxDynamicSharedMemorySize, RNN_SMEM);
        attr_done = true;
    }

    k_seed<<<9, 256>>>(hidden);
    k_pro2<<<148, 256, PRO2_SMEM>>>(inp, Wih0, bih0, bhh0, bias0);
    k_rnn<<<96, 256, RNN_SMEM>>>(Whh0, Wih1, Whh1, bih1, bhh1, bias1);
    k_epilogue<<<33280, 256>>>(fcw, fcb, out, out_size);
}

// round 14
// speedup vs baseline: 7.2798x; 1.3071x over previous
#include <cuda_runtime.h>
#include <cuda_bf16.h>
#include <cstddef>

#define TT    1024
#define BB    256
#define INDIM 128
#define HH    256
#define NG    16     // batch groups of 16 rows; 6 CTAs each

typedef unsigned long long ull;
typedef unsigned int uint;

// ---------------- scratch (device globals) ----------------
__device__ float g_X0[(size_t)TT * BB * HH];      // input proj + biases (fp32)
__device__ float g_h1all[(size_t)TT * BB * HH];   // all layer-1 hidden (fp32, for logits)
__device__ float g_h0last[BB * HH];
__device__ float g_h1last[BB * HH];
// s8 A-fragment rings (IMMA m16n8k32 layout), group-local:
// uint idx = ver*1024 + ksb*128 + lane*4 + reg ; byte of uint = k&3
__device__ uint g_h0F[4][NG][2048];
__device__ uint g_h1F[4][NG][2048];
__device__ __align__(128) unsigned g_cnt0[NG * 32];
__device__ __align__(128) unsigned g_cnt1[NG * 32];

// ---------------- acq/rel primitives ----------------
__device__ __forceinline__ unsigned arrive_acqrel(unsigned* p) {
    unsigned r;
    asm volatile("atom.acq_rel.gpu.global.add.u32 %0, [%1], 1;" : "=r"(r) : "l"(p) : "memory");
    return r;
}
__device__ __forceinline__ unsigned ld_acq_u(const unsigned* p) {
    unsigned r;
    asm volatile("ld.acquire.gpu.global.u32 %0, [%1];" : "=r"(r) : "l"(p) : "memory");
    return r;
}

__device__ __forceinline__ float tanh_fast(float x) {
    float xc = fminf(fmaxf(x, -15.0f), 15.0f);
    float e  = __expf(2.0f * xc);
    return __fdividef(e - 1.0f, e + 1.0f);
}
// bf16 split (prologue only)
__device__ __forceinline__ void split2(float a, float b, uint& hi, uint& lo) {
    __nv_bfloat162 h = __floats2bfloat162_rn(a, b);
    float ha = __bfloat162float(h.x), hb = __bfloat162float(h.y);
    __nv_bfloat162 l = __floats2bfloat162_rn(a - ha, b - hb);
    hi = *(uint*)&h; lo = *(uint*)&l;
}
// s16 fixed-point limb split: v in [-16384,16384] -> hi in [-64,64], lo in [-128,127]
__device__ __forceinline__ void qlimbs(float v, float scale, int& hi, int& lo) {
    int q = __float2int_rn(v * scale);
    hi = (q + 128) >> 8;
    lo = q - (hi << 8);
}
__device__ __forceinline__ uint pack4(int a, int b, int c, int d) {
    return (uint)(unsigned char)a | ((uint)(unsigned char)b << 8) |
           ((uint)(unsigned char)c << 16) | ((uint)(unsigned char)d << 24);
}
__device__ __forceinline__ unsigned short pack2s(int a, int b) {
    return (unsigned short)((uint)(unsigned char)a | ((uint)(unsigned char)b << 8));
}

#define MMA16816(d, a, b) \
    asm volatile("mma.sync.aligned.m16n8k16.row.col.f32.bf16.bf16.f32 " \
        "{%0,%1,%2,%3}, {%4,%5,%6,%7}, {%8,%9}, {%0,%1,%2,%3};" \
        : "+f"(d[0]), "+f"(d[1]), "+f"(d[2]), "+f"(d[3]) \
        : "r"((a).x), "r"((a).y), "r"((a).z), "r"((a).w), "r"((b).x), "r"((b).y))

#define IMMA16832(d, a, b) \
    asm volatile("mma.sync.aligned.m16n8k32.row.col.s32.s8.s8.s32 " \
        "{%0,%1,%2,%3}, {%4,%5,%6,%7}, {%8,%9}, {%0,%1,%2,%3};" \
        : "+r"((d)[0]), "+r"((d)[1]), "+r"((d)[2]), "+r"((d)[3]) \
        : "r"((a).x), "r"((a).y), "r"((a).z), "r"((a).w), "r"((b).x), "r"((b).y))

#define S16C 3.0517578125e-05f        // 2^-15
#define S8C  1.1920928955078125e-07f  // 2^-23

// =====================================================================
// Seed: pack initial hidden into s8 limb frag rings (slot 3); reset counters.
// =====================================================================
__global__ void __launch_bounds__(256) k_seed(const float* __restrict__ hidden) {
    int bx = blockIdx.x, tid = threadIdx.x;
    if (bx == 8) {
        if (tid < NG) { g_cnt0[tid * 32] = 0; g_cnt1[tid * 32] = 0; }
        return;
    }
    for (int s = 0; s < 16; ++s) {
        int it = bx * 4096 + s * 256 + tid;        // 0..32767
        int tensor = it >> 14;
        int rem = it & 16383;
        int b = rem >> 6, k4 = (rem & 63) << 2;
        float4 hv = *(const float4*)&hidden[(size_t)tensor * BB * HH + b * HH + k4];
        int h0,l0,h1,l1,h2,l2,h3,l3;
        qlimbs(hv.x, 16384.f, h0, l0); qlimbs(hv.y, 16384.f, h1, l1);
        qlimbs(hv.z, 16384.f, h2, l2); qlimbs(hv.w, 16384.f, h3, l3);
        uint uH = pack4(h0,h1,h2,h3), uL = pack4(l0,l1,l2,l3);
        int r = b & 15, grp = b >> 4;
        int lane = ((r & 7) << 2) | ((k4 >> 2) & 3);
        int reg = ((r >> 3) & 1) | (((k4 >> 4) & 1) << 1);
        int idx = (k4 >> 5) * 128 + lane * 4 + reg;
        uint* ring = (tensor == 0) ? g_h0F[3][grp] : g_h1F[3][grp];
        ring[idx] = uH; ring[1024 + idx] = uL;
    }
}

// =====================================================================
// Prologue (tensor-core bf16 3-term, validated R13): X0 = inp @ Wih0^T + biases.
// =====================================================================
#define PRO2_SMEM 157184
__global__ void __launch_bounds__(256, 1) k_pro2(
    const float* __restrict__ inp, const float* __restrict__ Wih0,
    const float* __restrict__ bih0, const float* __restrict__ bhh0,
    const float* __restrict__ bias0)
{
    extern __shared__ char smch[];
    uint*  sw   = (uint*)smch;
    float* sa   = (float*)(smch + 131072);
    float* sout = (float*)(smch + 139520);
    float* sb   = (float*)(smch + 156160);

    const int bx = blockIdx.x, tid = threadIdx.x;
    const int lane = tid & 31, wi = tid >> 5;
    const int gID = lane >> 2, tig = lane & 3;
    const int acol = tig * 2;

    for (int i = tid; i < 8192; i += 256) {
        int j = i >> 5, k4 = (i & 31) << 2;
        float4 w = *(const float4*)&Wih0[(size_t)j * INDIM + k4];
        uint h01, l01, h23, l23;
        split2(w.x, w.y, h01, l01);
        split2(w.z, w.w, h23, l23);
        int lane0 = ((j & 7) << 2) | ((k4 >> 1) & 3);
        int reg = (k4 >> 3) & 1, ksb = k4 >> 4, ng = j >> 3;
        int b0 = ((0 * 8 + ksb) * 32 + ng) * 32;
        int b1 = ((1 * 8 + ksb) * 32 + ng) * 32;
        sw[(b0 + lane0) * 2 + reg]     = h01;
        sw[(b0 + lane0 + 1) * 2 + reg] = h23;
        sw[(b1 + lane0) * 2 + reg]     = l01;
        sw[(b1 + lane0 + 1) * 2 + reg] = l23;
    }
    if (tid < 256) sb[tid] = bih0[tid] + bhh0[tid] + bias0[tid];
    __syncthreads();

    for (int mt = bx; mt < 16384; mt += 148) {
        const size_t r0 = (size_t)mt * 16;
        #pragma unroll
        for (int it = 0; it < 2; ++it) {
            int i = tid + it * 256;
            int row = i >> 5, c4 = (i & 31) << 2;
            *(float4*)&sa[row * 132 + c4] = *(const float4*)&inp[(r0 + row) * INDIM + c4];
        }
        __syncthreads();

        uint4 aH[8], aL[8];
        #pragma unroll
        for (int ksb = 0; ksb < 8; ++ksb) {
            int cb = ksb * 16 + acol;
            float2 p0 = *(const float2*)&sa[gID * 132 + cb];
            float2 p1 = *(const float2*)&sa[(gID + 8) * 132 + cb];
            float2 p2 = *(const float2*)&sa[gID * 132 + cb + 8];
            float2 p3 = *(const float2*)&sa[(gID + 8) * 132 + cb + 8];
            split2(p0.x, p0.y, aH[ksb].x, aL[ksb].x);
            split2(p1.x, p1.y, aH[ksb].y, aL[ksb].y);
            split2(p2.x, p2.y, aH[ksb].z, aL[ksb].z);
            split2(p3.x, p3.y, aH[ksb].w, aL[ksb].w);
        }

        float acc[4][4];
        #pragma unroll
        for (int n2 = 0; n2 < 4; ++n2)
            #pragma unroll
            for (int q = 0; q < 4; ++q) acc[n2][q] = 0.0f;

        #pragma unroll
        for (int ksb = 0; ksb < 8; ++ksb) {
            #pragma unroll
            for (int n2 = 0; n2 < 4; ++n2) {
                int ngg = wi * 4 + n2;
                uint2 bH = *(const uint2*)&sw[(((0 * 8 + ksb) * 32 + ngg) * 32 + lane) * 2];
                uint2 bL = *(const uint2*)&sw[(((1 * 8 + ksb) * 32 + ngg) * 32 + lane) * 2];
                MMA16816(acc[n2], aH[ksb], bH);
                MMA16816(acc[n2], aL[ksb], bH);
                MMA16816(acc[n2], aH[ksb], bL);
            }
        }
        __syncthreads();

        #pragma unroll
        for (int n2 = 0; n2 < 4; ++n2) {
            int j = (wi * 4 + n2) * 8 + acol;
            float2 bb = *(const float2*)&sb[j];
            *(float2*)&sout[gID * 260 + j]       = make_float2(acc[n2][0] + bb.x, acc[n2][1] + bb.y);
            *(float2*)&sout[(gID + 8) * 260 + j] = make_float2(acc[n2][2] + bb.x, acc[n2][3] + bb.y);
        }
        __syncthreads();

        #pragma unroll
        for (int it = 0; it < 4; ++it) {
            int li = tid + it * 256;
            int row = li >> 6, c4 = (li & 63) << 2;
            *(float4*)&g_X0[(r0 + row) * HH + c4] = *(const float4*)&sout[row * 260 + c4];
        }
        __syncthreads();
    }
}

// =====================================================================
// Persistent recurrence, INT8 IMMA version. 16 groups x 6 CTAs.
// role 0,1: layer0 (m16 n128 k256). role 2..5: layer1 (m16 n64 k512).
// Per tile: 3 IMMA sets: hh -> accA (2^16), hi*lo -> accB, lo*hi -> accC (2^8).
// =====================================================================
#define RNN_SMEM 81920
__global__ void __launch_bounds__(256, 1) k_rnn(
    const float* __restrict__ Whh0, const float* __restrict__ Wih1,
    const float* __restrict__ Whh1, const float* __restrict__ bih1,
    const float* __restrict__ bhh1, const float* __restrict__ bias1)
{
    extern __shared__ uint smu[];
    const int bx = blockIdx.x, tid = threadIdx.x;
    const int lane = tid & 31, wi = tid >> 5;
    const int gID = lane >> 2, tig = lane & 3;
    const int g = bx / 6, role = bx % 6, g32 = g * 32;
    const int b0 = g * 16;

    if (role < 2) {
        // ================= layer 0: m16 x n128 x k256 =================
        const int jg0 = role * 128;
        uint* sw = smu;             // [2 ver][8 ksb][16 ng][32 lane][2 reg] = 16384
        uint* sa = smu + 16384;     // [2 ver][8 ksb][128] = 2048

        // W limb staging: 128 rows x 64 k4-groups
        for (int i = tid; i < 8192; i += 256) {
            int jl = i >> 6, k4 = (i & 63) << 2;
            float4 w = *(const float4*)&Whh0[(size_t)(jg0 + jl) * HH + k4];
            int h0,l0,h1,l1,h2,l2,h3,l3;
            qlimbs(w.x, 131072.f, h0, l0); qlimbs(w.y, 131072.f, h1, l1);
            qlimbs(w.z, 131072.f, h2, l2); qlimbs(w.w, 131072.f, h3, l3);
            int lane0 = ((jl & 7) << 2) | ((k4 >> 2) & 3);
            int reg = (k4 >> 4) & 1, ksb = k4 >> 5, ng = jl >> 3;
            sw[(((0 * 8 + ksb) * 16 + ng) * 64) + lane0 * 2 + reg] = pack4(h0,h1,h2,h3);
            sw[(((1 * 8 + ksb) * 16 + ng) * 64) + lane0 * 2 + reg] = pack4(l0,l1,l2,l3);
        }

        for (int t = 0; t < TT; ++t) {
            if (tid == 0)       { while ((int)ld_acq_u(&g_cnt0[g32]) < 2 * t) { } }
            else if (tid == 32) { while ((int)ld_acq_u(&g_cnt1[g32]) < 4 * (t - 3)) { } }
            __syncthreads();

            // X0 prefetch
            float2 px[2][2];
            const int jb = jg0 + wi * 16;
            #pragma unroll
            for (int n2 = 0; n2 < 2; ++n2) {
                int j = jb + n2 * 8 + 2 * tig;
                px[n2][0] = __ldcs((const float2*)&g_X0[((size_t)t * BB + b0 + gID) * HH + j]);
                px[n2][1] = __ldcs((const float2*)&g_X0[((size_t)t * BB + b0 + gID + 8) * HH + j]);
            }

            // stage A = h0(t-1) s8 frags (8KB)
            {
                const uint* src = g_h0F[(t + 3) & 3][g];
                #pragma unroll
                for (int it = 0; it < 2; ++it) {
                    int i = (tid + it * 256) * 4;
                    *(uint4*)&sa[i] = __ldcg((const uint4*)&src[i]);
                }
            }
            __syncthreads();

            int accA[2][4], accB[2][4], accC[2][4];
            #pragma unroll
            for (int n2 = 0; n2 < 2; ++n2)
                #pragma unroll
                for (int q = 0; q < 4; ++q) { accA[n2][q] = 0; accB[n2][q] = 0; accC[n2][q] = 0; }

            #pragma unroll
            for (int ksb = 0; ksb < 8; ++ksb) {
                uint4 aH = *(uint4*)&sa[ksb * 128 + lane * 4];
                uint4 aL = *(uint4*)&sa[1024 + ksb * 128 + lane * 4];
                #pragma unroll
                for (int n2 = 0; n2 < 2; ++n2) {
                    int ngg = wi * 2 + n2;
                    uint2 bH = *(uint2*)&sw[((0 * 8 + ksb) * 16 + ngg) * 64 + lane * 2];
                    uint2 bL = *(uint2*)&sw[((1 * 8 + ksb) * 16 + ngg) * 64 + lane * 2];
                    IMMA16832(accA[n2], aH, bH);
                    IMMA16832(accB[n2], aH, bL);
                    IMMA16832(accC[n2], aL, bH);
                }
            }

            // epilogue: combine scales, + X0, tanh, quantize, frag halfword stores
            {
                uint* ring = g_h0F[t & 3][g];
                int cc0 = jb + 2 * tig;                         // col for n2=0
                #pragma unroll
                for (int n2 = 0; n2 < 2; ++n2) {
                    int cc = cc0 + n2 * 8;
                    float d0 = (float)accA[n2][0] * S16C + (float)(accB[n2][0] + accC[n2][0]) * S8C;
                    float d1 = (float)accA[n2][1] * S16C + (float)(accB[n2][1] + accC[n2][1]) * S8C;
                    float d2 = (float)accA[n2][2] * S16C + (float)(accB[n2][2] + accC[n2][2]) * S8C;
                    float d3 = (float)accA[n2][3] * S16C + (float)(accB[n2][3] + accC[n2][3]) * S8C;
                    float v00 = tanh_fast(d0 + px[n2][0].x);
                    float v01 = tanh_fast(d1 + px[n2][0].y);
                    float v10 = tanh_fast(d2 + px[n2][1].x);
                    float v11 = tanh_fast(d3 + px[n2][1].y);
                    int h00,l00,h01_,l01_,h10,l10,h11,l11;
                    qlimbs(v00, 16384.f, h00, l00); qlimbs(v01, 16384.f, h01_, l01_);
                    qlimbs(v10, 16384.f, h10, l10); qlimbs(v11, 16384.f, h11, l11);
                    int ksb_c = cc >> 5;
                    int lane_c = (gID << 2) | ((cc & 15) >> 2);
                    int idx0 = ksb_c * 128 + lane_c * 4 + (((cc >> 4) & 1) << 1);
                    int boff = cc & 2;
                    *(unsigned short*)((char*)(ring + idx0) + boff)            = pack2s(h00, h01_);
                    *(unsigned short*)((char*)(ring + idx0 + 1) + boff)        = pack2s(h10, h11);
                    *(unsigned short*)((char*)(ring + 1024 + idx0) + boff)     = pack2s(l00, l01_);
                    *(unsigned short*)((char*)(ring + 1024 + idx0 + 1) + boff) = pack2s(l10, l11);
                    if (t == TT - 1) {
                        *(float2*)&g_h0last[(b0 + gID) * HH + cc]     = make_float2(v00, v01);
                        *(float2*)&g_h0last[(b0 + gID + 8) * HH + cc] = make_float2(v10, v11);
                    }
                }
            }

            __syncthreads();
            if (tid == 0) arrive_acqrel(&g_cnt0[g32]);
        }
    } else {
        // ================= layer 1: m16 x n64 x k512 =================
        const int q64 = role - 2;
        const int jq0 = q64 * 64;
        uint* sw = smu;             // [2 ver][16 ksb][8 ng][32][2] = 16384
        uint* sa = smu + 16384;     // [2 ver][16 ksb][128] = 4096

        // W limb staging: 64 rows x 128 k4-groups (k<256: Wih1, else Whh1)
        for (int i = tid; i < 8192; i += 256) {
            int jl = i >> 7, k4 = (i & 127) << 2;
            float4 w = (k4 < 256)
                ? *(const float4*)&Wih1[(size_t)(jq0 + jl) * HH + k4]
                : *(const float4*)&Whh1[(size_t)(jq0 + jl) * HH + (k4 - 256)];
            int h0,l0,h1,l1,h2,l2,h3,l3;
            qlimbs(w.x, 131072.f, h0, l0); qlimbs(w.y, 131072.f, h1, l1);
            qlimbs(w.z, 131072.f, h2, l2); qlimbs(w.w, 131072.f, h3, l3);
            int lane0 = ((jl & 7) << 2) | ((k4 >> 2) & 3);
            int reg = (k4 >> 4) & 1, ksb = k4 >> 5, ng = jl >> 3;
            sw[(((0 * 16 + ksb) * 8 + ng) * 64) + lane0 * 2 + reg] = pack4(h0,h1,h2,h3);
            sw[(((1 * 16 + ksb) * 8 + ng) * 64) + lane0 * 2 + reg] = pack4(l0,l1,l2,l3);
        }

        const int jb = jq0 + wi * 8 + 2 * tig;
        const float bbx = bih1[jb] + bhh1[jb] + bias1[jb];
        const float bby = bih1[jb + 1] + bhh1[jb + 1] + bias1[jb + 1];

        for (int t = 0; t < TT; ++t) {
            if (tid == 0)       { while ((int)ld_acq_u(&g_cnt0[g32]) < 2 * (t + 1)) { } }
            else if (tid == 32) { while ((int)ld_acq_u(&g_cnt1[g32]) < 4 * t) { } }
            __syncthreads();

            // stage A: sa ksb 0..7 = h0(t), 8..15 = h1(t-1), per ver (16KB)
            {
                const uint* s0 = g_h0F[t & 3][g];
                const uint* s1 = g_h1F[(t + 3) & 3][g];
                #pragma unroll
                for (int it = 0; it < 4; ++it) {
                    int u4 = (tid + it * 256) * 4;          // 0..4095
                    int ver = u4 >> 11, rem = u4 & 2047;
                    const uint* src = (rem < 1024) ? &s0[ver * 1024 + rem]
                                                   : &s1[ver * 1024 + rem - 1024];
                    *(uint4*)&sa[u4] = __ldcg((const uint4*)src);
                }
            }
            __syncthreads();

            int accA[2][4], accB[2][4], accC[2][4];   // parity-split chains
            #pragma unroll
            for (int p = 0; p < 2; ++p)
                #pragma unroll
                for (int q = 0; q < 4; ++q) { accA[p][q] = 0; accB[p][q] = 0; accC[p][q] = 0; }

            #pragma unroll
            for (int ksb = 0; ksb < 16; ++ksb) {
                int p = ksb & 1;
                uint4 aH = *(uint4*)&sa[ksb * 128 + lane * 4];
                uint4 aL = *(uint4*)&sa[2048 + ksb * 128 + lane * 4];
                uint2 bH = *(uint2*)&sw[((0 * 16 + ksb) * 8 + wi) * 64 + lane * 2];
                uint2 bL = *(uint2*)&sw[((1 * 16 + ksb) * 8 + wi) * 64 + lane * 2];
                IMMA16832(accA[p], aH, bH);
                IMMA16832(accB[p], aH, bL);
                IMMA16832(accC[p], aL, bH);
            }

            // epilogue
            {
                float d[4];
                #pragma unroll
                for (int q = 0; q < 4; ++q) {
                    int iA = accA[0][q] + accA[1][q];
                    int iBC = accB[0][q] + accB[1][q] + accC[0][q] + accC[1][q];
                    d[q] = (float)iA * S16C + (float)iBC * S8C;
                }
                float v00 = tanh_fast(d[0] + bbx);
                float v01 = tanh_fast(d[1] + bby);
                float v10 = tanh_fast(d[2] + bbx);
                float v11 = tanh_fast(d[3] + bby);
                __stcs((float2*)&g_h1all[((size_t)t * BB + b0 + gID) * HH + jb], make_float2(v00, v01));
                __stcs((float2*)&g_h1all[((size_t)t * BB + b0 + gID + 8) * HH + jb], make_float2(v10, v11));
                if (t == TT - 1) {
                    *(float2*)&g_h1last[(b0 + gID) * HH + jb]     = make_float2(v00, v01);
                    *(float2*)&g_h1last[(b0 + gID + 8) * HH + jb] = make_float2(v10, v11);
                }
                int h00,l00,h01_,l01_,h10,l10,h11,l11;
                qlimbs(v00, 16384.f, h00, l00); qlimbs(v01, 16384.f, h01_, l01_);
                qlimbs(v10, 16384.f, h10, l10); qlimbs(v11, 16384.f, h11, l11);
                uint* ring = g_h1F[t & 3][g];
                int cc = jb;
                int ksb_c = cc >> 5;
                int lane_c = (gID << 2) | ((cc & 15) >> 2);
                int idx0 = ksb_c * 128 + lane_c * 4 + (((cc >> 4) & 1) << 1);
                int boff = cc & 2;
                *(unsigned short*)((char*)(ring + idx0) + boff)            = pack2s(h00, h01_);
                *(unsigned short*)((char*)(ring + idx0 + 1) + boff)        = pack2s(h10, h11);
                *(unsigned short*)((char*)(ring + 1024 + idx0) + boff)     = pack2s(l00, l01_);
                *(unsigned short*)((char*)(ring + 1024 + idx0 + 1) + boff) = pack2s(l10, l11);
            }

            __syncthreads();
            if (tid == 0) arrive_acqrel(&g_cnt1[g32]);
        }
    }
}

// =====================================================================
// Epilogue: logits = h1all @ fc_w^T + fc_b; copy last hidden.
// =====================================================================
__global__ void __launch_bounds__(256) k_epilogue(
    const float* __restrict__ fcw, const float* __restrict__ fcb,
    float* __restrict__ out, int out_size)
{
    int bx = blockIdx.x, tid = threadIdx.x;
    if (bx >= 32768) {
        int i = (bx - 32768) * 256 + tid;
        int base = TT * BB * 2;
        if (base + i < out_size) {
            float v = (i < BB * HH) ? g_h0last[i] : g_h1last[i - BB * HH];
            out[base + i] = v;
        }
        return;
    }
    __shared__ float sfw[2 * HH];
    __shared__ float sfb[2];
    for (int i = tid; i < 2 * HH; i += 256) sfw[i] = fcw[i];
    if (tid < 2) sfb[tid] = fcb[tid];
    __syncthreads();

    int w = tid >> 5, lane = tid & 31;
    size_t row = (size_t)bx * 8 + w;
    const float* hp = &g_h1all[row * HH + lane * 8];
    float4 h0v = *(const float4*)hp;
    float4 h1v = *(const float4*)(hp + 4);
    const float* w0 = &sfw[lane * 8];
    const float* w1 = &sfw[HH + lane * 8];
    float c0 = 0.f, c1 = 0.f;
    #pragma unroll
    for (int q = 0; q < 4; ++q) {
        c0 += (&h0v.x)[q] * w0[q] + (&h1v.x)[q] * w0[q + 4];
        c1 += (&h0v.x)[q] * w1[q] + (&h1v.x)[q] * w1[q + 4];
    }
    #pragma unroll
    for (int off = 16; off > 0; off >>= 1) {
        c0 += __shfl_down_sync(0xFFFFFFFFu, c0, off);
        c1 += __shfl_down_sync(0xFFFFFFFFu, c1, off);
    }
    if (lane == 0) {
        out[row * 2 + 0] = c0 + sfb[0];
        out[row * 2 + 1] = c1 + sfb[1];
    }
}

// ---------------- launch ----------------
extern "C" void kernel_launch(void* const* d_in, const int* in_sizes, int n_in,
                              void* d_out, int out_size) {
    const float* inp    = (const float*)d_in[0];
    const float* hidden = (const float*)d_in[1];
    const float* Wih0   = (const float*)d_in[2];
    const float* bih0   = (const float*)d_in[3];
    const float* Whh0   = (const float*)d_in[4];
    const float* bhh0   = (const float*)d_in[5];
    const float* bias0  = (const float*)d_in[6];
    const float* Wih1   = (const float*)d_in[7];
    const float* bih1   = (const float*)d_in[8];
    const float* Whh1   = (const float*)d_in[9];
    const float* bhh1   = (const float*)d_in[10];
    const float* bias1  = (const float*)d_in[11];
    const float* fcw    = (const float*)d_in[12];
    const float* fcb    = (const float*)d_in[13];
    float* out = (float*)d_out;

    static bool attr_done = false;
    if (!attr_done) {
        cudaFuncSetAttribute(k_pro2, cudaFuncAttributeMaxDynamicSharedMemorySize, PRO2_SMEM);
        cudaFuncSetAttribute(k_rnn,  cudaFuncAttributeMaxDynamicSharedMemorySize, RNN_SMEM);
        attr_done = true;
    }

    k_seed<<<9, 256>>>(hidden);
    k_pro2<<<148, 256, PRO2_SMEM>>>(inp, Wih0, bih0, bhh0, bias0);
    k_rnn<<<96, 256, RNN_SMEM>>>(Whh0, Wih1, Whh1, bih1, bhh1, bias1);
    k_epilogue<<<33280, 256>>>(fcw, fcb, out, out_size);
}

// round 15
// speedup vs baseline: 7.3398x; 1.0083x over previous
#include <cuda_runtime.h>
#include <cuda_bf16.h>
#include <cstddef>

#define TT    1024
#define BB    256
#define INDIM 128
#define HH    256
#define NG    16     // batch groups of 16 rows; 6 CTAs each

typedef unsigned long long ull;
typedef unsigned int uint;

// ---------------- scratch (device globals) ----------------
__device__ float g_X0[(size_t)TT * BB * HH];      // input proj + biases (fp32)
__device__ float g_h1all[(size_t)TT * BB * HH];   // all layer-1 hidden (fp32, for logits)
__device__ float g_h0last[BB * HH];
__device__ float g_h1last[BB * HH];
// s8 A-fragment rings (IMMA m16n8k32 layout), group-local:
// uint idx = ver*1024 + ksb*128 + lane*4 + reg ; byte of uint = k&3
__device__ uint g_h0F[4][NG][2048];
__device__ uint g_h1F[4][NG][2048];
__device__ __align__(128) unsigned g_cnt0[NG * 32];
__device__ __align__(128) unsigned g_cnt1[NG * 32];

// ---------------- acq/rel primitives ----------------
__device__ __forceinline__ unsigned arrive_acqrel(unsigned* p) {
    unsigned r;
    asm volatile("atom.acq_rel.gpu.global.add.u32 %0, [%1], 1;" : "=r"(r) : "l"(p) : "memory");
    return r;
}
__device__ __forceinline__ unsigned ld_acq_u(const unsigned* p) {
    unsigned r;
    asm volatile("ld.acquire.gpu.global.u32 %0, [%1];" : "=r"(r) : "l"(p) : "memory");
    return r;
}

__device__ __forceinline__ float tanh_fast(float x) {
    float xc = fminf(fmaxf(x, -15.0f), 15.0f);
    float e  = __expf(2.0f * xc);
    return __fdividef(e - 1.0f, e + 1.0f);
}
// bf16 split (prologue only)
__device__ __forceinline__ void split2(float a, float b, uint& hi, uint& lo) {
    __nv_bfloat162 h = __floats2bfloat162_rn(a, b);
    float ha = __bfloat162float(h.x), hb = __bfloat162float(h.y);
    __nv_bfloat162 l = __floats2bfloat162_rn(a - ha, b - hb);
    hi = *(uint*)&h; lo = *(uint*)&l;
}
// s16 fixed-point limb split
__device__ __forceinline__ void qlimbs(float v, float scale, int& hi, int& lo) {
    int q = __float2int_rn(v * scale);
    hi = (q + 128) >> 8;
    lo = q - (hi << 8);
}
__device__ __forceinline__ uint pack4(int a, int b, int c, int d) {
    return (uint)(unsigned char)a | ((uint)(unsigned char)b << 8) |
           ((uint)(unsigned char)c << 16) | ((uint)(unsigned char)d << 24);
}
__device__ __forceinline__ unsigned short pack2s(int a, int b) {
    return (unsigned short)((uint)(unsigned char)a | ((uint)(unsigned char)b << 8));
}

#define MMA16816(d, a, b) \
    asm volatile("mma.sync.aligned.m16n8k16.row.col.f32.bf16.bf16.f32 " \
        "{%0,%1,%2,%3}, {%4,%5,%6,%7}, {%8,%9}, {%0,%1,%2,%3};" \
        : "+f"(d[0]), "+f"(d[1]), "+f"(d[2]), "+f"(d[3]) \
        : "r"((a).x), "r"((a).y), "r"((a).z), "r"((a).w), "r"((b).x), "r"((b).y))

#define IMMA16832(d, a, b) \
    asm volatile("mma.sync.aligned.m16n8k32.row.col.s32.s8.s8.s32 " \
        "{%0,%1,%2,%3}, {%4,%5,%6,%7}, {%8,%9}, {%0,%1,%2,%3};" \
        : "+r"((d)[0]), "+r"((d)[1]), "+r"((d)[2]), "+r"((d)[3]) \
        : "r"((a).x), "r"((a).y), "r"((a).z), "r"((a).w), "r"((b).x), "r"((b).y))

#define S16C 3.0517578125e-05f        // 2^-15
#define S8C  1.1920928955078125e-07f  // 2^-23

// =====================================================================
// Seed: pack initial hidden into s8 limb frag rings (slot 3); reset counters.
// =====================================================================
__global__ void __launch_bounds__(256) k_seed(const float* __restrict__ hidden) {
    int bx = blockIdx.x, tid = threadIdx.x;
    if (bx == 8) {
        if (tid < NG) { g_cnt0[tid * 32] = 0; g_cnt1[tid * 32] = 0; }
        return;
    }
    for (int s = 0; s < 16; ++s) {
        int it = bx * 4096 + s * 256 + tid;        // 0..32767
        int tensor = it >> 14;
        int rem = it & 16383;
        int b = rem >> 6, k4 = (rem & 63) << 2;
        float4 hv = *(const float4*)&hidden[(size_t)tensor * BB * HH + b * HH + k4];
        int h0,l0,h1,l1,h2,l2,h3,l3;
        qlimbs(hv.x, 16384.f, h0, l0); qlimbs(hv.y, 16384.f, h1, l1);
        qlimbs(hv.z, 16384.f, h2, l2); qlimbs(hv.w, 16384.f, h3, l3);
        uint uH = pack4(h0,h1,h2,h3), uL = pack4(l0,l1,l2,l3);
        int r = b & 15, grp = b >> 4;
        int lane = ((r & 7) << 2) | ((k4 >> 2) & 3);
        int reg = ((r >> 3) & 1) | (((k4 >> 4) & 1) << 1);
        int idx = (k4 >> 5) * 128 + lane * 4 + reg;
        uint* ring = (tensor == 0) ? g_h0F[3][grp] : g_h1F[3][grp];
        ring[idx] = uH; ring[1024 + idx] = uL;
    }
}

// =====================================================================
// Prologue (tensor-core bf16 3-term, validated R13): X0 = inp @ Wih0^T + biases.
// =====================================================================
#define PRO2_SMEM 157184
__global__ void __launch_bounds__(256, 1) k_pro2(
    const float* __restrict__ inp, const float* __restrict__ Wih0,
    const float* __restrict__ bih0, const float* __restrict__ bhh0,
    const float* __restrict__ bias0)
{
    extern __shared__ char smch[];
    uint*  sw   = (uint*)smch;
    float* sa   = (float*)(smch + 131072);
    float* sout = (float*)(smch + 139520);
    float* sb   = (float*)(smch + 156160);

    const int bx = blockIdx.x, tid = threadIdx.x;
    const int lane = tid & 31, wi = tid >> 5;
    const int gID = lane >> 2, tig = lane & 3;
    const int acol = tig * 2;

    for (int i = tid; i < 8192; i += 256) {
        int j = i >> 5, k4 = (i & 31) << 2;
        float4 w = *(const float4*)&Wih0[(size_t)j * INDIM + k4];
        uint h01, l01, h23, l23;
        split2(w.x, w.y, h01, l01);
        split2(w.z, w.w, h23, l23);
        int lane0 = ((j & 7) << 2) | ((k4 >> 1) & 3);
        int reg = (k4 >> 3) & 1, ksb = k4 >> 4, ng = j >> 3;
        int b0 = ((0 * 8 + ksb) * 32 + ng) * 32;
        int b1 = ((1 * 8 + ksb) * 32 + ng) * 32;
        sw[(b0 + lane0) * 2 + reg]     = h01;
        sw[(b0 + lane0 + 1) * 2 + reg] = h23;
        sw[(b1 + lane0) * 2 + reg]     = l01;
        sw[(b1 + lane0 + 1) * 2 + reg] = l23;
    }
    if (tid < 256) sb[tid] = bih0[tid] + bhh0[tid] + bias0[tid];
    __syncthreads();

    for (int mt = bx; mt < 16384; mt += 148) {
        const size_t r0 = (size_t)mt * 16;
        #pragma unroll
        for (int it = 0; it < 2; ++it) {
            int i = tid + it * 256;
            int row = i >> 5, c4 = (i & 31) << 2;
            *(float4*)&sa[row * 132 + c4] = *(const float4*)&inp[(r0 + row) * INDIM + c4];
        }
        __syncthreads();

        uint4 aH[8], aL[8];
        #pragma unroll
        for (int ksb = 0; ksb < 8; ++ksb) {
            int cb = ksb * 16 + acol;
            float2 p0 = *(const float2*)&sa[gID * 132 + cb];
            float2 p1 = *(const float2*)&sa[(gID + 8) * 132 + cb];
            float2 p2 = *(const float2*)&sa[gID * 132 + cb + 8];
            float2 p3 = *(const float2*)&sa[(gID + 8) * 132 + cb + 8];
            split2(p0.x, p0.y, aH[ksb].x, aL[ksb].x);
            split2(p1.x, p1.y, aH[ksb].y, aL[ksb].y);
            split2(p2.x, p2.y, aH[ksb].z, aL[ksb].z);
            split2(p3.x, p3.y, aH[ksb].w, aL[ksb].w);
        }

        float acc[4][4];
        #pragma unroll
        for (int n2 = 0; n2 < 4; ++n2)
            #pragma unroll
            for (int q = 0; q < 4; ++q) acc[n2][q] = 0.0f;

        #pragma unroll
        for (int ksb = 0; ksb < 8; ++ksb) {
            #pragma unroll
            for (int n2 = 0; n2 < 4; ++n2) {
                int ngg = wi * 4 + n2;
                uint2 bH = *(const uint2*)&sw[(((0 * 8 + ksb) * 32 + ngg) * 32 + lane) * 2];
                uint2 bL = *(const uint2*)&sw[(((1 * 8 + ksb) * 32 + ngg) * 32 + lane) * 2];
                MMA16816(acc[n2], aH[ksb], bH);
                MMA16816(acc[n2], aL[ksb], bH);
                MMA16816(acc[n2], aH[ksb], bL);
            }
        }
        __syncthreads();

        #pragma unroll
        for (int n2 = 0; n2 < 4; ++n2) {
            int j = (wi * 4 + n2) * 8 + acol;
            float2 bb = *(const float2*)&sb[j];
            *(float2*)&sout[gID * 260 + j]       = make_float2(acc[n2][0] + bb.x, acc[n2][1] + bb.y);
            *(float2*)&sout[(gID + 8) * 260 + j] = make_float2(acc[n2][2] + bb.x, acc[n2][3] + bb.y);
        }
        __syncthreads();

        #pragma unroll
        for (int it = 0; it < 4; ++it) {
            int li = tid + it * 256;
            int row = li >> 6, c4 = (li & 63) << 2;
            *(float4*)&g_X0[(r0 + row) * HH + c4] = *(const float4*)&sout[row * 260 + c4];
        }
        __syncthreads();
    }
}

// =====================================================================
// Persistent recurrence, INT8 IMMA v2: direct-LDG A-frags (no smem staging),
// early arrive. 16 groups x 6 CTAs; smem = W frags only (64KB).
// =====================================================================
#define RNN_SMEM 65536
__global__ void __launch_bounds__(256, 1) k_rnn(
    const float* __restrict__ Whh0, const float* __restrict__ Wih1,
    const float* __restrict__ Whh1, const float* __restrict__ bih1,
    const float* __restrict__ bhh1, const float* __restrict__ bias1)
{
    extern __shared__ uint smu[];
    const int bx = blockIdx.x, tid = threadIdx.x;
    const int lane = tid & 31, wi = tid >> 5;
    const int gID = lane >> 2, tig = lane & 3;
    const int g = bx / 6, role = bx % 6, g32 = g * 32;
    const int b0 = g * 16;
    uint* sw = smu;   // 16384 uints both layers

    if (role < 2) {
        // ================= layer 0: m16 x n128 x k256 =================
        const int jg0 = role * 128;

        for (int i = tid; i < 8192; i += 256) {
            int jl = i >> 6, k4 = (i & 63) << 2;
            float4 w = *(const float4*)&Whh0[(size_t)(jg0 + jl) * HH + k4];
            int h0,l0,h1,l1,h2,l2,h3,l3;
            qlimbs(w.x, 131072.f, h0, l0); qlimbs(w.y, 131072.f, h1, l1);
            qlimbs(w.z, 131072.f, h2, l2); qlimbs(w.w, 131072.f, h3, l3);
            int lane0 = ((jl & 7) << 2) | ((k4 >> 2) & 3);
            int reg = (k4 >> 4) & 1, ksb = k4 >> 5, ng = jl >> 3;
            sw[(((0 * 8 + ksb) * 16 + ng) * 64) + lane0 * 2 + reg] = pack4(h0,h1,h2,h3);
            sw[(((1 * 8 + ksb) * 16 + ng) * 64) + lane0 * 2 + reg] = pack4(l0,l1,l2,l3);
        }

        for (int t = 0; t < TT; ++t) {
            if (tid == 0)       { while ((int)ld_acq_u(&g_cnt0[g32]) < 2 * t) { } }
            else if (tid == 32) { while ((int)ld_acq_u(&g_cnt1[g32]) < 4 * (t - 3)) { } }
            __syncthreads();

            // direct-LDG A = h0(t-1) frags into registers (lane-identical layout)
            const uint* srcA = g_h0F[(t + 3) & 3][g];
            uint4 aH[8], aL[8];
            #pragma unroll
            for (int ksb = 0; ksb < 8; ++ksb) {
                aH[ksb] = __ldcg((const uint4*)&srcA[ksb * 128 + lane * 4]);
                aL[ksb] = __ldcg((const uint4*)&srcA[1024 + ksb * 128 + lane * 4]);
            }

            // X0 prefetch
            float2 px[2][2];
            const int jb = jg0 + wi * 16;
            #pragma unroll
            for (int n2 = 0; n2 < 2; ++n2) {
                int j = jb + n2 * 8 + 2 * tig;
                px[n2][0] = __ldcs((const float2*)&g_X0[((size_t)t * BB + b0 + gID) * HH + j]);
                px[n2][1] = __ldcs((const float2*)&g_X0[((size_t)t * BB + b0 + gID + 8) * HH + j]);
            }

            int accA[2][4], accB[2][4], accC[2][4];
            #pragma unroll
            for (int n2 = 0; n2 < 2; ++n2)
                #pragma unroll
                for (int q = 0; q < 4; ++q) { accA[n2][q] = 0; accB[n2][q] = 0; accC[n2][q] = 0; }

            #pragma unroll
            for (int ksb = 0; ksb < 8; ++ksb) {
                #pragma unroll
                for (int n2 = 0; n2 < 2; ++n2) {
                    int ngg = wi * 2 + n2;
                    uint2 bH = *(uint2*)&sw[((0 * 8 + ksb) * 16 + ngg) * 64 + lane * 2];
                    uint2 bL = *(uint2*)&sw[((1 * 8 + ksb) * 16 + ngg) * 64 + lane * 2];
                    IMMA16832(accA[n2], aH[ksb], bH);
                    IMMA16832(accB[n2], aH[ksb], bL);
                    IMMA16832(accC[n2], aL[ksb], bH);
                }
            }

            // values + ring frag stores
            float v[2][4];
            uint* ring = g_h0F[t & 3][g];
            int cc0 = jb + 2 * tig;
            #pragma unroll
            for (int n2 = 0; n2 < 2; ++n2) {
                int cc = cc0 + n2 * 8;
                float d0 = (float)accA[n2][0] * S16C + (float)(accB[n2][0] + accC[n2][0]) * S8C;
                float d1 = (float)accA[n2][1] * S16C + (float)(accB[n2][1] + accC[n2][1]) * S8C;
                float d2 = (float)accA[n2][2] * S16C + (float)(accB[n2][2] + accC[n2][2]) * S8C;
                float d3 = (float)accA[n2][3] * S16C + (float)(accB[n2][3] + accC[n2][3]) * S8C;
                v[n2][0] = tanh_fast(d0 + px[n2][0].x);
                v[n2][1] = tanh_fast(d1 + px[n2][0].y);
                v[n2][2] = tanh_fast(d2 + px[n2][1].x);
                v[n2][3] = tanh_fast(d3 + px[n2][1].y);
                int h00,l00,h01_,l01_,h10,l10,h11,l11;
                qlimbs(v[n2][0], 16384.f, h00, l00); qlimbs(v[n2][1], 16384.f, h01_, l01_);
                qlimbs(v[n2][2], 16384.f, h10, l10); qlimbs(v[n2][3], 16384.f, h11, l11);
                int ksb_c = cc >> 5;
                int lane_c = (gID << 2) | ((cc & 15) >> 2);
                int idx0 = ksb_c * 128 + lane_c * 4 + (((cc >> 4) & 1) << 1);
                int boff = cc & 2;
                *(unsigned short*)((char*)(ring + idx0) + boff)            = pack2s(h00, h01_);
                *(unsigned short*)((char*)(ring + idx0 + 1) + boff)        = pack2s(h10, h11);
                *(unsigned short*)((char*)(ring + 1024 + idx0) + boff)     = pack2s(l00, l01_);
                *(unsigned short*)((char*)(ring + 1024 + idx0 + 1) + boff) = pack2s(l10, l11);
            }

            __syncthreads();
            if (tid == 0) arrive_acqrel(&g_cnt0[g32]);

            // non-consumed fp32 stores after release edge
            if (t == TT - 1) {
                #pragma unroll
                for (int n2 = 0; n2 < 2; ++n2) {
                    int cc = cc0 + n2 * 8;
                    *(float2*)&g_h0last[(b0 + gID) * HH + cc]     = make_float2(v[n2][0], v[n2][1]);
                    *(float2*)&g_h0last[(b0 + gID + 8) * HH + cc] = make_float2(v[n2][2], v[n2][3]);
                }
            }
        }
    } else {
        // ================= layer 1: m16 x n64 x k512 =================
        const int q64 = role - 2;
        const int jq0 = q64 * 64;

        for (int i = tid; i < 8192; i += 256) {
            int jl = i >> 7, k4 = (i & 127) << 2;
            float4 w = (k4 < 256)
                ? *(const float4*)&Wih1[(size_t)(jq0 + jl) * HH + k4]
                : *(const float4*)&Whh1[(size_t)(jq0 + jl) * HH + (k4 - 256)];
            int h0,l0,h1,l1,h2,l2,h3,l3;
            qlimbs(w.x, 131072.f, h0, l0); qlimbs(w.y, 131072.f, h1, l1);
            qlimbs(w.z, 131072.f, h2, l2); qlimbs(w.w, 131072.f, h3, l3);
            int lane0 = ((jl & 7) << 2) | ((k4 >> 2) & 3);
            int reg = (k4 >> 4) & 1, ksb = k4 >> 5, ng = jl >> 3;
            sw[(((0 * 16 + ksb) * 8 + ng) * 64) + lane0 * 2 + reg] = pack4(h0,h1,h2,h3);
            sw[(((1 * 16 + ksb) * 8 + ng) * 64) + lane0 * 2 + reg] = pack4(l0,l1,l2,l3);
        }

        const int jb = jq0 + wi * 8 + 2 * tig;
        const float bbx = bih1[jb] + bhh1[jb] + bias1[jb];
        const float bby = bih1[jb + 1] + bhh1[jb + 1] + bias1[jb + 1];

        for (int t = 0; t < TT; ++t) {
            if (tid == 0)       { while ((int)ld_acq_u(&g_cnt0[g32]) < 2 * (t + 1)) { } }
            else if (tid == 32) { while ((int)ld_acq_u(&g_cnt1[g32]) < 4 * t) { } }
            __syncthreads();

            // direct-LDG A: ksb 0..7 = h0(t), 8..15 = h1(t-1)
            const uint* s0 = g_h0F[t & 3][g];
            const uint* s1 = g_h1F[(t + 3) & 3][g];
            uint4 aH[16], aL[16];
            #pragma unroll
            for (int ksb = 0; ksb < 8; ++ksb) {
                aH[ksb] = __ldcg((const uint4*)&s0[ksb * 128 + lane * 4]);
                aL[ksb] = __ldcg((const uint4*)&s0[1024 + ksb * 128 + lane * 4]);
            }
            #pragma unroll
            for (int ksb = 0; ksb < 8; ++ksb) {
                aH[8 + ksb] = __ldcg((const uint4*)&s1[ksb * 128 + lane * 4]);
                aL[8 + ksb] = __ldcg((const uint4*)&s1[1024 + ksb * 128 + lane * 4]);
            }

            int accA[2][4], accB[2][4], accC[2][4];   // parity-split chains
            #pragma unroll
            for (int p = 0; p < 2; ++p)
                #pragma unroll
                for (int q = 0; q < 4; ++q) { accA[p][q] = 0; accB[p][q] = 0; accC[p][q] = 0; }

            #pragma unroll
            for (int ksb = 0; ksb < 16; ++ksb) {
                int p = ksb & 1;
                uint2 bH = *(uint2*)&sw[((0 * 16 + ksb) * 8 + wi) * 64 + lane * 2];
                uint2 bL = *(uint2*)&sw[((1 * 16 + ksb) * 8 + wi) * 64 + lane * 2];
                IMMA16832(accA[p], aH[ksb], bH);
                IMMA16832(accB[p], aH[ksb], bL);
                IMMA16832(accC[p], aL[ksb], bH);
            }

            // values + ring frag stores
            float d[4];
            #pragma unroll
            for (int q = 0; q < 4; ++q) {
                int iA = accA[0][q] + accA[1][q];
                int iBC = accB[0][q] + accB[1][q] + accC[0][q] + accC[1][q];
                d[q] = (float)iA * S16C + (float)iBC * S8C;
            }
            float v00 = tanh_fast(d[0] + bbx);
            float v01 = tanh_fast(d[1] + bby);
            float v10 = tanh_fast(d[2] + bbx);
            float v11 = tanh_fast(d[3] + bby);
            {
                int h00,l00,h01_,l01_,h10,l10,h11,l11;
                qlimbs(v00, 16384.f, h00, l00); qlimbs(v01, 16384.f, h01_, l01_);
                qlimbs(v10, 16384.f, h10, l10); qlimbs(v11, 16384.f, h11, l11);
                uint* ring = g_h1F[t & 3][g];
                int cc = jb;
                int ksb_c = cc >> 5;
                int lane_c = (gID << 2) | ((cc & 15) >> 2);
                int idx0 = ksb_c * 128 + lane_c * 4 + (((cc >> 4) & 1) << 1);
                int boff = cc & 2;
                *(unsigned short*)((char*)(ring + idx0) + boff)            = pack2s(h00, h01_);
                *(unsigned short*)((char*)(ring + idx0 + 1) + boff)        = pack2s(h10, h11);
                *(unsigned short*)((char*)(ring + 1024 + idx0) + boff)     = pack2s(l00, l01_);
                *(unsigned short*)((char*)(ring + 1024 + idx0 + 1) + boff) = pack2s(l10, l11);
            }

            __syncthreads();
            if (tid == 0) arrive_acqrel(&g_cnt1[g32]);

            // non-consumed fp32 stores after release edge
            __stcs((float2*)&g_h1all[((size_t)t * BB + b0 + gID) * HH + jb], make_float2(v00, v01));
            __stcs((float2*)&g_h1all[((size_t)t * BB + b0 + gID + 8) * HH + jb], make_float2(v10, v11));
            if (t == TT - 1) {
                *(float2*)&g_h1last[(b0 + gID) * HH + jb]     = make_float2(v00, v01);
                *(float2*)&g_h1last[(b0 + gID + 8) * HH + jb] = make_float2(v10, v11);
            }
        }
    }
}

// =====================================================================
// Epilogue: logits = h1all @ fc_w^T + fc_b; copy last hidden.
// =====================================================================
__global__ void __launch_bounds__(256) k_epilogue(
    const float* __restrict__ fcw, const float* __restrict__ fcb,
    float* __restrict__ out, int out_size)
{
    int bx = blockIdx.x, tid = threadIdx.x;
    if (bx >= 32768) {
        int i = (bx - 32768) * 256 + tid;
        int base = TT * BB * 2;
        if (base + i < out_size) {
            float v = (i < BB * HH) ? g_h0last[i] : g_h1last[i - BB * HH];
            out[base + i] = v;
        }
        return;
    }
    __shared__ float sfw[2 * HH];
    __shared__ float sfb[2];
    for (int i = tid; i < 2 * HH; i += 256) sfw[i] = fcw[i];
    if (tid < 2) sfb[tid] = fcb[tid];
    __syncthreads();

    int w = tid >> 5, lane = tid & 31;
    size_t row = (size_t)bx * 8 + w;
    const float* hp = &g_h1all[row * HH + lane * 8];
    float4 h0v = *(const float4*)hp;
    float4 h1v = *(const float4*)(hp + 4);
    const float* w0 = &sfw[lane * 8];
    const float* w1 = &sfw[HH + lane * 8];
    float c0 = 0.f, c1 = 0.f;
    #pragma unroll
    for (int q = 0; q < 4; ++q) {
        c0 += (&h0v.x)[q] * w0[q] + (&h1v.x)[q] * w0[q + 4];
        c1 += (&h0v.x)[q] * w1[q] + (&h1v.x)[q] * w1[q + 4];
    }
    #pragma unroll
    for (int off = 16; off > 0; off >>= 1) {
        c0 += __shfl_down_sync(0xFFFFFFFFu, c0, off);
        c1 += __shfl_down_sync(0xFFFFFFFFu, c1, off);
    }
    if (lane == 0) {
        out[row * 2 + 0] = c0 + sfb[0];
        out[row * 2 + 1] = c1 + sfb[1];
    }
}

// ---------------- launch ----------------
extern "C" void kernel_launch(void* const* d_in, const int* in_sizes, int n_in,
                              void* d_out, int out_size) {
    const float* inp    = (const float*)d_in[0];
    const float* hidden = (const float*)d_in[1];
    const float* Wih0   = (const float*)d_in[2];
    const float* bih0   = (const float*)d_in[3];
    const float* Whh0   = (const float*)d_in[4];
    const float* bhh0   = (const float*)d_in[5];
    const float* bias0  = (const float*)d_in[6];
    const float* Wih1   = (const float*)d_in[7];
    const float* bih1   = (const float*)d_in[8];
    const float* Whh1   = (const float*)d_in[9];
    const float* bhh1   = (const float*)d_in[10];
    const float* bias1  = (const float*)d_in[11];
    const float* fcw    = (const float*)d_in[12];
    const float* fcb    = (const float*)d_in[13];
    float* out = (float*)d_out;

    static bool attr_done = false;
    if (!attr_done) {
        cudaFuncSetAttribute(k_pro2, cudaFuncAttributeMaxDynamicSharedMemorySize, PRO2_SMEM);
        cudaFuncSetAttribute(k_rnn,  cudaFuncAttributeMaxDynamicSharedMemorySize, RNN_SMEM);
        attr_done = true;
    }

    k_seed<<<9, 256>>>(hidden);
    k_pro2<<<148, 256, PRO2_SMEM>>>(inp, Wih0, bih0, bhh0, bias0);
    k_rnn<<<96, 256, RNN_SMEM>>>(Whh0, Wih1, Whh1, bih1, bhh1, bias1);
    k_epilogue<<<33280, 256>>>(fcw, fcb, out, out_size);
}